// round 8
// baseline (speedup 1.0000x reference)
#include <cuda_runtime.h>
#include <math.h>

#define B_TOTAL 131072
#define Hh 128
#define Dd 256
#define Ee 128
#define G3H 384
#define MT 32
#define NTHR 256

typedef unsigned long long u64;

__device__ __forceinline__ u64 pack2(float lo, float hi) {
    u64 r;
    asm("mov.b64 %0,{%1,%2};" : "=l"(r)
        : "r"(__float_as_uint(lo)), "r"(__float_as_uint(hi)));
    return r;
}
__device__ __forceinline__ u64 bcast2(float x) {
    u64 r;
    asm("mov.b64 %0,{%1,%1};" : "=l"(r) : "r"(__float_as_uint(x)));
    return r;
}
__device__ __forceinline__ void ffma2(u64& d, u64 a, u64 b) {
    asm("fma.rn.f32x2 %0,%1,%2,%3;" : "=l"(d) : "l"(a), "l"(b), "l"(d));
}
__device__ __forceinline__ void unpk2(u64 v, float& a, float& b) {
    unsigned lo, hi;
    asm("mov.b64 {%0,%1},%2;" : "=r"(lo), "=r"(hi) : "l"(v));
    a = __uint_as_float(lo); b = __uint_as_float(hi);
}

// Transposed GRU weights (k-major [E][3H]) — device scratch, no allocation.
__device__ float g_wihT[Ee * G3H];
__device__ float g_whhT[Hh * G3H];

__global__ void transpose_gru_kernel(const float* __restrict__ wih,
                                     const float* __restrict__ whh) {
    int idx = blockIdx.x * blockDim.x + threadIdx.x;
    if (idx < Ee * G3H) {
        int e = idx / G3H, j = idx % G3H;
        g_wihT[idx] = wih[j * Ee + e];
        g_whhT[idx] = whh[j * Hh + e];
    }
}

// ---------------------------------------------------------------------------
// evolve: one RK4 (3/8 rule) step per row. 32 rows/CTA, 8 warps, 4 rows/warp.
// Round-1 structure (warp-private smem rows, no in-loop block barriers except
// one alignment barrier per stage before mm2), FFMA2-packed inner loops.
// ---------------------------------------------------------------------------
#define EV_SMEM_FLOATS 50080
__global__ void __launch_bounds__(NTHR, 1) evolve_kernel(
    const float* __restrict__ hidden, const float* __restrict__ dts,
    const float* __restrict__ w1, const float* __restrict__ b1,
    const float* __restrict__ lnw, const float* __restrict__ lnb,
    const float* __restrict__ w2, const float* __restrict__ b2,
    float* __restrict__ evolved)
{
    extern __shared__ float sm[];
    float* w1_s  = sm;              // 32768 floats (128KB), resident
    float* h_s   = sm + 32768;      // 32x128
    float* arg_s = sm + 36864;      // 32x128
    float* a_s   = sm + 40960;      // 32x256
    float* b1_s  = sm + 49152;      // 256
    float* lnw_s = sm + 49408;      // 256
    float* lnb_s = sm + 49664;      // 256
    float* b2_s  = sm + 49920;      // 128
    float* dt_s  = sm + 50048;      // 32

    const int tid  = threadIdx.x;
    const int lane = tid & 31;
    const int wrp  = tid >> 5;
    const int r0   = wrp * 4;                       // local row base (4 rows/warp)
    const size_t row0 = (size_t)blockIdx.x * MT;

    // ---- stage weights + tile ----
    {
        const float4* src = reinterpret_cast<const float4*>(w1);
        float4* dst = reinterpret_cast<float4*>(w1_s);
        #pragma unroll
        for (int t = 0; t < 32; ++t) dst[tid + t * NTHR] = src[tid + t * NTHR];
    }
    {
        const float4* src = reinterpret_cast<const float4*>(hidden + row0 * Hh);
        float4* dh = reinterpret_cast<float4*>(h_s);
        float4* da = reinterpret_cast<float4*>(arg_s);
        #pragma unroll
        for (int t = 0; t < 4; ++t) {
            float4 v = src[tid + t * NTHR];
            dh[tid + t * NTHR] = v;
            da[tid + t * NTHR] = v;
        }
    }
    if (tid < 256) { b1_s[tid] = b1[tid]; lnw_s[tid] = lnw[tid]; lnb_s[tid] = lnb[tid]; }
    if (tid < 128) b2_s[tid] = b2[tid];
    if (tid < 32)  dt_s[tid] = fmaxf(dts[row0 + tid], 0.0f);
    __syncthreads();

    float k1r[4][4], k2r[4][4], accr[4][4];

    #pragma unroll 1
    for (int s = 0; s < 4; ++s) {
        // ---- mm1: u[4 rows][8 cols] = arg @ w1 + b1 (FFMA2-packed) ----
        u64 u2[4][4];
        #pragma unroll
        for (int i = 0; i < 4; ++i)
            #pragma unroll
            for (int p = 0; p < 4; ++p)
                u2[i][p] = pack2(b1_s[lane * 8 + 2 * p], b1_s[lane * 8 + 2 * p + 1]);

        const ulonglong2* w1u = reinterpret_cast<const ulonglong2*>(w1_s);
        #pragma unroll 2
        for (int k = 0; k < Hh; k += 4) {
            float4 av[4];
            #pragma unroll
            for (int i = 0; i < 4; ++i)
                av[i] = *reinterpret_cast<const float4*>(arg_s + (r0 + i) * Hh + k);
            #pragma unroll
            for (int kk = 0; kk < 4; ++kk) {
                ulonglong2 W0 = w1u[(k + kk) * 64 + lane * 2];
                ulonglong2 W1 = w1u[(k + kk) * 64 + lane * 2 + 1];
                #pragma unroll
                for (int i = 0; i < 4; ++i) {
                    float a = (kk == 0) ? av[i].x : (kk == 1) ? av[i].y
                            : (kk == 2) ? av[i].z : av[i].w;
                    u64 aa = bcast2(a);
                    ffma2(u2[i][0], aa, W0.x);
                    ffma2(u2[i][1], aa, W0.y);
                    ffma2(u2[i][2], aa, W1.x);
                    ffma2(u2[i][3], aa, W1.y);
                }
            }
        }

        // ---- LayerNorm + exact GELU, a -> smem ----
        #pragma unroll
        for (int i = 0; i < 4; ++i) {
            float uv[8];
            #pragma unroll
            for (int p = 0; p < 4; ++p) unpk2(u2[i][p], uv[2 * p], uv[2 * p + 1]);
            float s1 = 0.f, s2 = 0.f;
            #pragma unroll
            for (int j = 0; j < 8; ++j) { s1 += uv[j]; s2 += uv[j] * uv[j]; }
            #pragma unroll
            for (int off = 16; off >= 1; off >>= 1) {
                s1 += __shfl_xor_sync(0xffffffffu, s1, off);
                s2 += __shfl_xor_sync(0xffffffffu, s2, off);
            }
            float mu   = s1 * (1.0f / Dd);
            float var  = s2 * (1.0f / Dd) - mu * mu;
            float rstd = rsqrtf(var + 1e-5f);
            #pragma unroll
            for (int j = 0; j < 8; ++j) {
                int c = lane * 8 + j;
                float v = (uv[j] - mu) * rstd * lnw_s[c] + lnb_s[c];
                a_s[(r0 + i) * Dd + c] = v * normcdff(v);   // exact gelu
            }
        }
        // align warps so the 8-warp shared w2 L2 stream dedups in L1
        __syncthreads();

        // ---- mm2: kv[4 rows][4 cols] = a @ w2 + b2 (w2 streamed, FFMA2) ----
        u64 kv2[4][2];
        #pragma unroll
        for (int i = 0; i < 4; ++i) {
            kv2[i][0] = pack2(b2_s[lane * 4],     b2_s[lane * 4 + 1]);
            kv2[i][1] = pack2(b2_s[lane * 4 + 2], b2_s[lane * 4 + 3]);
        }

        const ulonglong2* w2u = reinterpret_cast<const ulonglong2*>(w2);
        #pragma unroll 2
        for (int d = 0; d < Dd; d += 4) {
            float4 av[4];
            #pragma unroll
            for (int i = 0; i < 4; ++i)
                av[i] = *reinterpret_cast<const float4*>(a_s + (r0 + i) * Dd + d);
            #pragma unroll
            for (int dd = 0; dd < 4; ++dd) {
                ulonglong2 W = __ldg(w2u + (d + dd) * 32 + lane);
                #pragma unroll
                for (int i = 0; i < 4; ++i) {
                    float a = (dd == 0) ? av[i].x : (dd == 1) ? av[i].y
                            : (dd == 2) ? av[i].z : av[i].w;
                    u64 aa = bcast2(a);
                    ffma2(kv2[i][0], aa, W.x);
                    ffma2(kv2[i][1], aa, W.y);
                }
            }
        }

        // ---- RK4 stage combine (warp-private rows) ----
        float kv[4][4];
        #pragma unroll
        for (int i = 0; i < 4; ++i) {
            unpk2(kv2[i][0], kv[i][0], kv[i][1]);
            unpk2(kv2[i][1], kv[i][2], kv[i][3]);
        }

        if (s == 0) {
            #pragma unroll
            for (int i = 0; i < 4; ++i) {
                float dt = dt_s[r0 + i];
                #pragma unroll
                for (int j = 0; j < 4; ++j) {
                    int c = lane * 4 + j;
                    k1r[i][j] = kv[i][j];
                    accr[i][j] = kv[i][j];
                    arg_s[(r0 + i) * Hh + c] =
                        h_s[(r0 + i) * Hh + c] + dt * (kv[i][j] * (1.0f / 3.0f));
                }
            }
        } else if (s == 1) {
            #pragma unroll
            for (int i = 0; i < 4; ++i) {
                float dt = dt_s[r0 + i];
                #pragma unroll
                for (int j = 0; j < 4; ++j) {
                    int c = lane * 4 + j;
                    k2r[i][j] = kv[i][j];
                    accr[i][j] += 3.0f * kv[i][j];
                    arg_s[(r0 + i) * Hh + c] =
                        h_s[(r0 + i) * Hh + c] + dt * (kv[i][j] - k1r[i][j] * (1.0f / 3.0f));
                }
            }
        } else if (s == 2) {
            #pragma unroll
            for (int i = 0; i < 4; ++i) {
                float dt = dt_s[r0 + i];
                #pragma unroll
                for (int j = 0; j < 4; ++j) {
                    int c = lane * 4 + j;
                    accr[i][j] += 3.0f * kv[i][j];
                    arg_s[(r0 + i) * Hh + c] =
                        h_s[(r0 + i) * Hh + c] + dt * (k1r[i][j] - k2r[i][j] + kv[i][j]);
                }
            }
        } else {
            #pragma unroll
            for (int i = 0; i < 4; ++i) {
                float dt = dt_s[r0 + i];
                float4 o;
                float* op = reinterpret_cast<float*>(&o);
                #pragma unroll
                for (int j = 0; j < 4; ++j) {
                    int c = lane * 4 + j;
                    float hv = h_s[(r0 + i) * Hh + c];
                    float a = accr[i][j] + kv[i][j];
                    op[j] = (dt > 0.0f) ? (hv + dt * a * 0.125f) : hv;
                }
                *reinterpret_cast<float4*>(evolved + (row0 + r0 + i) * Hh + lane * 4) = o;
            }
        }
        __syncwarp();   // arg_s written before next stage's mm1 reads (same warp)
    }
}

// ---------------------------------------------------------------------------
// GRU update. lane owns column PAIRS: col = g*128 + 64*m + 2*lane (+t), so
// weights load as conflict-free LDS.64 feeding FFMA2 directly, and r/z/n for
// the same hidden index stay on the same lane.
// ---------------------------------------------------------------------------
#define GRU_SMEM_FLOATS 57344
__global__ void __launch_bounds__(NTHR, 1) gru_kernel(
    const float* __restrict__ evolved, const float* __restrict__ obs,
    const int* __restrict__ mask,
    const float* __restrict__ bih, const float* __restrict__ bhh,
    float* __restrict__ updated)
{
    extern __shared__ float sm[];
    float* w_s   = sm;              // 128x384 (192KB) — WihT then WhhT
    float* obs_s = sm + 49152;      // 32x128
    float* ev_s  = sm + 53248;      // 32x128

    const int tid  = threadIdx.x;
    const int lane = tid & 31;
    const int wrp  = tid >> 5;
    const int r0   = wrp * 4;
    const size_t row0 = (size_t)blockIdx.x * MT;

    {
        const float4* so = reinterpret_cast<const float4*>(obs + row0 * Ee);
        const float4* se = reinterpret_cast<const float4*>(evolved + row0 * Hh);
        float4* dobs = reinterpret_cast<float4*>(obs_s);
        float4* dev  = reinterpret_cast<float4*>(ev_s);
        #pragma unroll
        for (int t = 0; t < 4; ++t) {
            dobs[tid + t * NTHR] = so[tid + t * NTHR];
            dev[tid + t * NTHR]  = se[tid + t * NTHR];
        }
    }
    {
        const float4* src = reinterpret_cast<const float4*>(g_wihT);
        float4* dst = reinterpret_cast<float4*>(w_s);
        #pragma unroll
        for (int t = 0; t < 48; ++t) dst[tid + t * NTHR] = src[tid + t * NTHR];
    }
    __syncthreads();

    // accumulators: [row i][g*2+m] packed pairs
    u64 gi2[4][6], gh2[4][6];
    #pragma unroll
    for (int g = 0; g < 3; ++g)
        #pragma unroll
        for (int m = 0; m < 2; ++m) {
            int c = g * Hh + 64 * m + 2 * lane;
            u64 bi = pack2(__ldg(bih + c), __ldg(bih + c + 1));
            u64 bh = pack2(__ldg(bhh + c), __ldg(bhh + c + 1));
            #pragma unroll
            for (int i = 0; i < 4; ++i) { gi2[i][g * 2 + m] = bi; gh2[i][g * 2 + m] = bh; }
        }

    // gi = obs @ WihT + bih
    #pragma unroll 2
    for (int e = 0; e < Ee; e += 4) {
        float4 ov[4];
        #pragma unroll
        for (int i = 0; i < 4; ++i)
            ov[i] = *reinterpret_cast<const float4*>(obs_s + (r0 + i) * Ee + e);
        #pragma unroll
        for (int ee = 0; ee < 4; ++ee) {
            const float* wb = w_s + (e + ee) * G3H + 2 * lane;
            u64 W[6];
            #pragma unroll
            for (int g = 0; g < 3; ++g)
                #pragma unroll
                for (int m = 0; m < 2; ++m)
                    W[g * 2 + m] = *reinterpret_cast<const u64*>(wb + g * Hh + 64 * m);
            #pragma unroll
            for (int i = 0; i < 4; ++i) {
                float a = (ee == 0) ? ov[i].x : (ee == 1) ? ov[i].y
                        : (ee == 2) ? ov[i].z : ov[i].w;
                u64 aa = bcast2(a);
                #pragma unroll
                for (int q = 0; q < 6; ++q) ffma2(gi2[i][q], aa, W[q]);
            }
        }
    }
    __syncthreads();    // all warps done with WihT
    {
        const float4* src = reinterpret_cast<const float4*>(g_whhT);
        float4* dst = reinterpret_cast<float4*>(w_s);
        #pragma unroll
        for (int t = 0; t < 48; ++t) dst[tid + t * NTHR] = src[tid + t * NTHR];
    }
    __syncthreads();

    // gh = evolved @ WhhT + bhh
    #pragma unroll 2
    for (int e = 0; e < Hh; e += 4) {
        float4 ov[4];
        #pragma unroll
        for (int i = 0; i < 4; ++i)
            ov[i] = *reinterpret_cast<const float4*>(ev_s + (r0 + i) * Hh + e);
        #pragma unroll
        for (int ee = 0; ee < 4; ++ee) {
            const float* wb = w_s + (e + ee) * G3H + 2 * lane;
            u64 W[6];
            #pragma unroll
            for (int g = 0; g < 3; ++g)
                #pragma unroll
                for (int m = 0; m < 2; ++m)
                    W[g * 2 + m] = *reinterpret_cast<const u64*>(wb + g * Hh + 64 * m);
            #pragma unroll
            for (int i = 0; i < 4; ++i) {
                float a = (ee == 0) ? ov[i].x : (ee == 1) ? ov[i].y
                        : (ee == 2) ? ov[i].z : ov[i].w;
                u64 aa = bcast2(a);
                #pragma unroll
                for (int q = 0; q < 6; ++q) ffma2(gh2[i][q], aa, W[q]);
            }
        }
    }

    // gates + select
    #pragma unroll
    for (int i = 0; i < 4; ++i) {
        size_t grow = row0 + r0 + i;
        int msk = __ldg(mask + grow);
        #pragma unroll
        for (int m = 0; m < 2; ++m) {
            float ir0, ir1, iz0, iz1, in0, in1;
            float hr0, hr1, hz0, hz1, hn0, hn1;
            unpk2(gi2[i][0 + m], ir0, ir1);
            unpk2(gi2[i][2 + m], iz0, iz1);
            unpk2(gi2[i][4 + m], in0, in1);
            unpk2(gh2[i][0 + m], hr0, hr1);
            unpk2(gh2[i][2 + m], hz0, hz1);
            unpk2(gh2[i][4 + m], hn0, hn1);

            int hidx = 64 * m + 2 * lane;
            float2 ev = *reinterpret_cast<const float2*>(
                ev_s + (r0 + i) * Hh + hidx);

            float r0g = 1.0f / (1.0f + __expf(-(ir0 + hr0)));
            float z0g = 1.0f / (1.0f + __expf(-(iz0 + hz0)));
            float n0g = tanhf(in0 + r0g * hn0);
            float o0 = (msk > 0) ? ((1.0f - z0g) * n0g + z0g * ev.x) : ev.x;

            float r1g = 1.0f / (1.0f + __expf(-(ir1 + hr1)));
            float z1g = 1.0f / (1.0f + __expf(-(iz1 + hz1)));
            float n1g = tanhf(in1 + r1g * hn1);
            float o1 = (msk > 0) ? ((1.0f - z1g) * n1g + z1g * ev.y) : ev.y;

            float2 o; o.x = o0; o.y = o1;
            *reinterpret_cast<float2*>(updated + grow * Hh + hidx) = o;
        }
    }
}

// ---------------------------------------------------------------------------
extern "C" void kernel_launch(void* const* d_in, const int* in_sizes, int n_in,
                              void* d_out, int out_size)
{
    const float* hidden = (const float*)d_in[0];
    const float* dts    = (const float*)d_in[1];
    const float* obs    = (const float*)d_in[2];
    const int*   mask   = (const int*)d_in[3];
    const float* w1     = (const float*)d_in[4];
    const float* b1     = (const float*)d_in[5];
    const float* lnw    = (const float*)d_in[6];
    const float* lnb    = (const float*)d_in[7];
    const float* w2     = (const float*)d_in[8];
    const float* b2     = (const float*)d_in[9];
    const float* wih    = (const float*)d_in[10];
    const float* whh    = (const float*)d_in[11];
    const float* bih    = (const float*)d_in[12];
    const float* bhh    = (const float*)d_in[13];

    float* evolved = (float*)d_out;
    float* updated = evolved + (size_t)B_TOTAL * Hh;

    cudaFuncSetAttribute(evolve_kernel, cudaFuncAttributeMaxDynamicSharedMemorySize,
                         EV_SMEM_FLOATS * 4);
    cudaFuncSetAttribute(gru_kernel, cudaFuncAttributeMaxDynamicSharedMemorySize,
                         GRU_SMEM_FLOATS * 4);

    transpose_gru_kernel<<<(Ee * G3H + 255) / 256, 256>>>(wih, whh);
    evolve_kernel<<<B_TOTAL / MT, NTHR, EV_SMEM_FLOATS * 4>>>(
        hidden, dts, w1, b1, lnw, lnb, w2, b2, evolved);
    gru_kernel<<<B_TOTAL / MT, NTHR, GRU_SMEM_FLOATS * 4>>>(
        evolved, obs, mask, bih, bhh, updated);
}

// round 10
// speedup vs baseline: 1.8872x; 1.8872x over previous
#include <cuda_runtime.h>
#include <cuda_bf16.h>
#include <math.h>
#include <stdint.h>

#define NT 256

// ---------------- weight images: [n][k] bf16, hi/lo planes ----------------
__device__ __align__(16) uint8_t pB1[2][65536];   // w1^T  [256][128]
__device__ __align__(16) uint8_t pB2[2][65536];   // w2^T  [128][256]
__device__ __align__(16) uint8_t pR [2][65536];   // r gate [128][256] (wih_r||whh_r)
__device__ __align__(16) uint8_t pZ [2][65536];   // z gate [128][256]
__device__ __align__(16) uint8_t pIN[2][32768];   // wih_n [128][128]
__device__ __align__(16) uint8_t pHN[2][32768];   // whh_n [128][128]
__device__ float g_k1[16777216];                  // 64MB RK4 scratch

__device__ __forceinline__ void wsp(float x, uint8_t* hi, uint8_t* lo, uint32_t o) {
    __nv_bfloat16 h = __float2bfloat16_rn(x);
    __nv_bfloat16 l = __float2bfloat16_rn(x - __bfloat162float(h));
    *(uint16_t*)(hi + o) = __bfloat16_as_ushort(h);
    *(uint16_t*)(lo + o) = __bfloat16_as_ushort(l);
}

__global__ void prep_kernel(const float* __restrict__ w1, const float* __restrict__ w2,
                            const float* __restrict__ wih, const float* __restrict__ whh) {
    int i = blockIdx.x * blockDim.x + threadIdx.x;
    if (i < 32768) {
        int n = i >> 7, k = i & 127;
        wsp(w1[k * 256 + n], pB1[0], pB1[1], (uint32_t)(n * 128 + k) * 2);
    } else if (i < 65536) {
        int t = i - 32768, n = t >> 8, k = t & 255;
        wsp(w2[k * 128 + n], pB2[0], pB2[1], (uint32_t)(n * 256 + k) * 2);
    } else if (i < 98304) {
        int t = i - 65536, n = t >> 8, k = t & 255;
        float v = (k < 128) ? wih[n * 128 + k] : whh[n * 128 + (k - 128)];
        wsp(v, pR[0], pR[1], (uint32_t)(n * 256 + k) * 2);
    } else if (i < 131072) {
        int t = i - 98304, n = t >> 8, k = t & 255;
        float v = (k < 128) ? wih[(128 + n) * 128 + k] : whh[(128 + n) * 128 + (k - 128)];
        wsp(v, pZ[0], pZ[1], (uint32_t)(n * 256 + k) * 2);
    } else if (i < 147456) {
        int t = i - 131072, n = t >> 7, k = t & 127;
        wsp(wih[(256 + n) * 128 + k], pIN[0], pIN[1], (uint32_t)(n * 128 + k) * 2);
    } else if (i < 163840) {
        int t = i - 147456, n = t >> 7, k = t & 127;
        wsp(whh[(256 + n) * 128 + k], pHN[0], pHN[1], (uint32_t)(n * 128 + k) * 2);
    }
}

// ---------------- helpers ----------------
__device__ __forceinline__ uint32_t s2u(const void* p) {
    uint32_t a;
    asm("{.reg .u64 t; cvta.to.shared.u64 t,%1; cvt.u32.u64 %0,t;}" : "=r"(a) : "l"(p));
    return a;
}
__device__ __forceinline__ void cpa(uint32_t d, const void* s) {
    asm volatile("cp.async.cg.shared.global [%0],[%1],16;" :: "r"(d), "l"(s) : "memory");
}
#define CPC()  asm volatile("cp.async.commit_group;" ::: "memory")
#define WAIT1 asm volatile("cp.async.wait_group 1;" ::: "memory")
#define WAIT0 asm volatile("cp.async.wait_group 0;" ::: "memory")

__device__ __forceinline__ void mmab(float c[4], const uint32_t a[4], const uint32_t b[2]) {
    asm volatile("mma.sync.aligned.m16n8k16.row.col.f32.bf16.bf16.f32 "
        "{%0,%1,%2,%3},{%4,%5,%6,%7},{%8,%9},{%0,%1,%2,%3};"
        : "+f"(c[0]), "+f"(c[1]), "+f"(c[2]), "+f"(c[3])
        : "r"(a[0]), "r"(a[1]), "r"(a[2]), "r"(a[3]), "r"(b[0]), "r"(b[1]));
}
__device__ __forceinline__ void lda(uint32_t a[4], uint32_t plane, int row, int kb, int stride) {
    uint32_t ad = plane + (uint32_t)(row * stride + kb);
    asm volatile("ld.shared.b32 %0,[%1];" : "=r"(a[0]) : "r"(ad));
    asm volatile("ld.shared.b32 %0,[%1];" : "=r"(a[1]) : "r"(ad + 8 * stride));
    asm volatile("ld.shared.b32 %0,[%1];" : "=r"(a[2]) : "r"(ad + 16));
    asm volatile("ld.shared.b32 %0,[%1];" : "=r"(a[3]) : "r"(ad + 8 * stride + 16));
}
__device__ __forceinline__ void ldb(uint32_t b[2], uint32_t plane, int n, int koff) {
    uint32_t ad = plane + (uint32_t)(n * 80 + koff);
    asm volatile("ld.shared.b32 %0,[%1];" : "=r"(b[0]) : "r"(ad));
    asm volatile("ld.shared.b32 %0,[%1];" : "=r"(b[1]) : "r"(ad + 16));
}
__device__ __forceinline__ void sp2(float v0, float v1, uint32_t& hi, uint32_t& lo) {
    __nv_bfloat16 h0 = __float2bfloat16_rn(v0), h1 = __float2bfloat16_rn(v1);
    __nv_bfloat16 l0 = __float2bfloat16_rn(v0 - __bfloat162float(h0));
    __nv_bfloat16 l1 = __float2bfloat16_rn(v1 - __bfloat162float(h1));
    hi = (uint32_t)__bfloat16_as_ushort(h0) | ((uint32_t)__bfloat16_as_ushort(h1) << 16);
    lo = (uint32_t)__bfloat16_as_ushort(l0) | ((uint32_t)__bfloat16_as_ushort(l1) << 16);
}
// stream a [Nn][32k] hi+lo chunk into smem (row stride 80B, bank-conflict-free)
__device__ __forceinline__ void issueB(uint32_t dst, const uint8_t* hi, const uint8_t* lo,
                                       int Nn, int rowbytes, int kc, int tid) {
    const int perplane = Nn * 4, tot = perplane * 2, psz = Nn * 80;
    for (int f = tid; f < tot; f += NT) {
        int p = f >= perplane;
        int r2 = p ? f - perplane : f;
        int r = r2 >> 2, q = r2 & 3;
        const uint8_t* s = (p ? lo : hi) + (size_t)r * rowbytes + kc * 64 + q * 16;
        cpa(dst + (uint32_t)(p * psz + r * 80 + q * 16), s);
    }
    CPC();
}

// ---------------- evolve: RK4(3/8), 64 rows/CTA ----------------
// smem: AH 0(17408) AL 17408 | A2H 34816(33792) A2L 68608 | B 102400(2x40960)
//       stats 184320(2048) b1 186368 lnw 187392 lnb 188416 b2 189440 dt 189952
#define EV_SM 190208
__global__ void __launch_bounds__(NT, 1) evolve_kernel(
    const float* __restrict__ hidden, const float* __restrict__ dts,
    const float* __restrict__ b1, const float* __restrict__ lnw,
    const float* __restrict__ lnb, const float* __restrict__ b2,
    float* __restrict__ evolved, float* __restrict__ scr2)
{
    extern __shared__ uint8_t sm8[];
    const uint32_t sb = s2u(sm8);
    float* stats = (float*)(sm8 + 184320);
    float* b1s   = (float*)(sm8 + 186368);
    float* lnws  = (float*)(sm8 + 187392);
    float* lnbs  = (float*)(sm8 + 188416);
    float* b2s   = (float*)(sm8 + 189440);
    float* dtss  = (float*)(sm8 + 189952);

    const int tid = threadIdx.x, lane = tid & 31, wrp = tid >> 5;
    const int gid = lane >> 2, tig = lane & 3;
    const int wm = wrp >> 2, wn = wrp & 3;
    const size_t rowbase = (size_t)blockIdx.x * 64;

    b1s[tid] = b1[tid]; lnws[tid] = lnw[tid]; lnbs[tid] = lnb[tid];
    if (tid < 128) b2s[tid] = b2[tid];
    if (tid < 64)  dtss[tid] = fmaxf(__ldg(dts + rowbase + tid), 0.0f);
    // A0 = split(h)
    for (int idx = tid; idx < 8192; idx += NT) {
        int r = idx >> 7, c = idx & 127;
        float v = __ldg(hidden + (rowbase + r) * 128 + c);
        __nv_bfloat16 h = __float2bfloat16_rn(v);
        __nv_bfloat16 l = __float2bfloat16_rn(v - __bfloat162float(h));
        *(uint16_t*)(sm8 + r * 272 + c * 2) = __bfloat16_as_ushort(h);
        *(uint16_t*)(sm8 + 17408 + r * 272 + c * 2) = __bfloat16_as_ushort(l);
    }
    int cur = 0;
    issueB(sb + 102400, pB1[0], pB1[1], 256, 256, 0, tid);   // mm1 chunk0 -> buf0
    __syncthreads();

    #pragma unroll 1
    for (int s = 0; s < 4; ++s) {
        // ================= mm1: N=256, K=128 (4 chunks) =================
        float c1[2][8][4];
        #pragma unroll
        for (int mt = 0; mt < 2; ++mt)
            #pragma unroll
            for (int nt = 0; nt < 8; ++nt)
                #pragma unroll
                for (int e = 0; e < 4; ++e) c1[mt][nt][e] = 0.f;

        #pragma unroll 1
        for (int kc = 0; kc < 4; ++kc) {
            __syncthreads();
            if (kc < 3) issueB(sb + 102400 + (cur ^ 1) * 40960, pB1[0], pB1[1], 256, 256, kc + 1, tid);
            else        issueB(sb + 102400 + (cur ^ 1) * 40960, pB2[0], pB2[1], 128, 512, 0, tid);
            WAIT1;
            __syncthreads();
            uint32_t bb = sb + 102400 + cur * 40960;
            #pragma unroll
            for (int ks = 0; ks < 2; ++ks) {
                int kb = (kc * 32 + ks * 16) * 2 + tig * 4;
                uint32_t ah0[4], ah1[4], al0[4], al1[4];
                lda(ah0, sb,         wm * 32 + gid,      kb, 272);
                lda(ah1, sb,         wm * 32 + 16 + gid, kb, 272);
                lda(al0, sb + 17408, wm * 32 + gid,      kb, 272);
                lda(al1, sb + 17408, wm * 32 + 16 + gid, kb, 272);
                #pragma unroll
                for (int nt = 0; nt < 8; ++nt) {
                    uint32_t bh[2], bl[2];
                    int n = wn * 64 + nt * 8 + gid;
                    ldb(bh, bb,         n, ks * 32 + tig * 4);
                    ldb(bl, bb + 20480, n, ks * 32 + tig * 4);
                    mmab(c1[0][nt], ah0, bh); mmab(c1[1][nt], ah1, bh);
                    mmab(c1[0][nt], al0, bh); mmab(c1[1][nt], al1, bh);
                    mmab(c1[0][nt], ah0, bl); mmab(c1[1][nt], ah1, bl);
                }
            }
            cur ^= 1;
        }

        // ================= epilogue1: +b1, LN, GELU -> A2 =================
        #pragma unroll
        for (int mt = 0; mt < 2; ++mt)
            #pragma unroll
            for (int half = 0; half < 2; ++half) {
                float s1 = 0.f, s2 = 0.f;
                #pragma unroll
                for (int nt = 0; nt < 8; ++nt)
                    #pragma unroll
                    for (int j = 0; j < 2; ++j) {
                        int col = wn * 64 + nt * 8 + tig * 2 + j;
                        float v = c1[mt][nt][half * 2 + j] + b1s[col];
                        c1[mt][nt][half * 2 + j] = v;
                        s1 += v; s2 += v * v;
                    }
                s1 += __shfl_xor_sync(0xffffffffu, s1, 1);
                s1 += __shfl_xor_sync(0xffffffffu, s1, 2);
                s2 += __shfl_xor_sync(0xffffffffu, s2, 1);
                s2 += __shfl_xor_sync(0xffffffffu, s2, 2);
                if (tig == 0) {
                    int row = wm * 32 + mt * 16 + gid + half * 8;
                    stats[row * 8 + wn * 2] = s1;
                    stats[row * 8 + wn * 2 + 1] = s2;
                }
            }
        __syncthreads();
        #pragma unroll
        for (int mt = 0; mt < 2; ++mt)
            #pragma unroll
            for (int half = 0; half < 2; ++half) {
                int row = wm * 32 + mt * 16 + gid + half * 8;
                float t1 = stats[row * 8] + stats[row * 8 + 2] + stats[row * 8 + 4] + stats[row * 8 + 6];
                float t2 = stats[row * 8 + 1] + stats[row * 8 + 3] + stats[row * 8 + 5] + stats[row * 8 + 7];
                float mu = t1 * (1.0f / 256.0f);
                float var = t2 * (1.0f / 256.0f) - mu * mu;
                float rstd = rsqrtf(var + 1e-5f);
                #pragma unroll
                for (int nt = 0; nt < 8; ++nt) {
                    int col0 = wn * 64 + nt * 8 + tig * 2;
                    float v0 = (c1[mt][nt][half * 2] - mu) * rstd * lnws[col0] + lnbs[col0];
                    float v1 = (c1[mt][nt][half * 2 + 1] - mu) * rstd * lnws[col0 + 1] + lnbs[col0 + 1];
                    float g0 = v0 * normcdff(v0), g1 = v1 * normcdff(v1);
                    uint32_t hi, lo; sp2(g0, g1, hi, lo);
                    *(uint32_t*)(sm8 + 34816 + row * 528 + col0 * 2) = hi;
                    *(uint32_t*)(sm8 + 68608 + row * 528 + col0 * 2) = lo;
                }
            }

        // ================= mm2: N=128, K=256 (8 chunks) =================
        float c2[2][4][4];
        #pragma unroll
        for (int mt = 0; mt < 2; ++mt)
            #pragma unroll
            for (int nt = 0; nt < 4; ++nt)
                #pragma unroll
                for (int e = 0; e < 4; ++e) c2[mt][nt][e] = 0.f;

        #pragma unroll 1
        for (int kc = 0; kc < 8; ++kc) {
            __syncthreads();
            bool more = true;
            if (kc < 7)      issueB(sb + 102400 + (cur ^ 1) * 40960, pB2[0], pB2[1], 128, 512, kc + 1, tid);
            else if (s < 3)  issueB(sb + 102400 + (cur ^ 1) * 40960, pB1[0], pB1[1], 256, 256, 0, tid);
            else more = false;
            if (more) { WAIT1; } else { WAIT0; }
            __syncthreads();
            uint32_t bb = sb + 102400 + cur * 40960;
            #pragma unroll
            for (int ks = 0; ks < 2; ++ks) {
                int kb = (kc * 32 + ks * 16) * 2 + tig * 4;
                uint32_t ah0[4], ah1[4], al0[4], al1[4];
                lda(ah0, sb + 34816, wm * 32 + gid,      kb, 528);
                lda(ah1, sb + 34816, wm * 32 + 16 + gid, kb, 528);
                lda(al0, sb + 68608, wm * 32 + gid,      kb, 528);
                lda(al1, sb + 68608, wm * 32 + 16 + gid, kb, 528);
                #pragma unroll
                for (int nt = 0; nt < 4; ++nt) {
                    uint32_t bh[2], bl[2];
                    int n = wn * 32 + nt * 8 + gid;
                    ldb(bh, bb,         n, ks * 32 + tig * 4);
                    ldb(bl, bb + 10240, n, ks * 32 + tig * 4);
                    mmab(c2[0][nt], ah0, bh); mmab(c2[1][nt], ah1, bh);
                    mmab(c2[0][nt], al0, bh); mmab(c2[1][nt], al1, bh);
                    mmab(c2[0][nt], ah0, bl); mmab(c2[1][nt], ah1, bl);
                }
            }
            cur ^= 1;
        }

        // ================= epilogue2: RK4 combine =================
        size_t kb0 = (size_t)blockIdx.x * 8192 + tid;
        #pragma unroll
        for (int mt = 0; mt < 2; ++mt)
            #pragma unroll
            for (int half = 0; half < 2; ++half) {
                int row = wm * 32 + mt * 16 + gid + half * 8;
                float dt = dtss[row];
                #pragma unroll
                for (int nt = 0; nt < 4; ++nt) {
                    int colb = wn * 32 + nt * 8 + tig * 2;
                    float2 hv = *(const float2*)(hidden + (rowbase + row) * 128 + colb);
                    float a0, a1;
                    #pragma unroll
                    for (int jj = 0; jj < 2; ++jj) {
                        int col = colb + jj;
                        float kv = c2[mt][nt][half * 2 + jj] + b2s[col];
                        float h = jj ? hv.y : hv.x;
                        int j = mt * 16 + nt * 4 + half * 2 + jj;
                        size_t si = kb0 + (size_t)j * 256;
                        float arg;
                        if (s == 0) {
                            g_k1[si] = kv;
                            arg = h + dt * (kv * (1.0f / 3.0f));
                        } else if (s == 1) {
                            float k1 = g_k1[si];
                            scr2[si] = kv;
                            arg = h + dt * (kv - k1 * (1.0f / 3.0f));
                        } else if (s == 2) {
                            float k1 = g_k1[si], k2 = scr2[si];
                            arg = h + dt * (k1 - k2 + kv);
                            g_k1[si] = k1 + 3.0f * (k2 + kv);
                        } else {
                            float acc = g_k1[si];
                            arg = (dt > 0.0f) ? (h + dt * (acc + kv) * 0.125f) : h;
                        }
                        if (jj) a1 = arg; else a0 = arg;
                    }
                    if (s == 3) {
                        float2 o; o.x = a0; o.y = a1;
                        *(float2*)(evolved + (rowbase + row) * 128 + colb) = o;
                    } else {
                        uint32_t hi, lo; sp2(a0, a1, hi, lo);
                        *(uint32_t*)(sm8 + row * 272 + colb * 2) = hi;
                        *(uint32_t*)(sm8 + 17408 + row * 272 + colb * 2) = lo;
                    }
                }
            }
    }
}

// ---------------- GRU: 64 rows/CTA ----------------
// smem: AH 0(33792) AL 33792 | EV 67584(33792) | B 101376(2x20480)
//       brz 142336(1024) bin 143360(512) bhn 143872(512) mask 144384(256)
#define GRU_SM 144640
__global__ void __launch_bounds__(NT, 1) gru_kernel(
    const float* __restrict__ evolved, const float* __restrict__ obs,
    const int* __restrict__ mask,
    const float* __restrict__ bih, const float* __restrict__ bhh,
    float* __restrict__ updated)
{
    extern __shared__ uint8_t sm8[];
    const uint32_t sb = s2u(sm8);
    float* brz  = (float*)(sm8 + 142336);
    float* bin  = (float*)(sm8 + 143360);
    float* bhn  = (float*)(sm8 + 143872);
    int*   mskS = (int*)(sm8 + 144384);

    const int tid = threadIdx.x, lane = tid & 31, wrp = tid >> 5;
    const int gid = lane >> 2, tig = lane & 3;
    const int wm = wrp >> 2, wn = wrp & 3;
    const size_t rowbase = (size_t)blockIdx.x * 64;

    brz[tid] = bih[tid] + bhh[tid];
    if (tid < 128) { bin[tid] = bih[256 + tid]; bhn[tid] = bhh[256 + tid]; }
    if (tid < 64)  mskS[tid] = __ldg(mask + rowbase + tid);
    for (int idx = tid; idx < 8192; idx += NT) {
        int r = idx >> 7, c = idx & 127;
        float vo = __ldg(obs + (rowbase + r) * 128 + c);
        float ve = __ldg(evolved + (rowbase + r) * 128 + c);
        __nv_bfloat16 oh = __float2bfloat16_rn(vo);
        __nv_bfloat16 ol = __float2bfloat16_rn(vo - __bfloat162float(oh));
        __nv_bfloat16 eh = __float2bfloat16_rn(ve);
        __nv_bfloat16 el = __float2bfloat16_rn(ve - __bfloat162float(eh));
        *(uint16_t*)(sm8 + r * 528 + c * 2) = __bfloat16_as_ushort(oh);
        *(uint16_t*)(sm8 + r * 528 + 256 + c * 2) = __bfloat16_as_ushort(eh);
        *(uint16_t*)(sm8 + 33792 + r * 528 + c * 2) = __bfloat16_as_ushort(ol);
        *(uint16_t*)(sm8 + 33792 + r * 528 + 256 + c * 2) = __bfloat16_as_ushort(el);
        *(float*)(sm8 + 67584 + r * 528 + c * 4) = ve;
    }
    int cur = 0;
    issueB(sb + 101376, pIN[0], pIN[1], 128, 256, 0, tid);
    __syncthreads();

    auto rungate = [&](float acc[2][4][4], int kab, const uint8_t* hi, const uint8_t* lo,
                       int nch, int rb, const uint8_t* nhi, const uint8_t* nlo, int nrb) {
        #pragma unroll
        for (int mt = 0; mt < 2; ++mt)
            #pragma unroll
            for (int nt = 0; nt < 4; ++nt)
                #pragma unroll
                for (int e = 0; e < 4; ++e) acc[mt][nt][e] = 0.f;
        #pragma unroll 1
        for (int kc = 0; kc < nch; ++kc) {
            __syncthreads();
            bool more = true;
            if (kc + 1 < nch)  issueB(sb + 101376 + (cur ^ 1) * 20480, hi, lo, 128, rb, kc + 1, tid);
            else if (nhi)      issueB(sb + 101376 + (cur ^ 1) * 20480, nhi, nlo, 128, nrb, 0, tid);
            else more = false;
            if (more) { WAIT1; } else { WAIT0; }
            __syncthreads();
            uint32_t bb = sb + 101376 + cur * 20480;
            #pragma unroll
            for (int ks = 0; ks < 2; ++ks) {
                int kb = kab + (kc * 32 + ks * 16) * 2 + tig * 4;
                uint32_t ah0[4], ah1[4], al0[4], al1[4];
                lda(ah0, sb,         wm * 32 + gid,      kb, 528);
                lda(ah1, sb,         wm * 32 + 16 + gid, kb, 528);
                lda(al0, sb + 33792, wm * 32 + gid,      kb, 528);
                lda(al1, sb + 33792, wm * 32 + 16 + gid, kb, 528);
                #pragma unroll
                for (int nt = 0; nt < 4; ++nt) {
                    uint32_t bh[2], bl[2];
                    int n = wn * 32 + nt * 8 + gid;
                    ldb(bh, bb,         n, ks * 32 + tig * 4);
                    ldb(bl, bb + 10240, n, ks * 32 + tig * 4);
                    mmab(acc[0][nt], ah0, bh); mmab(acc[1][nt], ah1, bh);
                    mmab(acc[0][nt], al0, bh); mmab(acc[1][nt], al1, bh);
                    mmab(acc[0][nt], ah0, bl); mmab(acc[1][nt], ah1, bl);
                }
            }
            cur ^= 1;
        }
    };

    float aN[2][4][4], aH[2][4][4], aG[2][4][4];
    rungate(aN, 0,   pIN[0], pIN[1], 4, 256, pHN[0], pHN[1], 256);   // in
    rungate(aH, 256, pHN[0], pHN[1], 4, 256, pR[0],  pR[1],  512);   // hn
    rungate(aG, 0,   pR[0],  pR[1],  8, 512, pZ[0],  pZ[1],  512);   // r
    // n = tanh(in + bin + r*(hn + bhn))
    #pragma unroll
    for (int mt = 0; mt < 2; ++mt)
        #pragma unroll
        for (int nt = 0; nt < 4; ++nt)
            #pragma unroll
            for (int e = 0; e < 4; ++e) {
                int col = wn * 32 + nt * 8 + tig * 2 + (e & 1);
                float r = 1.0f / (1.0f + __expf(-(aG[mt][nt][e] + brz[col])));
                aN[mt][nt][e] = tanhf(aN[mt][nt][e] + bin[col] + r * (aH[mt][nt][e] + bhn[col]));
            }
    rungate(aG, 0, pZ[0], pZ[1], 8, 512, (const uint8_t*)0, (const uint8_t*)0, 0);   // z

    #pragma unroll
    for (int mt = 0; mt < 2; ++mt)
        #pragma unroll
        for (int half = 0; half < 2; ++half) {
            int row = wm * 32 + mt * 16 + gid + half * 8;
            int msk = mskS[row];
            #pragma unroll
            for (int nt = 0; nt < 4; ++nt) {
                int colb = wn * 32 + nt * 8 + tig * 2;
                float2 ev = *(const float2*)(sm8 + 67584 + row * 528 + colb * 4);
                float2 o;
                {
                    float z = 1.0f / (1.0f + __expf(-(aG[mt][nt][half * 2] + brz[128 + colb])));
                    float g = (1.0f - z) * aN[mt][nt][half * 2] + z * ev.x;
                    o.x = (msk > 0) ? g : ev.x;
                }
                {
                    float z = 1.0f / (1.0f + __expf(-(aG[mt][nt][half * 2 + 1] + brz[128 + colb + 1])));
                    float g = (1.0f - z) * aN[mt][nt][half * 2 + 1] + z * ev.y;
                    o.y = (msk > 0) ? g : ev.y;
                }
                *(float2*)(updated + (rowbase + row) * 128 + colb) = o;
            }
        }
}

// ---------------------------------------------------------------------------
extern "C" void kernel_launch(void* const* d_in, const int* in_sizes, int n_in,
                              void* d_out, int out_size)
{
    const float* hidden = (const float*)d_in[0];
    const float* dts    = (const float*)d_in[1];
    const float* obs    = (const float*)d_in[2];
    const int*   mask   = (const int*)d_in[3];
    const float* w1     = (const float*)d_in[4];
    const float* b1     = (const float*)d_in[5];
    const float* lnw    = (const float*)d_in[6];
    const float* lnb    = (const float*)d_in[7];
    const float* w2     = (const float*)d_in[8];
    const float* b2     = (const float*)d_in[9];
    const float* wih    = (const float*)d_in[10];
    const float* whh    = (const float*)d_in[11];
    const float* bih    = (const float*)d_in[12];
    const float* bhh    = (const float*)d_in[13];

    float* evolved = (float*)d_out;
    float* updated = evolved + (size_t)131072 * 128;

    cudaFuncSetAttribute(evolve_kernel, cudaFuncAttributeMaxDynamicSharedMemorySize, EV_SM);
    cudaFuncSetAttribute(gru_kernel, cudaFuncAttributeMaxDynamicSharedMemorySize, GRU_SM);

    prep_kernel<<<640, 256>>>(w1, w2, wih, whh);
    evolve_kernel<<<2048, NT, EV_SM>>>(hidden, dts, b1, lnw, lnb, b2, evolved, updated);
    gru_kernel<<<2048, NT, GRU_SM>>>(evolved, obs, mask, bih, bhh, updated);
}

// round 12
// speedup vs baseline: 2.0485x; 1.0855x over previous
#include <cuda_runtime.h>
#include <cuda_bf16.h>
#include <math.h>
#include <stdint.h>

#define NT 256

// ---------------- weight images: [n][k] bf16, hi/lo planes ----------------
__device__ __align__(16) uint8_t pB1[2][65536];   // w1^T  [256][128]
__device__ __align__(16) uint8_t pB2[2][65536];   // w2^T  [128][256]
__device__ __align__(16) uint8_t pR [2][65536];   // r gate [128][256] (wih_r||whh_r)
__device__ __align__(16) uint8_t pZ [2][65536];   // z gate [128][256]
__device__ __align__(16) uint8_t pIN[2][32768];   // wih_n [128][128]
__device__ __align__(16) uint8_t pHN[2][32768];   // whh_n [128][128]

__device__ __forceinline__ void wsp(float x, uint8_t* hi, uint8_t* lo, uint32_t o) {
    __nv_bfloat16 h = __float2bfloat16_rn(x);
    __nv_bfloat16 l = __float2bfloat16_rn(x - __bfloat162float(h));
    *(uint16_t*)(hi + o) = __bfloat16_as_ushort(h);
    *(uint16_t*)(lo + o) = __bfloat16_as_ushort(l);
}

__global__ void prep_kernel(const float* __restrict__ w1, const float* __restrict__ w2,
                            const float* __restrict__ wih, const float* __restrict__ whh) {
    int i = blockIdx.x * blockDim.x + threadIdx.x;
    if (i < 32768) {
        int n = i >> 7, k = i & 127;
        wsp(w1[k * 256 + n], pB1[0], pB1[1], (uint32_t)(n * 128 + k) * 2);
    } else if (i < 65536) {
        int t = i - 32768, n = t >> 8, k = t & 255;
        wsp(w2[k * 128 + n], pB2[0], pB2[1], (uint32_t)(n * 256 + k) * 2);
    } else if (i < 98304) {
        int t = i - 65536, n = t >> 8, k = t & 255;
        float v = (k < 128) ? wih[n * 128 + k] : whh[n * 128 + (k - 128)];
        wsp(v, pR[0], pR[1], (uint32_t)(n * 256 + k) * 2);
    } else if (i < 131072) {
        int t = i - 98304, n = t >> 8, k = t & 255;
        float v = (k < 128) ? wih[(128 + n) * 128 + k] : whh[(128 + n) * 128 + (k - 128)];
        wsp(v, pZ[0], pZ[1], (uint32_t)(n * 256 + k) * 2);
    } else if (i < 147456) {
        int t = i - 131072, n = t >> 7, k = t & 127;
        wsp(wih[(256 + n) * 128 + k], pIN[0], pIN[1], (uint32_t)(n * 128 + k) * 2);
    } else if (i < 163840) {
        int t = i - 147456, n = t >> 7, k = t & 127;
        wsp(whh[(256 + n) * 128 + k], pHN[0], pHN[1], (uint32_t)(n * 128 + k) * 2);
    }
}

// ---------------- helpers ----------------
__device__ __forceinline__ uint32_t s2u(const void* p) {
    uint32_t a;
    asm("{.reg .u64 t; cvta.to.shared.u64 t,%1; cvt.u32.u64 %0,t;}" : "=r"(a) : "l"(p));
    return a;
}
__device__ __forceinline__ void cpa(uint32_t d, const void* s) {
    asm volatile("cp.async.cg.shared.global [%0],[%1],16;" :: "r"(d), "l"(s) : "memory");
}
#define CPC()  asm volatile("cp.async.commit_group;" ::: "memory")
#define WAIT1 asm volatile("cp.async.wait_group 1;" ::: "memory")
#define WAIT0 asm volatile("cp.async.wait_group 0;" ::: "memory")

__device__ __forceinline__ void mmab(float c[4], const uint32_t a[4], const uint32_t b[2]) {
    asm volatile("mma.sync.aligned.m16n8k16.row.col.f32.bf16.bf16.f32 "
        "{%0,%1,%2,%3},{%4,%5,%6,%7},{%8,%9},{%0,%1,%2,%3};"
        : "+f"(c[0]), "+f"(c[1]), "+f"(c[2]), "+f"(c[3])
        : "r"(a[0]), "r"(a[1]), "r"(a[2]), "r"(a[3]), "r"(b[0]), "r"(b[1]));
}
__device__ __forceinline__ void ldm4(uint32_t f[4], uint32_t addr) {
    asm volatile("ldmatrix.sync.aligned.m8n8.x4.shared.b16 {%0,%1,%2,%3},[%4];"
        : "=r"(f[0]), "=r"(f[1]), "=r"(f[2]), "=r"(f[3]) : "r"(addr));
}
// A tile 16x16: m0 rows0-7/k0-7, m1 rows8-15/k0-7, m2 rows0-7/k8-15, m3 rows8-15/k8-15
__device__ __forceinline__ uint32_t aaddr(uint32_t plane, int rowTile, int kb,
                                          int stride, int lane) {
    int r = rowTile + (lane & 7) + (lane & 8);
    int ko = kb + ((lane & 16) ? 16 : 0);
    return plane + (uint32_t)(r * stride + ko);
}
// B pair (two 8n x 16k tiles): m0 n0/k0-7, m1 n0/k8-15, m2 n0+8/k0-7, m3 n0+8/k8-15
__device__ __forceinline__ uint32_t baddr(uint32_t plane, int n0, int kbyte, int lane) {
    int n = n0 + (lane & 7) + ((lane & 16) ? 8 : 0);
    int ko = kbyte + ((lane & 8) ? 16 : 0);
    return plane + (uint32_t)(n * 80 + ko);
}
__device__ __forceinline__ void sp2(float v0, float v1, uint32_t& hi, uint32_t& lo) {
    __nv_bfloat16 h0 = __float2bfloat16_rn(v0), h1 = __float2bfloat16_rn(v1);
    __nv_bfloat16 l0 = __float2bfloat16_rn(v0 - __bfloat162float(h0));
    __nv_bfloat16 l1 = __float2bfloat16_rn(v1 - __bfloat162float(h1));
    hi = (uint32_t)__bfloat16_as_ushort(h0) | ((uint32_t)__bfloat16_as_ushort(h1) << 16);
    lo = (uint32_t)__bfloat16_as_ushort(l0) | ((uint32_t)__bfloat16_as_ushort(l1) << 16);
}
// stream a [Nn][32k] hi+lo chunk into smem (row stride 80B, bank-conflict-free)
__device__ __forceinline__ void issueB(uint32_t dst, const uint8_t* hi, const uint8_t* lo,
                                       int Nn, int rowbytes, int kc, int tid) {
    const int perplane = Nn * 4, tot = perplane * 2, psz = Nn * 80;
    for (int f = tid; f < tot; f += NT) {
        int p = f >= perplane;
        int r2 = p ? f - perplane : f;
        int r = r2 >> 2, q = r2 & 3;
        const uint8_t* s = (p ? lo : hi) + (size_t)r * rowbytes + kc * 64 + q * 16;
        cpa(dst + (uint32_t)(p * psz + r * 80 + q * 16), s);
    }
    CPC();
}

// ---------------- evolve: RK4(3/8), 64 rows/CTA ----------------
// smem: AH 0(17408) AL 17408 | A2H 34816(33792) A2L 68608 | B 102400(2x40960)
//       stats 184320(2048) b1 186368(1024) lnw 187392 lnb 188416 b2 189440(512)
#define EV_SM 189952
__global__ void __launch_bounds__(NT, 1) evolve_kernel(
    const float* __restrict__ hidden, const float* __restrict__ dts,
    const float* __restrict__ b1, const float* __restrict__ lnw,
    const float* __restrict__ lnb, const float* __restrict__ b2,
    float* __restrict__ evolved)
{
    extern __shared__ uint8_t sm8[];
    const uint32_t sb = s2u(sm8);
    float* stats = (float*)(sm8 + 184320);
    float* b1s   = (float*)(sm8 + 186368);
    float* lnws  = (float*)(sm8 + 187392);
    float* lnbs  = (float*)(sm8 + 188416);
    float* b2s   = (float*)(sm8 + 189440);

    const int tid = threadIdx.x, lane = tid & 31, wrp = tid >> 5;
    const int gid = lane >> 2, tig = lane & 3;
    const int wm = wrp >> 2, wn = wrp & 3;
    const size_t rowbase = (size_t)blockIdx.x * 64;

    b1s[tid] = b1[tid]; lnws[tid] = lnw[tid]; lnbs[tid] = lnb[tid];
    if (tid < 128) b2s[tid] = b2[tid];
    // A0 = split(h)
    for (int idx = tid; idx < 8192; idx += NT) {
        int r = idx >> 7, c = idx & 127;
        float v = __ldg(hidden + (rowbase + r) * 128 + c);
        __nv_bfloat16 h = __float2bfloat16_rn(v);
        __nv_bfloat16 l = __float2bfloat16_rn(v - __bfloat162float(h));
        *(uint16_t*)(sm8 + r * 272 + c * 2) = __bfloat16_as_ushort(h);
        *(uint16_t*)(sm8 + 17408 + r * 272 + c * 2) = __bfloat16_as_ushort(l);
    }
    // h, dt in fragment coords (registers) — no gmem RTT in epilogues
    float hreg[32], dtr[4];
    #pragma unroll
    for (int mt = 0; mt < 2; ++mt)
        #pragma unroll
        for (int half = 0; half < 2; ++half) {
            int row = wm * 32 + mt * 16 + gid + half * 8;
            dtr[mt * 2 + half] = fmaxf(__ldg(dts + rowbase + row), 0.0f);
            #pragma unroll
            for (int nt = 0; nt < 4; ++nt) {
                float2 hv = __ldg((const float2*)(hidden + (rowbase + row) * 128
                                                  + wn * 32 + nt * 8 + tig * 2));
                hreg[mt * 16 + nt * 4 + half * 2]     = hv.x;
                hreg[mt * 16 + nt * 4 + half * 2 + 1] = hv.y;
            }
        }
    float k1r[32], pr[32];

    int cur = 0;
    issueB(sb + 102400, pB1[0], pB1[1], 256, 256, 0, tid);   // mm1 chunk0 -> buf0
    __syncthreads();

    #pragma unroll 1
    for (int s = 0; s < 4; ++s) {
        // ================= mm1: N=256, K=128 (4 chunks) =================
        float c1[2][8][4];
        #pragma unroll
        for (int mt = 0; mt < 2; ++mt)
            #pragma unroll
            for (int nt = 0; nt < 8; ++nt)
                #pragma unroll
                for (int e = 0; e < 4; ++e) c1[mt][nt][e] = 0.f;

        #pragma unroll 1
        for (int kc = 0; kc < 4; ++kc) {
            __syncthreads();
            if (kc < 3) issueB(sb + 102400 + (cur ^ 1) * 40960, pB1[0], pB1[1], 256, 256, kc + 1, tid);
            else        issueB(sb + 102400 + (cur ^ 1) * 40960, pB2[0], pB2[1], 128, 512, 0, tid);
            WAIT1;
            __syncthreads();
            uint32_t bb = sb + 102400 + cur * 40960;
            #pragma unroll
            for (int ks = 0; ks < 2; ++ks) {
                int kb = (kc * 32 + ks * 16) * 2;
                uint32_t ah0[4], ah1[4], al0[4], al1[4];
                ldm4(ah0, aaddr(sb,         wm * 32,      kb, 272, lane));
                ldm4(ah1, aaddr(sb,         wm * 32 + 16, kb, 272, lane));
                ldm4(al0, aaddr(sb + 17408, wm * 32,      kb, 272, lane));
                ldm4(al1, aaddr(sb + 17408, wm * 32 + 16, kb, 272, lane));
                #pragma unroll
                for (int np = 0; np < 4; ++np) {
                    uint32_t bh[4], bl[4];
                    ldm4(bh, baddr(bb,         wn * 64 + np * 16, ks * 32, lane));
                    ldm4(bl, baddr(bb + 20480, wn * 64 + np * 16, ks * 32, lane));
                    mmab(c1[0][2 * np], ah0, bh);     mmab(c1[1][2 * np], ah1, bh);
                    mmab(c1[0][2 * np], al0, bh);     mmab(c1[1][2 * np], al1, bh);
                    mmab(c1[0][2 * np], ah0, bl);     mmab(c1[1][2 * np], ah1, bl);
                    mmab(c1[0][2 * np + 1], ah0, bh + 2); mmab(c1[1][2 * np + 1], ah1, bh + 2);
                    mmab(c1[0][2 * np + 1], al0, bh + 2); mmab(c1[1][2 * np + 1], al1, bh + 2);
                    mmab(c1[0][2 * np + 1], ah0, bl + 2); mmab(c1[1][2 * np + 1], ah1, bl + 2);
                }
            }
            cur ^= 1;
        }

        // ================= epilogue1: +b1, LN, GELU -> A2 =================
        #pragma unroll
        for (int mt = 0; mt < 2; ++mt)
            #pragma unroll
            for (int half = 0; half < 2; ++half) {
                float s1 = 0.f, s2 = 0.f;
                #pragma unroll
                for (int nt = 0; nt < 8; ++nt)
                    #pragma unroll
                    for (int j = 0; j < 2; ++j) {
                        int col = wn * 64 + nt * 8 + tig * 2 + j;
                        float v = c1[mt][nt][half * 2 + j] + b1s[col];
                        c1[mt][nt][half * 2 + j] = v;
                        s1 += v; s2 += v * v;
                    }
                s1 += __shfl_xor_sync(0xffffffffu, s1, 1);
                s1 += __shfl_xor_sync(0xffffffffu, s1, 2);
                s2 += __shfl_xor_sync(0xffffffffu, s2, 1);
                s2 += __shfl_xor_sync(0xffffffffu, s2, 2);
                if (tig == 0) {
                    int row = wm * 32 + mt * 16 + gid + half * 8;
                    stats[row * 8 + wn * 2] = s1;
                    stats[row * 8 + wn * 2 + 1] = s2;
                }
            }
        __syncthreads();
        #pragma unroll
        for (int mt = 0; mt < 2; ++mt)
            #pragma unroll
            for (int half = 0; half < 2; ++half) {
                int row = wm * 32 + mt * 16 + gid + half * 8;
                float t1 = stats[row * 8] + stats[row * 8 + 2] + stats[row * 8 + 4] + stats[row * 8 + 6];
                float t2 = stats[row * 8 + 1] + stats[row * 8 + 3] + stats[row * 8 + 5] + stats[row * 8 + 7];
                float mu = t1 * (1.0f / 256.0f);
                float var = t2 * (1.0f / 256.0f) - mu * mu;
                float rstd = rsqrtf(var + 1e-5f);
                #pragma unroll
                for (int nt = 0; nt < 8; ++nt) {
                    int col0 = wn * 64 + nt * 8 + tig * 2;
                    float v0 = (c1[mt][nt][half * 2] - mu) * rstd * lnws[col0] + lnbs[col0];
                    float v1 = (c1[mt][nt][half * 2 + 1] - mu) * rstd * lnws[col0 + 1] + lnbs[col0 + 1];
                    float g0 = v0 * normcdff(v0), g1 = v1 * normcdff(v1);
                    uint32_t hi, lo; sp2(g0, g1, hi, lo);
                    *(uint32_t*)(sm8 + 34816 + row * 528 + col0 * 2) = hi;
                    *(uint32_t*)(sm8 + 68608 + row * 528 + col0 * 2) = lo;
                }
            }

        // ================= mm2: N=128, K=256 (8 chunks) =================
        float c2[2][4][4];
        #pragma unroll
        for (int mt = 0; mt < 2; ++mt)
            #pragma unroll
            for (int nt = 0; nt < 4; ++nt)
                #pragma unroll
                for (int e = 0; e < 4; ++e) c2[mt][nt][e] = 0.f;

        #pragma unroll 1
        for (int kc = 0; kc < 8; ++kc) {
            __syncthreads();
            bool more = true;
            if (kc < 7)      issueB(sb + 102400 + (cur ^ 1) * 40960, pB2[0], pB2[1], 128, 512, kc + 1, tid);
            else if (s < 3)  issueB(sb + 102400 + (cur ^ 1) * 40960, pB1[0], pB1[1], 256, 256, 0, tid);
            else more = false;
            if (more) { WAIT1; } else { WAIT0; }
            __syncthreads();
            uint32_t bb = sb + 102400 + cur * 40960;
            #pragma unroll
            for (int ks = 0; ks < 2; ++ks) {
                int kb = (kc * 32 + ks * 16) * 2;
                uint32_t ah0[4], ah1[4], al0[4], al1[4];
                ldm4(ah0, aaddr(sb + 34816, wm * 32,      kb, 528, lane));
                ldm4(ah1, aaddr(sb + 34816, wm * 32 + 16, kb, 528, lane));
                ldm4(al0, aaddr(sb + 68608, wm * 32,      kb, 528, lane));
                ldm4(al1, aaddr(sb + 68608, wm * 32 + 16, kb, 528, lane));
                #pragma unroll
                for (int np = 0; np < 2; ++np) {
                    uint32_t bh[4], bl[4];
                    ldm4(bh, baddr(bb,         wn * 32 + np * 16, ks * 32, lane));
                    ldm4(bl, baddr(bb + 10240, wn * 32 + np * 16, ks * 32, lane));
                    mmab(c2[0][2 * np], ah0, bh);     mmab(c2[1][2 * np], ah1, bh);
                    mmab(c2[0][2 * np], al0, bh);     mmab(c2[1][2 * np], al1, bh);
                    mmab(c2[0][2 * np], ah0, bl);     mmab(c2[1][2 * np], ah1, bl);
                    mmab(c2[0][2 * np + 1], ah0, bh + 2); mmab(c2[1][2 * np + 1], ah1, bh + 2);
                    mmab(c2[0][2 * np + 1], al0, bh + 2); mmab(c2[1][2 * np + 1], al1, bh + 2);
                    mmab(c2[0][2 * np + 1], ah0, bl + 2); mmab(c2[1][2 * np + 1], ah1, bl + 2);
                }
            }
            cur ^= 1;
        }

        // ================= epilogue2: RK4 combine (register state) =========
        #pragma unroll
        for (int mt = 0; mt < 2; ++mt)
            #pragma unroll
            for (int half = 0; half < 2; ++half) {
                int row = wm * 32 + mt * 16 + gid + half * 8;
                float dt = dtr[mt * 2 + half];
                #pragma unroll
                for (int nt = 0; nt < 4; ++nt) {
                    int colb = wn * 32 + nt * 8 + tig * 2;
                    float a0 = 0.f, a1 = 0.f;
                    #pragma unroll
                    for (int jj = 0; jj < 2; ++jj) {
                        int j = mt * 16 + nt * 4 + half * 2 + jj;
                        float kv = c2[mt][nt][half * 2 + jj] + b2s[colb + jj];
                        float h = hreg[j];
                        float arg;
                        if (s == 0) {
                            k1r[j] = kv;
                            arg = h + dt * (kv * (1.0f / 3.0f));
                        } else if (s == 1) {
                            pr[j] = k1r[j] - kv;
                            arg = h + dt * (kv - k1r[j] * (1.0f / 3.0f));
                        } else if (s == 2) {
                            arg = h + dt * (pr[j] + kv);
                            pr[j] = 4.0f * k1r[j] - 3.0f * pr[j] + 3.0f * kv;
                        } else {
                            arg = (dt > 0.0f) ? (h + dt * (pr[j] + kv) * 0.125f) : h;
                        }
                        if (jj) a1 = arg; else a0 = arg;
                    }
                    if (s == 3) {
                        float2 o; o.x = a0; o.y = a1;
                        *(float2*)(evolved + (rowbase + row) * 128 + colb) = o;
                    } else {
                        uint32_t hi, lo; sp2(a0, a1, hi, lo);
                        *(uint32_t*)(sm8 + row * 272 + colb * 2) = hi;
                        *(uint32_t*)(sm8 + 17408 + row * 272 + colb * 2) = lo;
                    }
                }
            }
    }
}

// ---------------- GRU: 64 rows/CTA ----------------
// smem: AH 0(33792) AL 33792 | EV 67584(33792) | B 101376(2x20480)
//       brz 142336(1024) bin 143360(512) bhn 143872(512) mask 144384(256)
#define GRU_SM 144640
__global__ void __launch_bounds__(NT, 1) gru_kernel(
    const float* __restrict__ evolved, const float* __restrict__ obs,
    const int* __restrict__ mask,
    const float* __restrict__ bih, const float* __restrict__ bhh,
    float* __restrict__ updated)
{
    extern __shared__ uint8_t sm8[];
    const uint32_t sb = s2u(sm8);
    float* brz  = (float*)(sm8 + 142336);
    float* bin  = (float*)(sm8 + 143360);
    float* bhn  = (float*)(sm8 + 143872);
    int*   mskS = (int*)(sm8 + 144384);

    const int tid = threadIdx.x, lane = tid & 31, wrp = tid >> 5;
    const int gid = lane >> 2, tig = lane & 3;
    const int wm = wrp >> 2, wn = wrp & 3;
    const size_t rowbase = (size_t)blockIdx.x * 64;

    brz[tid] = bih[tid] + bhh[tid];
    if (tid < 128) { bin[tid] = bih[256 + tid]; bhn[tid] = bhh[256 + tid]; }
    if (tid < 64)  mskS[tid] = __ldg(mask + rowbase + tid);
    for (int idx = tid; idx < 8192; idx += NT) {
        int r = idx >> 7, c = idx & 127;
        float vo = __ldg(obs + (rowbase + r) * 128 + c);
        float ve = __ldg(evolved + (rowbase + r) * 128 + c);
        __nv_bfloat16 oh = __float2bfloat16_rn(vo);
        __nv_bfloat16 ol = __float2bfloat16_rn(vo - __bfloat162float(oh));
        __nv_bfloat16 eh = __float2bfloat16_rn(ve);
        __nv_bfloat16 el = __float2bfloat16_rn(ve - __bfloat162float(eh));
        *(uint16_t*)(sm8 + r * 528 + c * 2) = __bfloat16_as_ushort(oh);
        *(uint16_t*)(sm8 + r * 528 + 256 + c * 2) = __bfloat16_as_ushort(eh);
        *(uint16_t*)(sm8 + 33792 + r * 528 + c * 2) = __bfloat16_as_ushort(ol);
        *(uint16_t*)(sm8 + 33792 + r * 528 + 256 + c * 2) = __bfloat16_as_ushort(el);
        *(float*)(sm8 + 67584 + r * 528 + c * 4) = ve;
    }
    int cur = 0;
    issueB(sb + 101376, pIN[0], pIN[1], 128, 256, 0, tid);
    __syncthreads();

    auto rungate = [&](float acc[2][4][4], int kab, const uint8_t* hi, const uint8_t* lo,
                       int nch, int rb, const uint8_t* nhi, const uint8_t* nlo, int nrb) {
        #pragma unroll
        for (int mt = 0; mt < 2; ++mt)
            #pragma unroll
            for (int nt = 0; nt < 4; ++nt)
                #pragma unroll
                for (int e = 0; e < 4; ++e) acc[mt][nt][e] = 0.f;
        #pragma unroll 1
        for (int kc = 0; kc < nch; ++kc) {
            __syncthreads();
            bool more = true;
            if (kc + 1 < nch)  issueB(sb + 101376 + (cur ^ 1) * 20480, hi, lo, 128, rb, kc + 1, tid);
            else if (nhi)      issueB(sb + 101376 + (cur ^ 1) * 20480, nhi, nlo, 128, nrb, 0, tid);
            else more = false;
            if (more) { WAIT1; } else { WAIT0; }
            __syncthreads();
            uint32_t bb = sb + 101376 + cur * 20480;
            #pragma unroll
            for (int ks = 0; ks < 2; ++ks) {
                int kb = kab + (kc * 32 + ks * 16) * 2;
                uint32_t ah0[4], ah1[4], al0[4], al1[4];
                ldm4(ah0, aaddr(sb,         wm * 32,      kb, 528, lane));
                ldm4(ah1, aaddr(sb,         wm * 32 + 16, kb, 528, lane));
                ldm4(al0, aaddr(sb + 33792, wm * 32,      kb, 528, lane));
                ldm4(al1, aaddr(sb + 33792, wm * 32 + 16, kb, 528, lane));
                #pragma unroll
                for (int np = 0; np < 2; ++np) {
                    uint32_t bh[4], bl[4];
                    ldm4(bh, baddr(bb,         wn * 32 + np * 16, ks * 32, lane));
                    ldm4(bl, baddr(bb + 10240, wn * 32 + np * 16, ks * 32, lane));
                    mmab(acc[0][2 * np], ah0, bh);     mmab(acc[1][2 * np], ah1, bh);
                    mmab(acc[0][2 * np], al0, bh);     mmab(acc[1][2 * np], al1, bh);
                    mmab(acc[0][2 * np], ah0, bl);     mmab(acc[1][2 * np], ah1, bl);
                    mmab(acc[0][2 * np + 1], ah0, bh + 2); mmab(acc[1][2 * np + 1], ah1, bh + 2);
                    mmab(acc[0][2 * np + 1], al0, bh + 2); mmab(acc[1][2 * np + 1], al1, bh + 2);
                    mmab(acc[0][2 * np + 1], ah0, bl + 2); mmab(acc[1][2 * np + 1], ah1, bl + 2);
                }
            }
            cur ^= 1;
        }
    };

    float aN[2][4][4], aH[2][4][4], aG[2][4][4];
    rungate(aN, 0,   pIN[0], pIN[1], 4, 256, pHN[0], pHN[1], 256);   // in
    rungate(aH, 256, pHN[0], pHN[1], 4, 256, pR[0],  pR[1],  512);   // hn
    rungate(aG, 0,   pR[0],  pR[1],  8, 512, pZ[0],  pZ[1],  512);   // r
    // n = tanh(in + bin + r*(hn + bhn))
    #pragma unroll
    for (int mt = 0; mt < 2; ++mt)
        #pragma unroll
        for (int nt = 0; nt < 4; ++nt)
            #pragma unroll
            for (int e = 0; e < 4; ++e) {
                int col = wn * 32 + nt * 8 + tig * 2 + (e & 1);
                float r = 1.0f / (1.0f + __expf(-(aG[mt][nt][e] + brz[col])));
                aN[mt][nt][e] = tanhf(aN[mt][nt][e] + bin[col] + r * (aH[mt][nt][e] + bhn[col]));
            }
    rungate(aG, 0, pZ[0], pZ[1], 8, 512, (const uint8_t*)0, (const uint8_t*)0, 0);   // z

    #pragma unroll
    for (int mt = 0; mt < 2; ++mt)
        #pragma unroll
        for (int half = 0; half < 2; ++half) {
            int row = wm * 32 + mt * 16 + gid + half * 8;
            int msk = mskS[row];
            #pragma unroll
            for (int nt = 0; nt < 4; ++nt) {
                int colb = wn * 32 + nt * 8 + tig * 2;
                float2 ev = *(const float2*)(sm8 + 67584 + row * 528 + colb * 4);
                float2 o;
                {
                    float z = 1.0f / (1.0f + __expf(-(aG[mt][nt][half * 2] + brz[128 + colb])));
                    float g = (1.0f - z) * aN[mt][nt][half * 2] + z * ev.x;
                    o.x = (msk > 0) ? g : ev.x;
                }
                {
                    float z = 1.0f / (1.0f + __expf(-(aG[mt][nt][half * 2 + 1] + brz[128 + colb + 1])));
                    float g = (1.0f - z) * aN[mt][nt][half * 2 + 1] + z * ev.y;
                    o.y = (msk > 0) ? g : ev.y;
                }
                *(float2*)(updated + (rowbase + row) * 128 + colb) = o;
            }
        }
}

// ---------------------------------------------------------------------------
extern "C" void kernel_launch(void* const* d_in, const int* in_sizes, int n_in,
                              void* d_out, int out_size)
{
    const float* hidden = (const float*)d_in[0];
    const float* dts    = (const float*)d_in[1];
    const float* obs    = (const float*)d_in[2];
    const int*   mask   = (const int*)d_in[3];
    const float* w1     = (const float*)d_in[4];
    const float* b1     = (const float*)d_in[5];
    const float* lnw    = (const float*)d_in[6];
    const float* lnb    = (const float*)d_in[7];
    const float* w2     = (const float*)d_in[8];
    const float* b2     = (const float*)d_in[9];
    const float* wih    = (const float*)d_in[10];
    const float* whh    = (const float*)d_in[11];
    const float* bih    = (const float*)d_in[12];
    const float* bhh    = (const float*)d_in[13];

    float* evolved = (float*)d_out;
    float* updated = evolved + (size_t)131072 * 128;

    cudaFuncSetAttribute(evolve_kernel, cudaFuncAttributeMaxDynamicSharedMemorySize, EV_SM);
    cudaFuncSetAttribute(gru_kernel, cudaFuncAttributeMaxDynamicSharedMemorySize, GRU_SM);

    prep_kernel<<<640, 256>>>(w1, w2, wih, whh);
    evolve_kernel<<<2048, NT, EV_SM>>>(hidden, dts, b1, lnw, lnb, b2, evolved);
    gru_kernel<<<2048, NT, GRU_SM>>>(evolved, obs, mask, bih, bhh, updated);
}

// round 13
// speedup vs baseline: 2.3645x; 1.1542x over previous
#include <cuda_runtime.h>
#include <cuda_bf16.h>
#include <math.h>
#include <stdint.h>

#define NT 256

// ---------------- weight images: [n][k] bf16, hi/lo planes ----------------
__device__ __align__(16) uint8_t pB1[2][65536];    // w1^T  [256][128]
__device__ __align__(16) uint8_t pB2[2][65536];    // w2^T  [128][256]
__device__ __align__(16) uint8_t pRZ[2][131072];   // rz interleaved [256][256]
__device__ __align__(16) uint8_t pIN[2][32768];    // wih_n [128][128]
__device__ __align__(16) uint8_t pHN[2][32768];    // whh_n [128][128]

__device__ __forceinline__ void wsp(float x, uint8_t* hi, uint8_t* lo, uint32_t o) {
    __nv_bfloat16 h = __float2bfloat16_rn(x);
    __nv_bfloat16 l = __float2bfloat16_rn(x - __bfloat162float(h));
    *(uint16_t*)(hi + o) = __bfloat16_as_ushort(h);
    *(uint16_t*)(lo + o) = __bfloat16_as_ushort(l);
}

__global__ void prep_kernel(const float* __restrict__ w1, const float* __restrict__ w2,
                            const float* __restrict__ wih, const float* __restrict__ whh) {
    int i = blockIdx.x * blockDim.x + threadIdx.x;
    if (i < 32768) {
        int n = i >> 7, k = i & 127;
        wsp(w1[k * 256 + n], pB1[0], pB1[1], (uint32_t)(n * 128 + k) * 2);
    } else if (i < 65536) {
        int t = i - 32768, n = t >> 8, k = t & 255;
        wsp(w2[k * 128 + n], pB2[0], pB2[1], (uint32_t)(n * 256 + k) * 2);
    } else if (i < 131072) {
        // rz merged, gate-interleaved: image row n -> h=(n>>6)*32+(n&31), gate=(n>>5)&1
        int t = i - 65536, n = t >> 8, k = t & 255;
        int h = (n >> 6) * 32 + (n & 31);
        int g = (n >> 5) & 1;
        int src = g * 128 + h;
        float v = (k < 128) ? wih[src * 128 + k] : whh[src * 128 + (k - 128)];
        wsp(v, pRZ[0], pRZ[1], (uint32_t)(n * 256 + k) * 2);
    } else if (i < 147456) {
        int t = i - 131072, n = t >> 7, k = t & 127;
        wsp(wih[(256 + n) * 128 + k], pIN[0], pIN[1], (uint32_t)(n * 128 + k) * 2);
    } else if (i < 163840) {
        int t = i - 147456, n = t >> 7, k = t & 127;
        wsp(whh[(256 + n) * 128 + k], pHN[0], pHN[1], (uint32_t)(n * 128 + k) * 2);
    }
}

// ---------------- helpers ----------------
__device__ __forceinline__ uint32_t s2u(const void* p) {
    uint32_t a;
    asm("{.reg .u64 t; cvta.to.shared.u64 t,%1; cvt.u32.u64 %0,t;}" : "=r"(a) : "l"(p));
    return a;
}
__device__ __forceinline__ void cpa(uint32_t d, const void* s) {
    asm volatile("cp.async.cg.shared.global [%0],[%1],16;" :: "r"(d), "l"(s) : "memory");
}
#define CPC()  asm volatile("cp.async.commit_group;" ::: "memory")
#define WAIT0 asm volatile("cp.async.wait_group 0;" ::: "memory")

__device__ __forceinline__ void mmab(float c[4], const uint32_t a[4], const uint32_t b[2]) {
    asm volatile("mma.sync.aligned.m16n8k16.row.col.f32.bf16.bf16.f32 "
        "{%0,%1,%2,%3},{%4,%5,%6,%7},{%8,%9},{%0,%1,%2,%3};"
        : "+f"(c[0]), "+f"(c[1]), "+f"(c[2]), "+f"(c[3])
        : "r"(a[0]), "r"(a[1]), "r"(a[2]), "r"(a[3]), "r"(b[0]), "r"(b[1]));
}
__device__ __forceinline__ void ldm4(uint32_t f[4], uint32_t addr) {
    asm volatile("ldmatrix.sync.aligned.m8n8.x4.shared.b16 {%0,%1,%2,%3},[%4];"
        : "=r"(f[0]), "=r"(f[1]), "=r"(f[2]), "=r"(f[3]) : "r"(addr));
}
__device__ __forceinline__ uint32_t aaddr(uint32_t plane, int rowTile, int kb,
                                          int stride, int lane) {
    int r = rowTile + (lane & 7) + (lane & 8);
    int ko = kb + ((lane & 16) ? 16 : 0);
    return plane + (uint32_t)(r * stride + ko);
}
__device__ __forceinline__ uint32_t baddr(uint32_t plane, int n0, int kbyte, int lane) {
    int n = n0 + (lane & 7) + ((lane & 16) ? 8 : 0);
    int ko = kbyte + ((lane & 8) ? 16 : 0);
    return plane + (uint32_t)(n * 80 + ko);
}
__device__ __forceinline__ void sp2(float v0, float v1, uint32_t& hi, uint32_t& lo) {
    __nv_bfloat16 h0 = __float2bfloat16_rn(v0), h1 = __float2bfloat16_rn(v1);
    __nv_bfloat16 l0 = __float2bfloat16_rn(v0 - __bfloat162float(h0));
    __nv_bfloat16 l1 = __float2bfloat16_rn(v1 - __bfloat162float(h1));
    hi = (uint32_t)__bfloat16_as_ushort(h0) | ((uint32_t)__bfloat16_as_ushort(h1) << 16);
    lo = (uint32_t)__bfloat16_as_ushort(l0) | ((uint32_t)__bfloat16_as_ushort(l1) << 16);
}
__device__ __forceinline__ void issueB(uint32_t dst, const uint8_t* hi, const uint8_t* lo,
                                       int Nn, int rowbytes, int kc, int tid) {
    const int perplane = Nn * 4, tot = perplane * 2, psz = Nn * 80;
    for (int f = tid; f < tot; f += NT) {
        int p = f >= perplane;
        int r2 = p ? f - perplane : f;
        int r = r2 >> 2, q = r2 & 3;
        const uint8_t* s = (p ? lo : hi) + (size_t)r * rowbytes + kc * 64 + q * 16;
        cpa(dst + (uint32_t)(p * psz + r * 80 + q * 16), s);
    }
    CPC();
}
__device__ __forceinline__ float gelu_e(float v) {
    return 0.5f * v * (1.0f + erff(v * 0.70710678f));
}

// ---------------- evolve: RK4(3/8), 64 rows/CTA ----------------
// smem: AH 0(17408) AL 17408 | A2H 34816(33792) A2L 68608 | B 102400(2x40960)
//       stats 184320(2048) b1 186368(1024) lnw 187392 lnb 188416 b2 189440(512)
#define EV_SM 189952
__global__ void __launch_bounds__(NT, 1) evolve_kernel(
    const float* __restrict__ hidden, const float* __restrict__ dts,
    const float* __restrict__ b1, const float* __restrict__ lnw,
    const float* __restrict__ lnb, const float* __restrict__ b2,
    float* __restrict__ evolved)
{
    extern __shared__ uint8_t sm8[];
    const uint32_t sb = s2u(sm8);
    float* stats = (float*)(sm8 + 184320);
    float* b1s   = (float*)(sm8 + 186368);
    float* lnws  = (float*)(sm8 + 187392);
    float* lnbs  = (float*)(sm8 + 188416);
    float* b2s   = (float*)(sm8 + 189440);

    const int tid = threadIdx.x, lane = tid & 31, wrp = tid >> 5;
    const int gid = lane >> 2, tig = lane & 3;
    const int wm = wrp >> 2, wn = wrp & 3;
    const size_t rowbase = (size_t)blockIdx.x * 64;

    b1s[tid] = b1[tid]; lnws[tid] = lnw[tid]; lnbs[tid] = lnb[tid];
    if (tid < 128) b2s[tid] = b2[tid];
    // A0 = split(h)
    for (int idx = tid; idx < 8192; idx += NT) {
        int r = idx >> 7, c = idx & 127;
        float v = __ldg(hidden + (rowbase + r) * 128 + c);
        __nv_bfloat16 h = __float2bfloat16_rn(v);
        __nv_bfloat16 l = __float2bfloat16_rn(v - __bfloat162float(h));
        *(uint16_t*)(sm8 + r * 272 + c * 2) = __bfloat16_as_ushort(h);
        *(uint16_t*)(sm8 + 17408 + r * 272 + c * 2) = __bfloat16_as_ushort(l);
    }
    // h, dt, RK4 state in registers (fragment coords)
    float hreg[32], dtr[4];
    #pragma unroll
    for (int mt = 0; mt < 2; ++mt)
        #pragma unroll
        for (int half = 0; half < 2; ++half) {
            int row = wm * 32 + mt * 16 + gid + half * 8;
            dtr[mt * 2 + half] = fmaxf(__ldg(dts + rowbase + row), 0.0f);
            #pragma unroll
            for (int nt = 0; nt < 4; ++nt) {
                float2 hv = __ldg((const float2*)(hidden + (rowbase + row) * 128
                                                  + wn * 32 + nt * 8 + tig * 2));
                hreg[mt * 16 + nt * 4 + half * 2]     = hv.x;
                hreg[mt * 16 + nt * 4 + half * 2 + 1] = hv.y;
            }
        }
    float k1r[32], pr[32];

    int cur = 0;
    issueB(sb + 102400, pB1[0], pB1[1], 256, 256, 0, tid);   // mm1 chunk0 -> buf0

    #pragma unroll 1
    for (int s = 0; s < 4; ++s) {
        // ================= mm1: N=256, K=128 (4 chunks, 1 sync each) =====
        float c1[2][8][4];
        #pragma unroll
        for (int mt = 0; mt < 2; ++mt)
            #pragma unroll
            for (int nt = 0; nt < 8; ++nt)
                #pragma unroll
                for (int e = 0; e < 4; ++e) c1[mt][nt][e] = 0.f;

        #pragma unroll 1
        for (int kc = 0; kc < 4; ++kc) {
            WAIT0;
            __syncthreads();
            if (kc < 3) issueB(sb + 102400 + (cur ^ 1) * 40960, pB1[0], pB1[1], 256, 256, kc + 1, tid);
            else        issueB(sb + 102400 + (cur ^ 1) * 40960, pB2[0], pB2[1], 128, 512, 0, tid);
            uint32_t bb = sb + 102400 + cur * 40960;
            #pragma unroll
            for (int ks = 0; ks < 2; ++ks) {
                int kb = (kc * 32 + ks * 16) * 2;
                uint32_t ah0[4], ah1[4], al0[4], al1[4];
                ldm4(ah0, aaddr(sb,         wm * 32,      kb, 272, lane));
                ldm4(ah1, aaddr(sb,         wm * 32 + 16, kb, 272, lane));
                ldm4(al0, aaddr(sb + 17408, wm * 32,      kb, 272, lane));
                ldm4(al1, aaddr(sb + 17408, wm * 32 + 16, kb, 272, lane));
                #pragma unroll
                for (int np = 0; np < 4; ++np) {
                    uint32_t bh[4], bl[4];
                    ldm4(bh, baddr(bb,         wn * 64 + np * 16, ks * 32, lane));
                    ldm4(bl, baddr(bb + 20480, wn * 64 + np * 16, ks * 32, lane));
                    mmab(c1[0][2 * np], ah0, bh);     mmab(c1[1][2 * np], ah1, bh);
                    mmab(c1[0][2 * np], al0, bh);     mmab(c1[1][2 * np], al1, bh);
                    mmab(c1[0][2 * np], ah0, bl);     mmab(c1[1][2 * np], ah1, bl);
                    mmab(c1[0][2 * np + 1], ah0, bh + 2); mmab(c1[1][2 * np + 1], ah1, bh + 2);
                    mmab(c1[0][2 * np + 1], al0, bh + 2); mmab(c1[1][2 * np + 1], al1, bh + 2);
                    mmab(c1[0][2 * np + 1], ah0, bl + 2); mmab(c1[1][2 * np + 1], ah1, bl + 2);
                }
            }
            cur ^= 1;
        }

        // ================= epilogue1: +b1, LN, GELU(erf) -> A2 ============
        #pragma unroll
        for (int mt = 0; mt < 2; ++mt)
            #pragma unroll
            for (int half = 0; half < 2; ++half) {
                float s1 = 0.f, s2 = 0.f;
                #pragma unroll
                for (int nt = 0; nt < 8; ++nt)
                    #pragma unroll
                    for (int j = 0; j < 2; ++j) {
                        int col = wn * 64 + nt * 8 + tig * 2 + j;
                        float v = c1[mt][nt][half * 2 + j] + b1s[col];
                        c1[mt][nt][half * 2 + j] = v;
                        s1 += v; s2 += v * v;
                    }
                s1 += __shfl_xor_sync(0xffffffffu, s1, 1);
                s1 += __shfl_xor_sync(0xffffffffu, s1, 2);
                s2 += __shfl_xor_sync(0xffffffffu, s2, 1);
                s2 += __shfl_xor_sync(0xffffffffu, s2, 2);
                if (tig == 0) {
                    int row = wm * 32 + mt * 16 + gid + half * 8;
                    stats[row * 8 + wn * 2] = s1;
                    stats[row * 8 + wn * 2 + 1] = s2;
                }
            }
        __syncthreads();
        #pragma unroll
        for (int mt = 0; mt < 2; ++mt)
            #pragma unroll
            for (int half = 0; half < 2; ++half) {
                int row = wm * 32 + mt * 16 + gid + half * 8;
                float t1 = stats[row * 8] + stats[row * 8 + 2] + stats[row * 8 + 4] + stats[row * 8 + 6];
                float t2 = stats[row * 8 + 1] + stats[row * 8 + 3] + stats[row * 8 + 5] + stats[row * 8 + 7];
                float mu = t1 * (1.0f / 256.0f);
                float var = t2 * (1.0f / 256.0f) - mu * mu;
                float rstd = rsqrtf(var + 1e-5f);
                #pragma unroll
                for (int nt = 0; nt < 8; ++nt) {
                    int col0 = wn * 64 + nt * 8 + tig * 2;
                    float v0 = (c1[mt][nt][half * 2] - mu) * rstd * lnws[col0] + lnbs[col0];
                    float v1 = (c1[mt][nt][half * 2 + 1] - mu) * rstd * lnws[col0 + 1] + lnbs[col0 + 1];
                    float g0 = gelu_e(v0), g1 = gelu_e(v1);
                    uint32_t hi, lo; sp2(g0, g1, hi, lo);
                    *(uint32_t*)(sm8 + 34816 + row * 528 + col0 * 2) = hi;
                    *(uint32_t*)(sm8 + 68608 + row * 528 + col0 * 2) = lo;
                }
            }

        // ================= mm2: N=128, K=256 (8 chunks, 1 sync each) =====
        float c2[2][4][4];
        #pragma unroll
        for (int mt = 0; mt < 2; ++mt)
            #pragma unroll
            for (int nt = 0; nt < 4; ++nt)
                #pragma unroll
                for (int e = 0; e < 4; ++e) c2[mt][nt][e] = 0.f;

        #pragma unroll 1
        for (int kc = 0; kc < 8; ++kc) {
            WAIT0;
            __syncthreads();
            if (kc < 7)      issueB(sb + 102400 + (cur ^ 1) * 40960, pB2[0], pB2[1], 128, 512, kc + 1, tid);
            else if (s < 3)  issueB(sb + 102400 + (cur ^ 1) * 40960, pB1[0], pB1[1], 256, 256, 0, tid);
            uint32_t bb = sb + 102400 + cur * 40960;
            #pragma unroll
            for (int ks = 0; ks < 2; ++ks) {
                int kb = (kc * 32 + ks * 16) * 2;
                uint32_t ah0[4], ah1[4], al0[4], al1[4];
                ldm4(ah0, aaddr(sb + 34816, wm * 32,      kb, 528, lane));
                ldm4(ah1, aaddr(sb + 34816, wm * 32 + 16, kb, 528, lane));
                ldm4(al0, aaddr(sb + 68608, wm * 32,      kb, 528, lane));
                ldm4(al1, aaddr(sb + 68608, wm * 32 + 16, kb, 528, lane));
                #pragma unroll
                for (int np = 0; np < 2; ++np) {
                    uint32_t bh[4], bl[4];
                    ldm4(bh, baddr(bb,         wn * 32 + np * 16, ks * 32, lane));
                    ldm4(bl, baddr(bb + 10240, wn * 32 + np * 16, ks * 32, lane));
                    mmab(c2[0][2 * np], ah0, bh);     mmab(c2[1][2 * np], ah1, bh);
                    mmab(c2[0][2 * np], al0, bh);     mmab(c2[1][2 * np], al1, bh);
                    mmab(c2[0][2 * np], ah0, bl);     mmab(c2[1][2 * np], ah1, bl);
                    mmab(c2[0][2 * np + 1], ah0, bh + 2); mmab(c2[1][2 * np + 1], ah1, bh + 2);
                    mmab(c2[0][2 * np + 1], al0, bh + 2); mmab(c2[1][2 * np + 1], al1, bh + 2);
                    mmab(c2[0][2 * np + 1], ah0, bl + 2); mmab(c2[1][2 * np + 1], ah1, bl + 2);
                }
            }
            cur ^= 1;
        }

        // ================= epilogue2: RK4 combine (register state) =========
        #pragma unroll
        for (int mt = 0; mt < 2; ++mt)
            #pragma unroll
            for (int half = 0; half < 2; ++half) {
                int row = wm * 32 + mt * 16 + gid + half * 8;
                float dt = dtr[mt * 2 + half];
                #pragma unroll
                for (int nt = 0; nt < 4; ++nt) {
                    int colb = wn * 32 + nt * 8 + tig * 2;
                    float a0 = 0.f, a1 = 0.f;
                    #pragma unroll
                    for (int jj = 0; jj < 2; ++jj) {
                        int j = mt * 16 + nt * 4 + half * 2 + jj;
                        float kv = c2[mt][nt][half * 2 + jj] + b2s[colb + jj];
                        float h = hreg[j];
                        float arg;
                        if (s == 0) {
                            k1r[j] = kv;
                            arg = h + dt * (kv * (1.0f / 3.0f));
                        } else if (s == 1) {
                            pr[j] = k1r[j] - kv;
                            arg = h + dt * (kv - k1r[j] * (1.0f / 3.0f));
                        } else if (s == 2) {
                            arg = h + dt * (pr[j] + kv);
                            pr[j] = 4.0f * k1r[j] - 3.0f * pr[j] + 3.0f * kv;
                        } else {
                            arg = (dt > 0.0f) ? (h + dt * (pr[j] + kv) * 0.125f) : h;
                        }
                        if (jj) a1 = arg; else a0 = arg;
                    }
                    if (s == 3) {
                        float2 o; o.x = a0; o.y = a1;
                        *(float2*)(evolved + (rowbase + row) * 128 + colb) = o;
                    } else {
                        uint32_t hi, lo; sp2(a0, a1, hi, lo);
                        *(uint32_t*)(sm8 + row * 272 + colb * 2) = hi;
                        *(uint32_t*)(sm8 + 17408 + row * 272 + colb * 2) = lo;
                    }
                }
            }
    }
}

// ---------------- GRU: 64 rows/CTA ----------------
// smem: AH 0(33792) AL 33792 | EV 67584(33792) | B 101376(2x40960)
//       brz 183296(1024) bin 184320(512) bhn 184832(512) mask 185344(256)
#define GRU_SM 185600

// NP = n-tile pairs per warp (2 -> N=128 total, 4 -> N=256 total)
template<int NP>
__device__ __forceinline__ void rungate(
    float (*acc)[4],          // [2*2*NP][4], index mt*(2*NP)+tile
    int kab, const uint8_t* hi, const uint8_t* lo, int nch, int rb,
    const uint8_t* nhi, const uint8_t* nlo, int nNn, int nrb,
    uint32_t sb, uint8_t* sm8, int& cur, int tid, int lane, int wm, int wn)
{
    const int TPW = 2 * NP;
    const int psz = NP * 64 * 80;   // lo-plane offset within buffer
    #pragma unroll
    for (int i = 0; i < 2 * TPW; ++i)
        #pragma unroll
        for (int e = 0; e < 4; ++e) acc[i][e] = 0.f;
    #pragma unroll 1
    for (int kc = 0; kc < nch; ++kc) {
        WAIT0;
        __syncthreads();
        if (kc + 1 < nch) issueB(sb + 101376 + (cur ^ 1) * 40960, hi, lo, NP * 64, rb, kc + 1, tid);
        else if (nhi)     issueB(sb + 101376 + (cur ^ 1) * 40960, nhi, nlo, nNn, nrb, 0, tid);
        uint32_t bb = sb + 101376 + cur * 40960;
        #pragma unroll
        for (int ks = 0; ks < 2; ++ks) {
            int kb = kab + (kc * 32 + ks * 16) * 2;
            uint32_t ah0[4], ah1[4], al0[4], al1[4];
            ldm4(ah0, aaddr(sb,         wm * 32,      kb, 528, lane));
            ldm4(ah1, aaddr(sb,         wm * 32 + 16, kb, 528, lane));
            ldm4(al0, aaddr(sb + 33792, wm * 32,      kb, 528, lane));
            ldm4(al1, aaddr(sb + 33792, wm * 32 + 16, kb, 528, lane));
            #pragma unroll
            for (int np = 0; np < NP; ++np) {
                uint32_t bh[4], bl[4];
                ldm4(bh, baddr(bb,       wn * (NP * 16) + np * 16, ks * 32, lane));
                ldm4(bl, baddr(bb + psz, wn * (NP * 16) + np * 16, ks * 32, lane));
                mmab(acc[0 * TPW + 2 * np], ah0, bh);     mmab(acc[1 * TPW + 2 * np], ah1, bh);
                mmab(acc[0 * TPW + 2 * np], al0, bh);     mmab(acc[1 * TPW + 2 * np], al1, bh);
                mmab(acc[0 * TPW + 2 * np], ah0, bl);     mmab(acc[1 * TPW + 2 * np], ah1, bl);
                mmab(acc[0 * TPW + 2 * np + 1], ah0, bh + 2); mmab(acc[1 * TPW + 2 * np + 1], ah1, bh + 2);
                mmab(acc[0 * TPW + 2 * np + 1], al0, bh + 2); mmab(acc[1 * TPW + 2 * np + 1], al1, bh + 2);
                mmab(acc[0 * TPW + 2 * np + 1], ah0, bl + 2); mmab(acc[1 * TPW + 2 * np + 1], ah1, bl + 2);
            }
        }
        cur ^= 1;
    }
}

__global__ void __launch_bounds__(NT, 1) gru_kernel(
    const float* __restrict__ evolved, const float* __restrict__ obs,
    const int* __restrict__ mask,
    const float* __restrict__ bih, const float* __restrict__ bhh,
    float* __restrict__ updated)
{
    extern __shared__ uint8_t sm8[];
    const uint32_t sb = s2u(sm8);
    float* brz  = (float*)(sm8 + 183296);
    float* bin  = (float*)(sm8 + 184320);
    float* bhn  = (float*)(sm8 + 184832);
    int*   mskS = (int*)(sm8 + 185344);

    const int tid = threadIdx.x, lane = tid & 31, wrp = tid >> 5;
    const int gid = lane >> 2, tig = lane & 3;
    const int wm = wrp >> 2, wn = wrp & 3;
    const size_t rowbase = (size_t)blockIdx.x * 64;

    brz[tid] = bih[tid] + bhh[tid];
    if (tid < 128) { bin[tid] = bih[256 + tid]; bhn[tid] = bhh[256 + tid]; }
    if (tid < 64)  mskS[tid] = __ldg(mask + rowbase + tid);
    for (int idx = tid; idx < 8192; idx += NT) {
        int r = idx >> 7, c = idx & 127;
        float vo = __ldg(obs + (rowbase + r) * 128 + c);
        float ve = __ldg(evolved + (rowbase + r) * 128 + c);
        __nv_bfloat16 oh = __float2bfloat16_rn(vo);
        __nv_bfloat16 ol = __float2bfloat16_rn(vo - __bfloat162float(oh));
        __nv_bfloat16 eh = __float2bfloat16_rn(ve);
        __nv_bfloat16 el = __float2bfloat16_rn(ve - __bfloat162float(eh));
        *(uint16_t*)(sm8 + r * 528 + c * 2) = __bfloat16_as_ushort(oh);
        *(uint16_t*)(sm8 + r * 528 + 256 + c * 2) = __bfloat16_as_ushort(eh);
        *(uint16_t*)(sm8 + 33792 + r * 528 + c * 2) = __bfloat16_as_ushort(ol);
        *(uint16_t*)(sm8 + 33792 + r * 528 + 256 + c * 2) = __bfloat16_as_ushort(el);
        *(float*)(sm8 + 67584 + r * 528 + c * 4) = ve;
    }
    int cur = 0;
    issueB(sb + 101376, pIN[0], pIN[1], 128, 256, 0, tid);

    float aN[8][4], aH[8][4], aRZ[16][4];
    rungate<2>(aN, 0,   pIN[0], pIN[1], 4, 256, pHN[0], pHN[1], 128, 256,
               sb, sm8, cur, tid, lane, wm, wn);
    rungate<2>(aH, 256, pHN[0], pHN[1], 4, 256, pRZ[0], pRZ[1], 256, 512,
               sb, sm8, cur, tid, lane, wm, wn);
    rungate<4>(aRZ, 0,  pRZ[0], pRZ[1], 8, 512, (const uint8_t*)0, (const uint8_t*)0, 0, 0,
               sb, sm8, cur, tid, lane, wm, wn);

    // n = tanh(in + bin + r*(hn + bhn));  r from aRZ tiles 0-3, z from 4-7
    #pragma unroll
    for (int mt = 0; mt < 2; ++mt)
        #pragma unroll
        for (int nt = 0; nt < 4; ++nt)
            #pragma unroll
            for (int e = 0; e < 4; ++e) {
                int col = wn * 32 + nt * 8 + tig * 2 + (e & 1);
                float r = 1.0f / (1.0f + __expf(-(aRZ[mt * 8 + nt][e] + brz[col])));
                aN[mt * 4 + nt][e] = tanhf(aN[mt * 4 + nt][e] + bin[col]
                                           + r * (aH[mt * 4 + nt][e] + bhn[col]));
            }

    #pragma unroll
    for (int mt = 0; mt < 2; ++mt)
        #pragma unroll
        for (int half = 0; half < 2; ++half) {
            int row = wm * 32 + mt * 16 + gid + half * 8;
            int msk = mskS[row];
            #pragma unroll
            for (int nt = 0; nt < 4; ++nt) {
                int colb = wn * 32 + nt * 8 + tig * 2;
                float2 ev = *(const float2*)(sm8 + 67584 + row * 528 + colb * 4);
                float2 o;
                {
                    float z = 1.0f / (1.0f + __expf(-(aRZ[mt * 8 + nt + 4][half * 2] + brz[128 + colb])));
                    float g = (1.0f - z) * aN[mt * 4 + nt][half * 2] + z * ev.x;
                    o.x = (msk > 0) ? g : ev.x;
                }
                {
                    float z = 1.0f / (1.0f + __expf(-(aRZ[mt * 8 + nt + 4][half * 2 + 1] + brz[128 + colb + 1])));
                    float g = (1.0f - z) * aN[mt * 4 + nt][half * 2 + 1] + z * ev.y;
                    o.y = (msk > 0) ? g : ev.y;
                }
                *(float2*)(updated + (rowbase + row) * 128 + colb) = o;
            }
        }
}

// ---------------------------------------------------------------------------
extern "C" void kernel_launch(void* const* d_in, const int* in_sizes, int n_in,
                              void* d_out, int out_size)
{
    const float* hidden = (const float*)d_in[0];
    const float* dts    = (const float*)d_in[1];
    const float* obs    = (const float*)d_in[2];
    const int*   mask   = (const int*)d_in[3];
    const float* w1     = (const float*)d_in[4];
    const float* b1     = (const float*)d_in[5];
    const float* lnw    = (const float*)d_in[6];
    const float* lnb    = (const float*)d_in[7];
    const float* w2     = (const float*)d_in[8];
    const float* b2     = (const float*)d_in[9];
    const float* wih    = (const float*)d_in[10];
    const float* whh    = (const float*)d_in[11];
    const float* bih    = (const float*)d_in[12];
    const float* bhh    = (const float*)d_in[13];

    float* evolved = (float*)d_out;
    float* updated = evolved + (size_t)131072 * 128;

    cudaFuncSetAttribute(evolve_kernel, cudaFuncAttributeMaxDynamicSharedMemorySize, EV_SM);
    cudaFuncSetAttribute(gru_kernel, cudaFuncAttributeMaxDynamicSharedMemorySize, GRU_SM);

    prep_kernel<<<640, 256>>>(w1, w2, wih, whh);
    evolve_kernel<<<2048, NT, EV_SM>>>(hidden, dts, b1, lnw, lnb, b2, evolved);
    gru_kernel<<<2048, NT, GRU_SM>>>(evolved, obs, mask, bih, bhh, updated);
}

// round 14
// speedup vs baseline: 3.1210x; 1.3199x over previous
#include <cuda_runtime.h>
#include <cuda_fp16.h>
#include <math.h>
#include <stdint.h>

#define NT 256

// ---------------- weight images: [n][k] fp16 (hi plane only) ----------------
__device__ __align__(16) uint8_t pB1[65536];    // w1^T  [256][128]
__device__ __align__(16) uint8_t pB2[65536];    // w2^T  [128][256]
__device__ __align__(16) uint8_t pRZ[131072];   // rz interleaved [256][256]
__device__ __align__(16) uint8_t pIN[32768];    // wih_n [128][128]
__device__ __align__(16) uint8_t pHN[32768];    // whh_n [128][128]

__device__ __forceinline__ void wsp(float x, uint8_t* img, uint32_t o) {
    *(uint16_t*)(img + o) = __half_as_ushort(__float2half_rn(x));
}

__global__ void prep_kernel(const float* __restrict__ w1, const float* __restrict__ w2,
                            const float* __restrict__ wih, const float* __restrict__ whh) {
    int i = blockIdx.x * blockDim.x + threadIdx.x;
    if (i < 32768) {
        int n = i >> 7, k = i & 127;
        wsp(w1[k * 256 + n], pB1, (uint32_t)(n * 128 + k) * 2);
    } else if (i < 65536) {
        int t = i - 32768, n = t >> 8, k = t & 255;
        wsp(w2[k * 128 + n], pB2, (uint32_t)(n * 256 + k) * 2);
    } else if (i < 131072) {
        // rz merged, gate-interleaved: image row n -> h=(n>>6)*32+(n&31), gate=(n>>5)&1
        int t = i - 65536, n = t >> 8, k = t & 255;
        int h = (n >> 6) * 32 + (n & 31);
        int g = (n >> 5) & 1;
        int src = g * 128 + h;
        float v = (k < 128) ? wih[src * 128 + k] : whh[src * 128 + (k - 128)];
        wsp(v, pRZ, (uint32_t)(n * 256 + k) * 2);
    } else if (i < 147456) {
        int t = i - 131072, n = t >> 7, k = t & 127;
        wsp(wih[(256 + n) * 128 + k], pIN, (uint32_t)(n * 128 + k) * 2);
    } else if (i < 163840) {
        int t = i - 147456, n = t >> 7, k = t & 127;
        wsp(whh[(256 + n) * 128 + k], pHN, (uint32_t)(n * 128 + k) * 2);
    }
}

// ---------------- helpers ----------------
__device__ __forceinline__ uint32_t s2u(const void* p) {
    uint32_t a;
    asm("{.reg .u64 t; cvta.to.shared.u64 t,%1; cvt.u32.u64 %0,t;}" : "=r"(a) : "l"(p));
    return a;
}
__device__ __forceinline__ void cpa(uint32_t d, const void* s) {
    asm volatile("cp.async.cg.shared.global [%0],[%1],16;" :: "r"(d), "l"(s) : "memory");
}
#define CPC()  asm volatile("cp.async.commit_group;" ::: "memory")
#define WAIT0 asm volatile("cp.async.wait_group 0;" ::: "memory")

__device__ __forceinline__ void mmab(float c[4], const uint32_t a[4], const uint32_t b[2]) {
    asm volatile("mma.sync.aligned.m16n8k16.row.col.f32.f16.f16.f32 "
        "{%0,%1,%2,%3},{%4,%5,%6,%7},{%8,%9},{%0,%1,%2,%3};"
        : "+f"(c[0]), "+f"(c[1]), "+f"(c[2]), "+f"(c[3])
        : "r"(a[0]), "r"(a[1]), "r"(a[2]), "r"(a[3]), "r"(b[0]), "r"(b[1]));
}
__device__ __forceinline__ void ldm4(uint32_t f[4], uint32_t addr) {
    asm volatile("ldmatrix.sync.aligned.m8n8.x4.shared.b16 {%0,%1,%2,%3},[%4];"
        : "=r"(f[0]), "=r"(f[1]), "=r"(f[2]), "=r"(f[3]) : "r"(addr));
}
__device__ __forceinline__ uint32_t aaddr(uint32_t plane, int rowTile, int kb,
                                          int stride, int lane) {
    int r = rowTile + (lane & 7) + (lane & 8);
    int ko = kb + ((lane & 16) ? 16 : 0);
    return plane + (uint32_t)(r * stride + ko);
}
__device__ __forceinline__ uint32_t baddr(uint32_t plane, int n0, int kbyte, int lane) {
    int n = n0 + (lane & 7) + ((lane & 16) ? 8 : 0);
    int ko = kbyte + ((lane & 8) ? 16 : 0);
    return plane + (uint32_t)(n * 80 + ko);
}
// fp16 hi/lo split of a float pair -> packed h2 regs
__device__ __forceinline__ void sp2(float v0, float v1, uint32_t& hi, uint32_t& lo) {
    __half h0 = __float2half_rn(v0), h1 = __float2half_rn(v1);
    __half l0 = __float2half_rn(v0 - __half2float(h0));
    __half l1 = __float2half_rn(v1 - __half2float(h1));
    hi = (uint32_t)__half_as_ushort(h0) | ((uint32_t)__half_as_ushort(h1) << 16);
    lo = (uint32_t)__half_as_ushort(l0) | ((uint32_t)__half_as_ushort(l1) << 16);
}
// stream a [Nn][32k] fp16 chunk into smem (row stride 80B, bank-conflict-free)
__device__ __forceinline__ void issueB(uint32_t dst, const uint8_t* img,
                                       int Nn, int rowbytes, int kc, int tid) {
    const int tot = Nn * 4;
    for (int f = tid; f < tot; f += NT) {
        int r = f >> 2, q = f & 3;
        cpa(dst + (uint32_t)(r * 80 + q * 16),
            img + (size_t)r * rowbytes + kc * 64 + q * 16);
    }
    CPC();
}
__device__ __forceinline__ float gelu_e(float v) {
    return 0.5f * v * (1.0f + erff(v * 0.70710678f));
}

// ---------------- evolve: RK4(3/8), 64 rows/CTA ----------------
// smem: AH 0(17408) AL 17408 | A2H 34816(33792) A2L 68608 | B 102400(2x20480)
//       stats 143360(2048) b1 145408(1024) lnw 146432 lnb 147456 b2 148480(512)
#define EV_SM 148992
__global__ void __launch_bounds__(NT, 1) evolve_kernel(
    const float* __restrict__ hidden, const float* __restrict__ dts,
    const float* __restrict__ b1, const float* __restrict__ lnw,
    const float* __restrict__ lnb, const float* __restrict__ b2,
    float* __restrict__ evolved)
{
    extern __shared__ uint8_t sm8[];
    const uint32_t sb = s2u(sm8);
    float* stats = (float*)(sm8 + 143360);
    float* b1s   = (float*)(sm8 + 145408);
    float* lnws  = (float*)(sm8 + 146432);
    float* lnbs  = (float*)(sm8 + 147456);
    float* b2s   = (float*)(sm8 + 148480);

    const int tid = threadIdx.x, lane = tid & 31, wrp = tid >> 5;
    const int gid = lane >> 2, tig = lane & 3;
    const int wm = wrp >> 2, wn = wrp & 3;
    const size_t rowbase = (size_t)blockIdx.x * 64;

    b1s[tid] = b1[tid]; lnws[tid] = lnw[tid]; lnbs[tid] = lnb[tid];
    if (tid < 128) b2s[tid] = b2[tid];
    // A0 = split(h)  (fp16 hi/lo planes)
    for (int idx = tid; idx < 8192; idx += NT) {
        int r = idx >> 7, c = idx & 127;
        float v = __ldg(hidden + (rowbase + r) * 128 + c);
        __half h = __float2half_rn(v);
        __half l = __float2half_rn(v - __half2float(h));
        *(uint16_t*)(sm8 + r * 272 + c * 2) = __half_as_ushort(h);
        *(uint16_t*)(sm8 + 17408 + r * 272 + c * 2) = __half_as_ushort(l);
    }
    // h, dt, RK4 state in registers (fragment coords)
    float hreg[32], dtr[4];
    #pragma unroll
    for (int mt = 0; mt < 2; ++mt)
        #pragma unroll
        for (int half = 0; half < 2; ++half) {
            int row = wm * 32 + mt * 16 + gid + half * 8;
            dtr[mt * 2 + half] = fmaxf(__ldg(dts + rowbase + row), 0.0f);
            #pragma unroll
            for (int nt = 0; nt < 4; ++nt) {
                float2 hv = __ldg((const float2*)(hidden + (rowbase + row) * 128
                                                  + wn * 32 + nt * 8 + tig * 2));
                hreg[mt * 16 + nt * 4 + half * 2]     = hv.x;
                hreg[mt * 16 + nt * 4 + half * 2 + 1] = hv.y;
            }
        }
    float k1r[32], pr[32];

    int cur = 0;
    issueB(sb + 102400, pB1, 256, 256, 0, tid);   // mm1 chunk0 -> buf0

    #pragma unroll 1
    for (int s = 0; s < 4; ++s) {
        // ================= mm1: N=256, K=128 (4 chunks, 1 sync each) =====
        float c1[2][8][4];
        #pragma unroll
        for (int mt = 0; mt < 2; ++mt)
            #pragma unroll
            for (int nt = 0; nt < 8; ++nt)
                #pragma unroll
                for (int e = 0; e < 4; ++e) c1[mt][nt][e] = 0.f;

        #pragma unroll 1
        for (int kc = 0; kc < 4; ++kc) {
            WAIT0;
            __syncthreads();
            if (kc < 3) issueB(sb + 102400 + (cur ^ 1) * 20480, pB1, 256, 256, kc + 1, tid);
            else        issueB(sb + 102400 + (cur ^ 1) * 20480, pB2, 128, 512, 0, tid);
            uint32_t bb = sb + 102400 + cur * 20480;
            #pragma unroll
            for (int ks = 0; ks < 2; ++ks) {
                int kb = (kc * 32 + ks * 16) * 2;
                uint32_t ah0[4], ah1[4], al0[4], al1[4];
                ldm4(ah0, aaddr(sb,         wm * 32,      kb, 272, lane));
                ldm4(ah1, aaddr(sb,         wm * 32 + 16, kb, 272, lane));
                ldm4(al0, aaddr(sb + 17408, wm * 32,      kb, 272, lane));
                ldm4(al1, aaddr(sb + 17408, wm * 32 + 16, kb, 272, lane));
                #pragma unroll
                for (int np = 0; np < 4; ++np) {
                    uint32_t bh[4];
                    ldm4(bh, baddr(bb, wn * 64 + np * 16, ks * 32, lane));
                    mmab(c1[0][2 * np], ah0, bh);     mmab(c1[1][2 * np], ah1, bh);
                    mmab(c1[0][2 * np], al0, bh);     mmab(c1[1][2 * np], al1, bh);
                    mmab(c1[0][2 * np + 1], ah0, bh + 2); mmab(c1[1][2 * np + 1], ah1, bh + 2);
                    mmab(c1[0][2 * np + 1], al0, bh + 2); mmab(c1[1][2 * np + 1], al1, bh + 2);
                }
            }
            cur ^= 1;
        }

        // ================= epilogue1: +b1, LN, GELU(erf) -> A2 ============
        #pragma unroll
        for (int mt = 0; mt < 2; ++mt)
            #pragma unroll
            for (int half = 0; half < 2; ++half) {
                float s1 = 0.f, s2 = 0.f;
                #pragma unroll
                for (int nt = 0; nt < 8; ++nt)
                    #pragma unroll
                    for (int j = 0; j < 2; ++j) {
                        int col = wn * 64 + nt * 8 + tig * 2 + j;
                        float v = c1[mt][nt][half * 2 + j] + b1s[col];
                        c1[mt][nt][half * 2 + j] = v;
                        s1 += v; s2 += v * v;
                    }
                s1 += __shfl_xor_sync(0xffffffffu, s1, 1);
                s1 += __shfl_xor_sync(0xffffffffu, s1, 2);
                s2 += __shfl_xor_sync(0xffffffffu, s2, 1);
                s2 += __shfl_xor_sync(0xffffffffu, s2, 2);
                if (tig == 0) {
                    int row = wm * 32 + mt * 16 + gid + half * 8;
                    stats[row * 8 + wn * 2] = s1;
                    stats[row * 8 + wn * 2 + 1] = s2;
                }
            }
        __syncthreads();
        #pragma unroll
        for (int mt = 0; mt < 2; ++mt)
            #pragma unroll
            for (int half = 0; half < 2; ++half) {
                int row = wm * 32 + mt * 16 + gid + half * 8;
                float t1 = stats[row * 8] + stats[row * 8 + 2] + stats[row * 8 + 4] + stats[row * 8 + 6];
                float t2 = stats[row * 8 + 1] + stats[row * 8 + 3] + stats[row * 8 + 5] + stats[row * 8 + 7];
                float mu = t1 * (1.0f / 256.0f);
                float var = t2 * (1.0f / 256.0f) - mu * mu;
                float rstd = rsqrtf(var + 1e-5f);
                #pragma unroll
                for (int nt = 0; nt < 8; ++nt) {
                    int col0 = wn * 64 + nt * 8 + tig * 2;
                    float v0 = (c1[mt][nt][half * 2] - mu) * rstd * lnws[col0] + lnbs[col0];
                    float v1 = (c1[mt][nt][half * 2 + 1] - mu) * rstd * lnws[col0 + 1] + lnbs[col0 + 1];
                    float g0 = gelu_e(v0), g1 = gelu_e(v1);
                    uint32_t hi, lo; sp2(g0, g1, hi, lo);
                    *(uint32_t*)(sm8 + 34816 + row * 528 + col0 * 2) = hi;
                    *(uint32_t*)(sm8 + 68608 + row * 528 + col0 * 2) = lo;
                }
            }

        // ================= mm2: N=128, K=256 (8 chunks, 1 sync each) =====
        float c2[2][4][4];
        #pragma unroll
        for (int mt = 0; mt < 2; ++mt)
            #pragma unroll
            for (int nt = 0; nt < 4; ++nt)
                #pragma unroll
                for (int e = 0; e < 4; ++e) c2[mt][nt][e] = 0.f;

        #pragma unroll 1
        for (int kc = 0; kc < 8; ++kc) {
            WAIT0;
            __syncthreads();
            if (kc < 7)      issueB(sb + 102400 + (cur ^ 1) * 20480, pB2, 128, 512, kc + 1, tid);
            else if (s < 3)  issueB(sb + 102400 + (cur ^ 1) * 20480, pB1, 256, 256, 0, tid);
            uint32_t bb = sb + 102400 + cur * 20480;
            #pragma unroll
            for (int ks = 0; ks < 2; ++ks) {
                int kb = (kc * 32 + ks * 16) * 2;
                uint32_t ah0[4], ah1[4], al0[4], al1[4];
                ldm4(ah0, aaddr(sb + 34816, wm * 32,      kb, 528, lane));
                ldm4(ah1, aaddr(sb + 34816, wm * 32 + 16, kb, 528, lane));
                ldm4(al0, aaddr(sb + 68608, wm * 32,      kb, 528, lane));
                ldm4(al1, aaddr(sb + 68608, wm * 32 + 16, kb, 528, lane));
                #pragma unroll
                for (int np = 0; np < 2; ++np) {
                    uint32_t bh[4];
                    ldm4(bh, baddr(bb, wn * 32 + np * 16, ks * 32, lane));
                    mmab(c2[0][2 * np], ah0, bh);     mmab(c2[1][2 * np], ah1, bh);
                    mmab(c2[0][2 * np], al0, bh);     mmab(c2[1][2 * np], al1, bh);
                    mmab(c2[0][2 * np + 1], ah0, bh + 2); mmab(c2[1][2 * np + 1], ah1, bh + 2);
                    mmab(c2[0][2 * np + 1], al0, bh + 2); mmab(c2[1][2 * np + 1], al1, bh + 2);
                }
            }
            cur ^= 1;
        }

        // ================= epilogue2: RK4 combine (register state) =========
        #pragma unroll
        for (int mt = 0; mt < 2; ++mt)
            #pragma unroll
            for (int half = 0; half < 2; ++half) {
                int row = wm * 32 + mt * 16 + gid + half * 8;
                float dt = dtr[mt * 2 + half];
                #pragma unroll
                for (int nt = 0; nt < 4; ++nt) {
                    int colb = wn * 32 + nt * 8 + tig * 2;
                    float a0 = 0.f, a1 = 0.f;
                    #pragma unroll
                    for (int jj = 0; jj < 2; ++jj) {
                        int j = mt * 16 + nt * 4 + half * 2 + jj;
                        float kv = c2[mt][nt][half * 2 + jj] + b2s[colb + jj];
                        float h = hreg[j];
                        float arg;
                        if (s == 0) {
                            k1r[j] = kv;
                            arg = h + dt * (kv * (1.0f / 3.0f));
                        } else if (s == 1) {
                            pr[j] = k1r[j] - kv;
                            arg = h + dt * (kv - k1r[j] * (1.0f / 3.0f));
                        } else if (s == 2) {
                            arg = h + dt * (pr[j] + kv);
                            pr[j] = 4.0f * k1r[j] - 3.0f * pr[j] + 3.0f * kv;
                        } else {
                            arg = (dt > 0.0f) ? (h + dt * (pr[j] + kv) * 0.125f) : h;
                        }
                        if (jj) a1 = arg; else a0 = arg;
                    }
                    if (s == 3) {
                        float2 o; o.x = a0; o.y = a1;
                        *(float2*)(evolved + (rowbase + row) * 128 + colb) = o;
                    } else {
                        uint32_t hi, lo; sp2(a0, a1, hi, lo);
                        *(uint32_t*)(sm8 + row * 272 + colb * 2) = hi;
                        *(uint32_t*)(sm8 + 17408 + row * 272 + colb * 2) = lo;
                    }
                }
            }
    }
}

// ---------------- GRU: 64 rows/CTA ----------------
// smem: AH 0(33792) AL 33792 | EV 67584(33792) | B 101376(2x20480)
//       brz 142336(1024) bin 143360(512) bhn 143872(512) mask 144384(256)
#define GRU_SM 144640

// NP = n-tile pairs per warp (2 -> N=128 total, 4 -> N=256 total)
template<int NP>
__device__ __forceinline__ void rungate(
    float (*acc)[4],          // [2*2*NP][4], index mt*(2*NP)+tile
    int kab, const uint8_t* img, int nch, int rb,
    const uint8_t* nimg, int nNn, int nrb,
    uint32_t sb, uint8_t* sm8, int& cur, int tid, int lane, int wm, int wn)
{
    const int TPW = 2 * NP;
    #pragma unroll
    for (int i = 0; i < 2 * TPW; ++i)
        #pragma unroll
        for (int e = 0; e < 4; ++e) acc[i][e] = 0.f;
    #pragma unroll 1
    for (int kc = 0; kc < nch; ++kc) {
        WAIT0;
        __syncthreads();
        if (kc + 1 < nch) issueB(sb + 101376 + (cur ^ 1) * 20480, img, NP * 64, rb, kc + 1, tid);
        else if (nimg)    issueB(sb + 101376 + (cur ^ 1) * 20480, nimg, nNn, nrb, 0, tid);
        uint32_t bb = sb + 101376 + cur * 20480;
        #pragma unroll
        for (int ks = 0; ks < 2; ++ks) {
            int kb = kab + (kc * 32 + ks * 16) * 2;
            uint32_t ah0[4], ah1[4], al0[4], al1[4];
            ldm4(ah0, aaddr(sb,         wm * 32,      kb, 528, lane));
            ldm4(ah1, aaddr(sb,         wm * 32 + 16, kb, 528, lane));
            ldm4(al0, aaddr(sb + 33792, wm * 32,      kb, 528, lane));
            ldm4(al1, aaddr(sb + 33792, wm * 32 + 16, kb, 528, lane));
            #pragma unroll
            for (int np = 0; np < NP; ++np) {
                uint32_t bh[4];
                ldm4(bh, baddr(bb, wn * (NP * 16) + np * 16, ks * 32, lane));
                mmab(acc[0 * TPW + 2 * np], ah0, bh);     mmab(acc[1 * TPW + 2 * np], ah1, bh);
                mmab(acc[0 * TPW + 2 * np], al0, bh);     mmab(acc[1 * TPW + 2 * np], al1, bh);
                mmab(acc[0 * TPW + 2 * np + 1], ah0, bh + 2); mmab(acc[1 * TPW + 2 * np + 1], ah1, bh + 2);
                mmab(acc[0 * TPW + 2 * np + 1], al0, bh + 2); mmab(acc[1 * TPW + 2 * np + 1], al1, bh + 2);
            }
        }
        cur ^= 1;
    }
}

__global__ void __launch_bounds__(NT, 1) gru_kernel(
    const float* __restrict__ evolved, const float* __restrict__ obs,
    const int* __restrict__ mask,
    const float* __restrict__ bih, const float* __restrict__ bhh,
    float* __restrict__ updated)
{
    extern __shared__ uint8_t sm8[];
    const uint32_t sb = s2u(sm8);
    float* brz  = (float*)(sm8 + 142336);
    float* bin  = (float*)(sm8 + 143360);
    float* bhn  = (float*)(sm8 + 143872);
    int*   mskS = (int*)(sm8 + 144384);

    const int tid = threadIdx.x, lane = tid & 31, wrp = tid >> 5;
    const int gid = lane >> 2, tig = lane & 3;
    const int wm = wrp >> 2, wn = wrp & 3;
    const size_t rowbase = (size_t)blockIdx.x * 64;

    brz[tid] = bih[tid] + bhh[tid];
    if (tid < 128) { bin[tid] = bih[256 + tid]; bhn[tid] = bhh[256 + tid]; }
    if (tid < 64)  mskS[tid] = __ldg(mask + rowbase + tid);
    for (int idx = tid; idx < 8192; idx += NT) {
        int r = idx >> 7, c = idx & 127;
        float vo = __ldg(obs + (rowbase + r) * 128 + c);
        float ve = __ldg(evolved + (rowbase + r) * 128 + c);
        __half oh = __float2half_rn(vo);
        __half ol = __float2half_rn(vo - __half2float(oh));
        __half eh = __float2half_rn(ve);
        __half el = __float2half_rn(ve - __half2float(eh));
        *(uint16_t*)(sm8 + r * 528 + c * 2) = __half_as_ushort(oh);
        *(uint16_t*)(sm8 + r * 528 + 256 + c * 2) = __half_as_ushort(eh);
        *(uint16_t*)(sm8 + 33792 + r * 528 + c * 2) = __half_as_ushort(ol);
        *(uint16_t*)(sm8 + 33792 + r * 528 + 256 + c * 2) = __half_as_ushort(el);
        *(float*)(sm8 + 67584 + r * 528 + c * 4) = ve;
    }
    int cur = 0;
    issueB(sb + 101376, pIN, 128, 256, 0, tid);

    float aN[8][4], aH[8][4], aRZ[16][4];
    rungate<2>(aN, 0,   pIN, 4, 256, pHN, 128, 256, sb, sm8, cur, tid, lane, wm, wn);
    rungate<2>(aH, 256, pHN, 4, 256, pRZ, 256, 512, sb, sm8, cur, tid, lane, wm, wn);
    rungate<4>(aRZ, 0,  pRZ, 8, 512, (const uint8_t*)0, 0, 0, sb, sm8, cur, tid, lane, wm, wn);

    // n = tanh(in + bin + r*(hn + bhn));  r from aRZ tiles 0-3, z from 4-7
    #pragma unroll
    for (int mt = 0; mt < 2; ++mt)
        #pragma unroll
        for (int nt = 0; nt < 4; ++nt)
            #pragma unroll
            for (int e = 0; e < 4; ++e) {
                int col = wn * 32 + nt * 8 + tig * 2 + (e & 1);
                float r = 1.0f / (1.0f + __expf(-(aRZ[mt * 8 + nt][e] + brz[col])));
                aN[mt * 4 + nt][e] = tanhf(aN[mt * 4 + nt][e] + bin[col]
                                           + r * (aH[mt * 4 + nt][e] + bhn[col]));
            }

    #pragma unroll
    for (int mt = 0; mt < 2; ++mt)
        #pragma unroll
        for (int half = 0; half < 2; ++half) {
            int row = wm * 32 + mt * 16 + gid + half * 8;
            int msk = mskS[row];
            #pragma unroll
            for (int nt = 0; nt < 4; ++nt) {
                int colb = wn * 32 + nt * 8 + tig * 2;
                float2 ev = *(const float2*)(sm8 + 67584 + row * 528 + colb * 4);
                float2 o;
                {
                    float z = 1.0f / (1.0f + __expf(-(aRZ[mt * 8 + nt + 4][half * 2] + brz[128 + colb])));
                    float g = (1.0f - z) * aN[mt * 4 + nt][half * 2] + z * ev.x;
                    o.x = (msk > 0) ? g : ev.x;
                }
                {
                    float z = 1.0f / (1.0f + __expf(-(aRZ[mt * 8 + nt + 4][half * 2 + 1] + brz[128 + colb + 1])));
                    float g = (1.0f - z) * aN[mt * 4 + nt][half * 2 + 1] + z * ev.y;
                    o.y = (msk > 0) ? g : ev.y;
                }
                *(float2*)(updated + (rowbase + row) * 128 + colb) = o;
            }
        }
}

// ---------------------------------------------------------------------------
extern "C" void kernel_launch(void* const* d_in, const int* in_sizes, int n_in,
                              void* d_out, int out_size)
{
    const float* hidden = (const float*)d_in[0];
    const float* dts    = (const float*)d_in[1];
    const float* obs    = (const float*)d_in[2];
    const int*   mask   = (const int*)d_in[3];
    const float* w1     = (const float*)d_in[4];
    const float* b1     = (const float*)d_in[5];
    const float* lnw    = (const float*)d_in[6];
    const float* lnb    = (const float*)d_in[7];
    const float* w2     = (const float*)d_in[8];
    const float* b2     = (const float*)d_in[9];
    const float* wih    = (const float*)d_in[10];
    const float* whh    = (const float*)d_in[11];
    const float* bih    = (const float*)d_in[12];
    const float* bhh    = (const float*)d_in[13];

    float* evolved = (float*)d_out;
    float* updated = evolved + (size_t)131072 * 128;

    cudaFuncSetAttribute(evolve_kernel, cudaFuncAttributeMaxDynamicSharedMemorySize, EV_SM);
    cudaFuncSetAttribute(gru_kernel, cudaFuncAttributeMaxDynamicSharedMemorySize, GRU_SM);

    prep_kernel<<<640, 256>>>(w1, w2, wih, whh);
    evolve_kernel<<<2048, NT, EV_SM>>>(hidden, dts, b1, lnw, lnb, b2, evolved);
    gru_kernel<<<2048, NT, GRU_SM>>>(evolved, obs, mask, bih, bhh, updated);
}

// round 15
// speedup vs baseline: 3.6534x; 1.1706x over previous
#include <cuda_runtime.h>
#include <cuda_fp16.h>
#include <math.h>
#include <stdint.h>

#define NT 256

// ---------------- weight images: [n][k] fp16 (hi plane only) ----------------
__device__ __align__(16) uint8_t pB1[65536];    // w1^T  [256][128]
__device__ __align__(16) uint8_t pB2[65536];    // w2^T  [128][256]
__device__ __align__(16) uint8_t pRZ[131072];   // rz interleaved [256][256]
__device__ __align__(16) uint8_t pIN[32768];    // wih_n [128][128]
__device__ __align__(16) uint8_t pHN[32768];    // whh_n [128][128]

__device__ __forceinline__ void wsp(float x, uint8_t* img, uint32_t o) {
    *(uint16_t*)(img + o) = __half_as_ushort(__float2half_rn(x));
}

__global__ void prep_kernel(const float* __restrict__ w1, const float* __restrict__ w2,
                            const float* __restrict__ wih, const float* __restrict__ whh) {
    int i = blockIdx.x * blockDim.x + threadIdx.x;
    if (i < 32768) {
        int n = i >> 7, k = i & 127;
        wsp(w1[k * 256 + n], pB1, (uint32_t)(n * 128 + k) * 2);
    } else if (i < 65536) {
        int t = i - 32768, n = t >> 8, k = t & 255;
        wsp(w2[k * 128 + n], pB2, (uint32_t)(n * 256 + k) * 2);
    } else if (i < 131072) {
        // rz merged, gate-interleaved: image row n -> h=(n>>6)*32+(n&31), gate=(n>>5)&1
        int t = i - 65536, n = t >> 8, k = t & 255;
        int h = (n >> 6) * 32 + (n & 31);
        int g = (n >> 5) & 1;
        int src = g * 128 + h;
        float v = (k < 128) ? wih[src * 128 + k] : whh[src * 128 + (k - 128)];
        wsp(v, pRZ, (uint32_t)(n * 256 + k) * 2);
    } else if (i < 147456) {
        int t = i - 131072, n = t >> 7, k = t & 127;
        wsp(wih[(256 + n) * 128 + k], pIN, (uint32_t)(n * 128 + k) * 2);
    } else if (i < 163840) {
        int t = i - 147456, n = t >> 7, k = t & 127;
        wsp(whh[(256 + n) * 128 + k], pHN, (uint32_t)(n * 128 + k) * 2);
    }
}

// ---------------- helpers ----------------
__device__ __forceinline__ uint32_t s2u(const void* p) {
    uint32_t a;
    asm("{.reg .u64 t; cvta.to.shared.u64 t,%1; cvt.u32.u64 %0,t;}" : "=r"(a) : "l"(p));
    return a;
}
__device__ __forceinline__ void cpa(uint32_t d, const void* s) {
    asm volatile("cp.async.cg.shared.global [%0],[%1],16;" :: "r"(d), "l"(s) : "memory");
}
#define CPC()  asm volatile("cp.async.commit_group;" ::: "memory")
#define WAIT0 asm volatile("cp.async.wait_group 0;" ::: "memory")

__device__ __forceinline__ void mmab(float c[4], const uint32_t a[4], const uint32_t b[2]) {
    asm volatile("mma.sync.aligned.m16n8k16.row.col.f32.f16.f16.f32 "
        "{%0,%1,%2,%3},{%4,%5,%6,%7},{%8,%9},{%0,%1,%2,%3};"
        : "+f"(c[0]), "+f"(c[1]), "+f"(c[2]), "+f"(c[3])
        : "r"(a[0]), "r"(a[1]), "r"(a[2]), "r"(a[3]), "r"(b[0]), "r"(b[1]));
}
__device__ __forceinline__ void ldm4(uint32_t f[4], uint32_t addr) {
    asm volatile("ldmatrix.sync.aligned.m8n8.x4.shared.b16 {%0,%1,%2,%3},[%4];"
        : "=r"(f[0]), "=r"(f[1]), "=r"(f[2]), "=r"(f[3]) : "r"(addr));
}
__device__ __forceinline__ uint32_t aaddr(uint32_t plane, int rowTile, int kb,
                                          int stride, int lane) {
    int r = rowTile + (lane & 7) + (lane & 8);
    int ko = kb + ((lane & 16) ? 16 : 0);
    return plane + (uint32_t)(r * stride + ko);
}
__device__ __forceinline__ uint32_t baddr(uint32_t plane, int n0, int kbyte, int lane) {
    int n = n0 + (lane & 7) + ((lane & 16) ? 8 : 0);
    int ko = kbyte + ((lane & 8) ? 16 : 0);
    return plane + (uint32_t)(n * 80 + ko);
}
// fp16 hi/lo split of a float pair -> packed h2 regs
__device__ __forceinline__ void sp2(float v0, float v1, uint32_t& hi, uint32_t& lo) {
    __half h0 = __float2half_rn(v0), h1 = __float2half_rn(v1);
    __half l0 = __float2half_rn(v0 - __half2float(h0));
    __half l1 = __float2half_rn(v1 - __half2float(h1));
    hi = (uint32_t)__half_as_ushort(h0) | ((uint32_t)__half_as_ushort(h1) << 16);
    lo = (uint32_t)__half_as_ushort(l0) | ((uint32_t)__half_as_ushort(l1) << 16);
}
__device__ __forceinline__ uint32_t pk2(float v0, float v1) {
    __half h0 = __float2half_rn(v0), h1 = __float2half_rn(v1);
    return (uint32_t)__half_as_ushort(h0) | ((uint32_t)__half_as_ushort(h1) << 16);
}
// stream a [Nn][32k] fp16 chunk into smem (row stride 80B, bank-conflict-free)
__device__ __forceinline__ void issueB(uint32_t dst, const uint8_t* img,
                                       int Nn, int rowbytes, int kc, int tid) {
    const int tot = Nn * 4;
    for (int f = tid; f < tot; f += NT) {
        int r = f >> 2, q = f & 3;
        cpa(dst + (uint32_t)(r * 80 + q * 16),
            img + (size_t)r * rowbytes + kc * 64 + q * 16);
    }
    CPC();
}
__device__ __forceinline__ float gelu_e(float v) {
    return 0.5f * v * (1.0f + erff(v * 0.70710678f));
}

// ---------------- evolve: RK4(3/8), 64 rows/CTA ----------------
// smem: AH 0(17408) AL 17408 | A2H 34816(33792) |
//       B1 resident 68608(4x20480=81920) | B2 150528(2x20480=40960)
//       stats 191488(2048) b1 193536(1024) lnw 194560 lnb 195584 b2 196608(512)
#define EV_SM 197120
__global__ void __launch_bounds__(NT, 1) evolve_kernel(
    const float* __restrict__ hidden, const float* __restrict__ dts,
    const float* __restrict__ b1, const float* __restrict__ lnw,
    const float* __restrict__ lnb, const float* __restrict__ b2,
    float* __restrict__ evolved)
{
    extern __shared__ uint8_t sm8[];
    const uint32_t sb = s2u(sm8);
    const uint32_t b1res = sb + 68608;
    const uint32_t b2buf = sb + 150528;
    float* stats = (float*)(sm8 + 191488);
    float* b1s   = (float*)(sm8 + 193536);
    float* lnws  = (float*)(sm8 + 194560);
    float* lnbs  = (float*)(sm8 + 195584);
    float* b2s   = (float*)(sm8 + 196608);

    const int tid = threadIdx.x, lane = tid & 31, wrp = tid >> 5;
    const int gid = lane >> 2, tig = lane & 3;
    const int wm = wrp >> 2, wn = wrp & 3;
    const size_t rowbase = (size_t)blockIdx.x * 64;

    // load resident B1 (all 4 k-chunks) once
    #pragma unroll
    for (int kc = 0; kc < 4; ++kc)
        issueB(b1res + kc * 20480, pB1, 256, 256, kc, tid);

    b1s[tid] = b1[tid]; lnws[tid] = lnw[tid]; lnbs[tid] = lnb[tid];
    if (tid < 128) b2s[tid] = b2[tid];
    // A0 = split(h)  (fp16 hi/lo planes)
    for (int idx = tid; idx < 8192; idx += NT) {
        int r = idx >> 7, c = idx & 127;
        float v = __ldg(hidden + (rowbase + r) * 128 + c);
        __half h = __float2half_rn(v);
        __half l = __float2half_rn(v - __half2float(h));
        *(uint16_t*)(sm8 + r * 272 + c * 2) = __half_as_ushort(h);
        *(uint16_t*)(sm8 + 17408 + r * 272 + c * 2) = __half_as_ushort(l);
    }
    // h, dt, RK4 state in registers (fragment coords)
    float hreg[32], dtr[4];
    #pragma unroll
    for (int mt = 0; mt < 2; ++mt)
        #pragma unroll
        for (int half = 0; half < 2; ++half) {
            int row = wm * 32 + mt * 16 + gid + half * 8;
            dtr[mt * 2 + half] = fmaxf(__ldg(dts + rowbase + row), 0.0f);
            #pragma unroll
            for (int nt = 0; nt < 4; ++nt) {
                float2 hv = __ldg((const float2*)(hidden + (rowbase + row) * 128
                                                  + wn * 32 + nt * 8 + tig * 2));
                hreg[mt * 16 + nt * 4 + half * 2]     = hv.x;
                hreg[mt * 16 + nt * 4 + half * 2 + 1] = hv.y;
            }
        }
    float k1r[32], pr[32];

    WAIT0;   // resident B1 fully arrived (per-thread); stage-top sync publishes

    #pragma unroll 1
    for (int s = 0; s < 4; ++s) {
        __syncthreads();                 // publish A args (+B1 on s=0)
        issueB(b2buf, pB2, 128, 512, 0, tid);   // prefetch mm2 chunk0 -> buf0

        // ================= mm1: N=256, K=128 (resident B1, no syncs) ======
        float c1[2][8][4];
        #pragma unroll
        for (int mt = 0; mt < 2; ++mt)
            #pragma unroll
            for (int nt = 0; nt < 8; ++nt)
                #pragma unroll
                for (int e = 0; e < 4; ++e) c1[mt][nt][e] = 0.f;

        #pragma unroll 1
        for (int kc = 0; kc < 4; ++kc) {
            uint32_t bb = b1res + kc * 20480;
            #pragma unroll
            for (int ks = 0; ks < 2; ++ks) {
                int kb = (kc * 32 + ks * 16) * 2;
                uint32_t ah0[4], ah1[4], al0[4], al1[4];
                ldm4(ah0, aaddr(sb,         wm * 32,      kb, 272, lane));
                ldm4(ah1, aaddr(sb,         wm * 32 + 16, kb, 272, lane));
                ldm4(al0, aaddr(sb + 17408, wm * 32,      kb, 272, lane));
                ldm4(al1, aaddr(sb + 17408, wm * 32 + 16, kb, 272, lane));
                #pragma unroll
                for (int np = 0; np < 4; ++np) {
                    uint32_t bh[4];
                    ldm4(bh, baddr(bb, wn * 64 + np * 16, ks * 32, lane));
                    mmab(c1[0][2 * np], ah0, bh);     mmab(c1[1][2 * np], ah1, bh);
                    mmab(c1[0][2 * np], al0, bh);     mmab(c1[1][2 * np], al1, bh);
                    mmab(c1[0][2 * np + 1], ah0, bh + 2); mmab(c1[1][2 * np + 1], ah1, bh + 2);
                    mmab(c1[0][2 * np + 1], al0, bh + 2); mmab(c1[1][2 * np + 1], al1, bh + 2);
                }
            }
        }

        // ================= epilogue1: +b1, LN, GELU(erf) -> A2 (hi only) ===
        #pragma unroll
        for (int mt = 0; mt < 2; ++mt)
            #pragma unroll
            for (int half = 0; half < 2; ++half) {
                float s1 = 0.f, s2 = 0.f;
                #pragma unroll
                for (int nt = 0; nt < 8; ++nt)
                    #pragma unroll
                    for (int j = 0; j < 2; ++j) {
                        int col = wn * 64 + nt * 8 + tig * 2 + j;
                        float v = c1[mt][nt][half * 2 + j] + b1s[col];
                        c1[mt][nt][half * 2 + j] = v;
                        s1 += v; s2 += v * v;
                    }
                s1 += __shfl_xor_sync(0xffffffffu, s1, 1);
                s1 += __shfl_xor_sync(0xffffffffu, s1, 2);
                s2 += __shfl_xor_sync(0xffffffffu, s2, 1);
                s2 += __shfl_xor_sync(0xffffffffu, s2, 2);
                if (tig == 0) {
                    int row = wm * 32 + mt * 16 + gid + half * 8;
                    stats[row * 8 + wn * 2] = s1;
                    stats[row * 8 + wn * 2 + 1] = s2;
                }
            }
        __syncthreads();
        #pragma unroll
        for (int mt = 0; mt < 2; ++mt)
            #pragma unroll
            for (int half = 0; half < 2; ++half) {
                int row = wm * 32 + mt * 16 + gid + half * 8;
                float t1 = stats[row * 8] + stats[row * 8 + 2] + stats[row * 8 + 4] + stats[row * 8 + 6];
                float t2 = stats[row * 8 + 1] + stats[row * 8 + 3] + stats[row * 8 + 5] + stats[row * 8 + 7];
                float mu = t1 * (1.0f / 256.0f);
                float var = t2 * (1.0f / 256.0f) - mu * mu;
                float rstd = rsqrtf(var + 1e-5f);
                #pragma unroll
                for (int nt = 0; nt < 8; ++nt) {
                    int col0 = wn * 64 + nt * 8 + tig * 2;
                    float v0 = (c1[mt][nt][half * 2] - mu) * rstd * lnws[col0] + lnbs[col0];
                    float v1 = (c1[mt][nt][half * 2 + 1] - mu) * rstd * lnws[col0 + 1] + lnbs[col0 + 1];
                    *(uint32_t*)(sm8 + 34816 + row * 528 + col0 * 2) = pk2(gelu_e(v0), gelu_e(v1));
                }
            }

        // ================= mm2: N=128, K=256 (8 chunks, A2 hi-only) =======
        float c2[2][4][4];
        #pragma unroll
        for (int mt = 0; mt < 2; ++mt)
            #pragma unroll
            for (int nt = 0; nt < 4; ++nt)
                #pragma unroll
                for (int e = 0; e < 4; ++e) c2[mt][nt][e] = 0.f;

        int cur = 0;
        #pragma unroll 1
        for (int kc = 0; kc < 8; ++kc) {
            WAIT0;
            __syncthreads();
            if (kc < 7) issueB(b2buf + (cur ^ 1) * 20480, pB2, 128, 512, kc + 1, tid);
            uint32_t bb = b2buf + cur * 20480;
            #pragma unroll
            for (int ks = 0; ks < 2; ++ks) {
                int kb = (kc * 32 + ks * 16) * 2;
                uint32_t ah0[4], ah1[4];
                ldm4(ah0, aaddr(sb + 34816, wm * 32,      kb, 528, lane));
                ldm4(ah1, aaddr(sb + 34816, wm * 32 + 16, kb, 528, lane));
                #pragma unroll
                for (int np = 0; np < 2; ++np) {
                    uint32_t bh[4];
                    ldm4(bh, baddr(bb, wn * 32 + np * 16, ks * 32, lane));
                    mmab(c2[0][2 * np], ah0, bh);     mmab(c2[1][2 * np], ah1, bh);
                    mmab(c2[0][2 * np + 1], ah0, bh + 2); mmab(c2[1][2 * np + 1], ah1, bh + 2);
                }
            }
            cur ^= 1;
        }

        // ================= epilogue2: RK4 combine (register state) =========
        #pragma unroll
        for (int mt = 0; mt < 2; ++mt)
            #pragma unroll
            for (int half = 0; half < 2; ++half) {
                int row = wm * 32 + mt * 16 + gid + half * 8;
                float dt = dtr[mt * 2 + half];
                #pragma unroll
                for (int nt = 0; nt < 4; ++nt) {
                    int colb = wn * 32 + nt * 8 + tig * 2;
                    float a0 = 0.f, a1 = 0.f;
                    #pragma unroll
                    for (int jj = 0; jj < 2; ++jj) {
                        int j = mt * 16 + nt * 4 + half * 2 + jj;
                        float kv = c2[mt][nt][half * 2 + jj] + b2s[colb + jj];
                        float h = hreg[j];
                        float arg;
                        if (s == 0) {
                            k1r[j] = kv;
                            arg = h + dt * (kv * (1.0f / 3.0f));
                        } else if (s == 1) {
                            pr[j] = k1r[j] - kv;
                            arg = h + dt * (kv - k1r[j] * (1.0f / 3.0f));
                        } else if (s == 2) {
                            arg = h + dt * (pr[j] + kv);
                            pr[j] = 4.0f * k1r[j] - 3.0f * pr[j] + 3.0f * kv;
                        } else {
                            arg = (dt > 0.0f) ? (h + dt * (pr[j] + kv) * 0.125f) : h;
                        }
                        if (jj) a1 = arg; else a0 = arg;
                    }
                    if (s == 3) {
                        float2 o; o.x = a0; o.y = a1;
                        *(float2*)(evolved + (rowbase + row) * 128 + colb) = o;
                    } else {
                        uint32_t hi, lo; sp2(a0, a1, hi, lo);
                        *(uint32_t*)(sm8 + row * 272 + colb * 2) = hi;
                        *(uint32_t*)(sm8 + 17408 + row * 272 + colb * 2) = lo;
                    }
                }
            }
    }
}

// ---------------- GRU: 64 rows/CTA ----------------
// smem: AH 0(33792) AL 33792 | EV 67584(33792) | B 101376(2x20480)
//       brz 142336(1024) bin 143360(512) bhn 143872(512) mask 144384(256)
#define GRU_SM 144640

// NP = n-tile pairs per warp (2 -> N=128 total, 4 -> N=256 total)
template<int NP>
__device__ __forceinline__ void rungate(
    float (*acc)[4],          // [2*2*NP][4], index mt*(2*NP)+tile
    int kab, const uint8_t* img, int nch, int rb,
    const uint8_t* nimg, int nNn, int nrb,
    uint32_t sb, uint8_t* sm8, int& cur, int tid, int lane, int wm, int wn)
{
    const int TPW = 2 * NP;
    #pragma unroll
    for (int i = 0; i < 2 * TPW; ++i)
        #pragma unroll
        for (int e = 0; e < 4; ++e) acc[i][e] = 0.f;
    #pragma unroll 1
    for (int kc = 0; kc < nch; ++kc) {
        WAIT0;
        __syncthreads();
        if (kc + 1 < nch) issueB(sb + 101376 + (cur ^ 1) * 20480, img, NP * 64, rb, kc + 1, tid);
        else if (nimg)    issueB(sb + 101376 + (cur ^ 1) * 20480, nimg, nNn, nrb, 0, tid);
        uint32_t bb = sb + 101376 + cur * 20480;
        #pragma unroll
        for (int ks = 0; ks < 2; ++ks) {
            int kb = kab + (kc * 32 + ks * 16) * 2;
            uint32_t ah0[4], ah1[4], al0[4], al1[4];
            ldm4(ah0, aaddr(sb,         wm * 32,      kb, 528, lane));
            ldm4(ah1, aaddr(sb,         wm * 32 + 16, kb, 528, lane));
            ldm4(al0, aaddr(sb + 33792, wm * 32,      kb, 528, lane));
            ldm4(al1, aaddr(sb + 33792, wm * 32 + 16, kb, 528, lane));
            #pragma unroll
            for (int np = 0; np < NP; ++np) {
                uint32_t bh[4];
                ldm4(bh, baddr(bb, wn * (NP * 16) + np * 16, ks * 32, lane));
                mmab(acc[0 * TPW + 2 * np], ah0, bh);     mmab(acc[1 * TPW + 2 * np], ah1, bh);
                mmab(acc[0 * TPW + 2 * np], al0, bh);     mmab(acc[1 * TPW + 2 * np], al1, bh);
                mmab(acc[0 * TPW + 2 * np + 1], ah0, bh + 2); mmab(acc[1 * TPW + 2 * np + 1], ah1, bh + 2);
                mmab(acc[0 * TPW + 2 * np + 1], al0, bh + 2); mmab(acc[1 * TPW + 2 * np + 1], al1, bh + 2);
            }
        }
        cur ^= 1;
    }
}

__global__ void __launch_bounds__(NT, 1) gru_kernel(
    const float* __restrict__ evolved, const float* __restrict__ obs,
    const int* __restrict__ mask,
    const float* __restrict__ bih, const float* __restrict__ bhh,
    float* __restrict__ updated)
{
    extern __shared__ uint8_t sm8[];
    const uint32_t sb = s2u(sm8);
    float* brz  = (float*)(sm8 + 142336);
    float* bin  = (float*)(sm8 + 143360);
    float* bhn  = (float*)(sm8 + 143872);
    int*   mskS = (int*)(sm8 + 144384);

    const int tid = threadIdx.x, lane = tid & 31, wrp = tid >> 5;
    const int gid = lane >> 2, tig = lane & 3;
    const int wm = wrp >> 2, wn = wrp & 3;
    const size_t rowbase = (size_t)blockIdx.x * 64;

    brz[tid] = bih[tid] + bhh[tid];
    if (tid < 128) { bin[tid] = bih[256 + tid]; bhn[tid] = bhh[256 + tid]; }
    if (tid < 64)  mskS[tid] = __ldg(mask + rowbase + tid);
    for (int idx = tid; idx < 8192; idx += NT) {
        int r = idx >> 7, c = idx & 127;
        float vo = __ldg(obs + (rowbase + r) * 128 + c);
        float ve = __ldg(evolved + (rowbase + r) * 128 + c);
        __half oh = __float2half_rn(vo);
        __half ol = __float2half_rn(vo - __half2float(oh));
        __half eh = __float2half_rn(ve);
        __half el = __float2half_rn(ve - __half2float(eh));
        *(uint16_t*)(sm8 + r * 528 + c * 2) = __half_as_ushort(oh);
        *(uint16_t*)(sm8 + r * 528 + 256 + c * 2) = __half_as_ushort(eh);
        *(uint16_t*)(sm8 + 33792 + r * 528 + c * 2) = __half_as_ushort(ol);
        *(uint16_t*)(sm8 + 33792 + r * 528 + 256 + c * 2) = __half_as_ushort(el);
        *(float*)(sm8 + 67584 + r * 528 + c * 4) = ve;
    }
    int cur = 0;
    issueB(sb + 101376, pIN, 128, 256, 0, tid);

    float aN[8][4], aH[8][4], aRZ[16][4];
    rungate<2>(aN, 0,   pIN, 4, 256, pHN, 128, 256, sb, sm8, cur, tid, lane, wm, wn);
    rungate<2>(aH, 256, pHN, 4, 256, pRZ, 256, 512, sb, sm8, cur, tid, lane, wm, wn);
    rungate<4>(aRZ, 0,  pRZ, 8, 512, (const uint8_t*)0, 0, 0, sb, sm8, cur, tid, lane, wm, wn);

    // n = tanh(in + bin + r*(hn + bhn));  r from aRZ tiles 0-3, z from 4-7
    #pragma unroll
    for (int mt = 0; mt < 2; ++mt)
        #pragma unroll
        for (int nt = 0; nt < 4; ++nt)
            #pragma unroll
            for (int e = 0; e < 4; ++e) {
                int col = wn * 32 + nt * 8 + tig * 2 + (e & 1);
                float r = 1.0f / (1.0f + __expf(-(aRZ[mt * 8 + nt][e] + brz[col])));
                aN[mt * 4 + nt][e] = tanhf(aN[mt * 4 + nt][e] + bin[col]
                                           + r * (aH[mt * 4 + nt][e] + bhn[col]));
            }

    #pragma unroll
    for (int mt = 0; mt < 2; ++mt)
        #pragma unroll
        for (int half = 0; half < 2; ++half) {
            int row = wm * 32 + mt * 16 + gid + half * 8;
            int msk = mskS[row];
            #pragma unroll
            for (int nt = 0; nt < 4; ++nt) {
                int colb = wn * 32 + nt * 8 + tig * 2;
                float2 ev = *(const float2*)(sm8 + 67584 + row * 528 + colb * 4);
                float2 o;
                {
                    float z = 1.0f / (1.0f + __expf(-(aRZ[mt * 8 + nt + 4][half * 2] + brz[128 + colb])));
                    float g = (1.0f - z) * aN[mt * 4 + nt][half * 2] + z * ev.x;
                    o.x = (msk > 0) ? g : ev.x;
                }
                {
                    float z = 1.0f / (1.0f + __expf(-(aRZ[mt * 8 + nt + 4][half * 2 + 1] + brz[128 + colb + 1])));
                    float g = (1.0f - z) * aN[mt * 4 + nt][half * 2 + 1] + z * ev.y;
                    o.y = (msk > 0) ? g : ev.y;
                }
                *(float2*)(updated + (rowbase + row) * 128 + colb) = o;
            }
        }
}

// ---------------------------------------------------------------------------
extern "C" void kernel_launch(void* const* d_in, const int* in_sizes, int n_in,
                              void* d_out, int out_size)
{
    const float* hidden = (const float*)d_in[0];
    const float* dts    = (const float*)d_in[1];
    const float* obs    = (const float*)d_in[2];
    const int*   mask   = (const int*)d_in[3];
    const float* w1     = (const float*)d_in[4];
    const float* b1     = (const float*)d_in[5];
    const float* lnw    = (const float*)d_in[6];
    const float* lnb    = (const float*)d_in[7];
    const float* w2     = (const float*)d_in[8];
    const float* b2     = (const float*)d_in[9];
    const float* wih    = (const float*)d_in[10];
    const float* whh    = (const float*)d_in[11];
    const float* bih    = (const float*)d_in[12];
    const float* bhh    = (const float*)d_in[13];

    float* evolved = (float*)d_out;
    float* updated = evolved + (size_t)131072 * 128;

    cudaFuncSetAttribute(evolve_kernel, cudaFuncAttributeMaxDynamicSharedMemorySize, EV_SM);
    cudaFuncSetAttribute(gru_kernel, cudaFuncAttributeMaxDynamicSharedMemorySize, GRU_SM);

    prep_kernel<<<640, 256>>>(w1, w2, wih, whh);
    evolve_kernel<<<2048, NT, EV_SM>>>(hidden, dts, b1, lnw, lnb, b2, evolved);
    gru_kernel<<<2048, NT, GRU_SM>>>(evolved, obs, mask, bih, bhh, updated);
}

// round 16
// speedup vs baseline: 3.9699x; 1.0866x over previous
#include <cuda_runtime.h>
#include <cuda_fp16.h>
#include <math.h>
#include <stdint.h>

#define NT 256

// ---------------- weight images: [n][k] fp16 (hi plane only) ----------------
__device__ __align__(16) uint8_t pB1[65536];    // w1^T  [256][128]
__device__ __align__(16) uint8_t pB2[65536];    // w2^T  [128][256]
__device__ __align__(16) uint8_t pRZ[131072];   // rz interleaved [256][256]
__device__ __align__(16) uint8_t pIN[32768];    // wih_n [128][128]
__device__ __align__(16) uint8_t pHN[32768];    // whh_n [128][128]

__device__ __forceinline__ void wsp(float x, uint8_t* img, uint32_t o) {
    *(uint16_t*)(img + o) = __half_as_ushort(__float2half_rn(x));
}

__global__ void prep_kernel(const float* __restrict__ w1, const float* __restrict__ w2,
                            const float* __restrict__ wih, const float* __restrict__ whh) {
    int i = blockIdx.x * blockDim.x + threadIdx.x;
    if (i < 32768) {
        int n = i >> 7, k = i & 127;
        wsp(w1[k * 256 + n], pB1, (uint32_t)(n * 128 + k) * 2);
    } else if (i < 65536) {
        int t = i - 32768, n = t >> 8, k = t & 255;
        wsp(w2[k * 128 + n], pB2, (uint32_t)(n * 256 + k) * 2);
    } else if (i < 131072) {
        // rz merged, gate-interleaved: image row n -> h=(n>>6)*32+(n&31), gate=(n>>5)&1
        int t = i - 65536, n = t >> 8, k = t & 255;
        int h = (n >> 6) * 32 + (n & 31);
        int g = (n >> 5) & 1;
        int src = g * 128 + h;
        float v = (k < 128) ? wih[src * 128 + k] : whh[src * 128 + (k - 128)];
        wsp(v, pRZ, (uint32_t)(n * 256 + k) * 2);
    } else if (i < 147456) {
        int t = i - 131072, n = t >> 7, k = t & 127;
        wsp(wih[(256 + n) * 128 + k], pIN, (uint32_t)(n * 128 + k) * 2);
    } else if (i < 163840) {
        int t = i - 147456, n = t >> 7, k = t & 127;
        wsp(whh[(256 + n) * 128 + k], pHN, (uint32_t)(n * 128 + k) * 2);
    }
}

// ---------------- helpers ----------------
__device__ __forceinline__ uint32_t s2u(const void* p) {
    uint32_t a;
    asm("{.reg .u64 t; cvta.to.shared.u64 t,%1; cvt.u32.u64 %0,t;}" : "=r"(a) : "l"(p));
    return a;
}
__device__ __forceinline__ void cpa(uint32_t d, const void* s) {
    asm volatile("cp.async.cg.shared.global [%0],[%1],16;" :: "r"(d), "l"(s) : "memory");
}
#define CPC()  asm volatile("cp.async.commit_group;" ::: "memory")
#define WAIT0 asm volatile("cp.async.wait_group 0;" ::: "memory")

__device__ __forceinline__ void mmab(float c[4], const uint32_t a[4], const uint32_t b[2]) {
    asm volatile("mma.sync.aligned.m16n8k16.row.col.f32.f16.f16.f32 "
        "{%0,%1,%2,%3},{%4,%5,%6,%7},{%8,%9},{%0,%1,%2,%3};"
        : "+f"(c[0]), "+f"(c[1]), "+f"(c[2]), "+f"(c[3])
        : "r"(a[0]), "r"(a[1]), "r"(a[2]), "r"(a[3]), "r"(b[0]), "r"(b[1]));
}
__device__ __forceinline__ void ldm4(uint32_t f[4], uint32_t addr) {
    asm volatile("ldmatrix.sync.aligned.m8n8.x4.shared.b16 {%0,%1,%2,%3},[%4];"
        : "=r"(f[0]), "=r"(f[1]), "=r"(f[2]), "=r"(f[3]) : "r"(addr));
}
__device__ __forceinline__ uint32_t aaddr(uint32_t plane, int rowTile, int kb,
                                          int stride, int lane) {
    int r = rowTile + (lane & 7) + (lane & 8);
    int ko = kb + ((lane & 16) ? 16 : 0);
    return plane + (uint32_t)(r * stride + ko);
}
// B fragment address with arbitrary row stride (row-major [n][k] region)
__device__ __forceinline__ uint32_t baddr2(uint32_t plane, int n0, int kb,
                                           int lane, int stride) {
    int n = n0 + (lane & 7) + ((lane & 16) ? 8 : 0);
    int ko = kb + ((lane & 8) ? 16 : 0);
    return plane + (uint32_t)(n * stride + ko);
}
// fp16 hi/lo split of a float pair -> packed h2 regs
__device__ __forceinline__ void sp2(float v0, float v1, uint32_t& hi, uint32_t& lo) {
    __half h0 = __float2half_rn(v0), h1 = __float2half_rn(v1);
    __half l0 = __float2half_rn(v0 - __half2float(h0));
    __half l1 = __float2half_rn(v1 - __half2float(h1));
    hi = (uint32_t)__half_as_ushort(h0) | ((uint32_t)__half_as_ushort(h1) << 16);
    lo = (uint32_t)__half_as_ushort(l0) | ((uint32_t)__half_as_ushort(l1) << 16);
}
__device__ __forceinline__ uint32_t pk2(float v0, float v1) {
    __half h0 = __float2half_rn(v0), h1 = __float2half_rn(v1);
    return (uint32_t)__half_as_ushort(h0) | ((uint32_t)__half_as_ushort(h1) << 16);
}
// resident weight load: [rows][rowbytes] image -> smem rows with given stride
__device__ __forceinline__ void loadRes(uint32_t dst, const uint8_t* img,
                                        int rows, int rowbytes, int stride, int tid) {
    int per = rowbytes >> 4, tot = rows * per;
    for (int f = tid; f < tot; f += NT) {
        int r = f / per, q = f - r * per;
        cpa(dst + (uint32_t)(r * stride + q * 16),
            img + (size_t)r * rowbytes + q * 16);
    }
}
// stream a [Nn][64k] fp16 chunk into smem (row stride 144B, conflict-free)
__device__ __forceinline__ void issueB64(uint32_t dst, const uint8_t* img,
                                         int Nn, int rowbytes, int kc, int tid) {
    const int tot = Nn * 8;
    for (int f = tid; f < tot; f += NT) {
        int r = f >> 3, q = f & 7;
        cpa(dst + (uint32_t)(r * 144 + q * 16),
            img + (size_t)r * rowbytes + kc * 128 + q * 16);
    }
    CPC();
}
__device__ __forceinline__ float gelu_e(float v) {
    return 0.5f * v * (1.0f + erff(v * 0.70710678f));
}

// ---------------- evolve: RK4(3/8), 64 rows/CTA, ALL weights resident ------
// smem: AH 0(17408) AL 17408(17408) | A2H 34816(33792) |
//       B1 68608(256x272=69632) | B2 138240(128x528=67584)
//       stats 205824(2048) b1 207872(1024) lnw 208896 lnb 209920 b2 210944(512)
#define EV_SM 211456
__global__ void __launch_bounds__(NT, 1) evolve_kernel(
    const float* __restrict__ hidden, const float* __restrict__ dts,
    const float* __restrict__ b1, const float* __restrict__ lnw,
    const float* __restrict__ lnb, const float* __restrict__ b2,
    float* __restrict__ evolved)
{
    extern __shared__ uint8_t sm8[];
    const uint32_t sb = s2u(sm8);
    const uint32_t b1res = sb + 68608;
    const uint32_t b2res = sb + 138240;
    float* stats = (float*)(sm8 + 205824);
    float* b1s   = (float*)(sm8 + 207872);
    float* lnws  = (float*)(sm8 + 208896);
    float* lnbs  = (float*)(sm8 + 209920);
    float* b2s   = (float*)(sm8 + 210944);

    const int tid = threadIdx.x, lane = tid & 31, wrp = tid >> 5;
    const int gid = lane >> 2, tig = lane & 3;
    const int wm = wrp >> 2, wn = wrp & 3;
    const size_t rowbase = (size_t)blockIdx.x * 64;

    // load ALL weights once (overlapped with A staging below)
    loadRes(b1res, pB1, 256, 256, 272, tid);
    loadRes(b2res, pB2, 128, 512, 528, tid);
    CPC();

    b1s[tid] = b1[tid]; lnws[tid] = lnw[tid]; lnbs[tid] = lnb[tid];
    if (tid < 128) b2s[tid] = b2[tid];
    // A0 = split(h)  (fp16 hi/lo planes)
    for (int idx = tid; idx < 8192; idx += NT) {
        int r = idx >> 7, c = idx & 127;
        float v = __ldg(hidden + (rowbase + r) * 128 + c);
        __half h = __float2half_rn(v);
        __half l = __float2half_rn(v - __half2float(h));
        *(uint16_t*)(sm8 + r * 272 + c * 2) = __half_as_ushort(h);
        *(uint16_t*)(sm8 + 17408 + r * 272 + c * 2) = __half_as_ushort(l);
    }
    // h, dt, RK4 state in registers (fragment coords)
    float hreg[32], dtr[4];
    #pragma unroll
    for (int mt = 0; mt < 2; ++mt)
        #pragma unroll
        for (int half = 0; half < 2; ++half) {
            int row = wm * 32 + mt * 16 + gid + half * 8;
            dtr[mt * 2 + half] = fmaxf(__ldg(dts + rowbase + row), 0.0f);
            #pragma unroll
            for (int nt = 0; nt < 4; ++nt) {
                float2 hv = __ldg((const float2*)(hidden + (rowbase + row) * 128
                                                  + wn * 32 + nt * 8 + tig * 2));
                hreg[mt * 16 + nt * 4 + half * 2]     = hv.x;
                hreg[mt * 16 + nt * 4 + half * 2 + 1] = hv.y;
            }
        }
    float k1r[32], pr[32];

    WAIT0;   // weights + nothing else pending (per-thread); stage-top sync publishes

    #pragma unroll 1
    for (int s = 0; s < 4; ++s) {
        __syncthreads();   // publish A arg planes (and weights on s=0)

        // ================= mm1: N=256, K=128 (resident B1, barrier-free) ==
        float c1[2][8][4];
        #pragma unroll
        for (int mt = 0; mt < 2; ++mt)
            #pragma unroll
            for (int nt = 0; nt < 8; ++nt)
                #pragma unroll
                for (int e = 0; e < 4; ++e) c1[mt][nt][e] = 0.f;

        #pragma unroll 2
        for (int ks = 0; ks < 8; ++ks) {
            int kb = ks * 32;
            uint32_t ah0[4], ah1[4], al0[4], al1[4];
            ldm4(ah0, aaddr(sb,         wm * 32,      kb, 272, lane));
            ldm4(ah1, aaddr(sb,         wm * 32 + 16, kb, 272, lane));
            ldm4(al0, aaddr(sb + 17408, wm * 32,      kb, 272, lane));
            ldm4(al1, aaddr(sb + 17408, wm * 32 + 16, kb, 272, lane));
            #pragma unroll
            for (int np = 0; np < 4; ++np) {
                uint32_t bh[4];
                ldm4(bh, baddr2(b1res, wn * 64 + np * 16, kb, lane, 272));
                mmab(c1[0][2 * np], ah0, bh);     mmab(c1[1][2 * np], ah1, bh);
                mmab(c1[0][2 * np], al0, bh);     mmab(c1[1][2 * np], al1, bh);
                mmab(c1[0][2 * np + 1], ah0, bh + 2); mmab(c1[1][2 * np + 1], ah1, bh + 2);
                mmab(c1[0][2 * np + 1], al0, bh + 2); mmab(c1[1][2 * np + 1], al1, bh + 2);
            }
        }

        // ================= epilogue1: +b1, LN, GELU(erf) -> A2 (hi only) ===
        #pragma unroll
        for (int mt = 0; mt < 2; ++mt)
            #pragma unroll
            for (int half = 0; half < 2; ++half) {
                float s1 = 0.f, s2 = 0.f;
                #pragma unroll
                for (int nt = 0; nt < 8; ++nt)
                    #pragma unroll
                    for (int j = 0; j < 2; ++j) {
                        int col = wn * 64 + nt * 8 + tig * 2 + j;
                        float v = c1[mt][nt][half * 2 + j] + b1s[col];
                        c1[mt][nt][half * 2 + j] = v;
                        s1 += v; s2 += v * v;
                    }
                s1 += __shfl_xor_sync(0xffffffffu, s1, 1);
                s1 += __shfl_xor_sync(0xffffffffu, s1, 2);
                s2 += __shfl_xor_sync(0xffffffffu, s2, 1);
                s2 += __shfl_xor_sync(0xffffffffu, s2, 2);
                if (tig == 0) {
                    int row = wm * 32 + mt * 16 + gid + half * 8;
                    stats[row * 8 + wn * 2] = s1;
                    stats[row * 8 + wn * 2 + 1] = s2;
                }
            }
        __syncthreads();
        #pragma unroll
        for (int mt = 0; mt < 2; ++mt)
            #pragma unroll
            for (int half = 0; half < 2; ++half) {
                int row = wm * 32 + mt * 16 + gid + half * 8;
                float t1 = stats[row * 8] + stats[row * 8 + 2] + stats[row * 8 + 4] + stats[row * 8 + 6];
                float t2 = stats[row * 8 + 1] + stats[row * 8 + 3] + stats[row * 8 + 5] + stats[row * 8 + 7];
                float mu = t1 * (1.0f / 256.0f);
                float var = t2 * (1.0f / 256.0f) - mu * mu;
                float rstd = rsqrtf(var + 1e-5f);
                #pragma unroll
                for (int nt = 0; nt < 8; ++nt) {
                    int col0 = wn * 64 + nt * 8 + tig * 2;
                    float v0 = (c1[mt][nt][half * 2] - mu) * rstd * lnws[col0] + lnbs[col0];
                    float v1 = (c1[mt][nt][half * 2 + 1] - mu) * rstd * lnws[col0 + 1] + lnbs[col0 + 1];
                    *(uint32_t*)(sm8 + 34816 + row * 528 + col0 * 2) = pk2(gelu_e(v0), gelu_e(v1));
                }
            }
        __syncthreads();   // publish A2 before cross-warp mm2 reads

        // ================= mm2: N=128, K=256 (resident B2, barrier-free) ==
        float c2[2][4][4];
        #pragma unroll
        for (int mt = 0; mt < 2; ++mt)
            #pragma unroll
            for (int nt = 0; nt < 4; ++nt)
                #pragma unroll
                for (int e = 0; e < 4; ++e) c2[mt][nt][e] = 0.f;

        #pragma unroll 2
        for (int ks = 0; ks < 16; ++ks) {
            int kb = ks * 32;
            uint32_t ah0[4], ah1[4];
            ldm4(ah0, aaddr(sb + 34816, wm * 32,      kb, 528, lane));
            ldm4(ah1, aaddr(sb + 34816, wm * 32 + 16, kb, 528, lane));
            #pragma unroll
            for (int np = 0; np < 2; ++np) {
                uint32_t bh[4];
                ldm4(bh, baddr2(b2res, wn * 32 + np * 16, kb, lane, 528));
                mmab(c2[0][2 * np], ah0, bh);     mmab(c2[1][2 * np], ah1, bh);
                mmab(c2[0][2 * np + 1], ah0, bh + 2); mmab(c2[1][2 * np + 1], ah1, bh + 2);
            }
        }

        // ================= epilogue2: RK4 combine (register state) =========
        #pragma unroll
        for (int mt = 0; mt < 2; ++mt)
            #pragma unroll
            for (int half = 0; half < 2; ++half) {
                int row = wm * 32 + mt * 16 + gid + half * 8;
                float dt = dtr[mt * 2 + half];
                #pragma unroll
                for (int nt = 0; nt < 4; ++nt) {
                    int colb = wn * 32 + nt * 8 + tig * 2;
                    float a0 = 0.f, a1 = 0.f;
                    #pragma unroll
                    for (int jj = 0; jj < 2; ++jj) {
                        int j = mt * 16 + nt * 4 + half * 2 + jj;
                        float kv = c2[mt][nt][half * 2 + jj] + b2s[colb + jj];
                        float h = hreg[j];
                        float arg;
                        if (s == 0) {
                            k1r[j] = kv;
                            arg = h + dt * (kv * (1.0f / 3.0f));
                        } else if (s == 1) {
                            pr[j] = k1r[j] - kv;
                            arg = h + dt * (kv - k1r[j] * (1.0f / 3.0f));
                        } else if (s == 2) {
                            arg = h + dt * (pr[j] + kv);
                            pr[j] = 4.0f * k1r[j] - 3.0f * pr[j] + 3.0f * kv;
                        } else {
                            arg = (dt > 0.0f) ? (h + dt * (pr[j] + kv) * 0.125f) : h;
                        }
                        if (jj) a1 = arg; else a0 = arg;
                    }
                    if (s == 3) {
                        float2 o; o.x = a0; o.y = a1;
                        *(float2*)(evolved + (rowbase + row) * 128 + colb) = o;
                    } else {
                        uint32_t hi, lo; sp2(a0, a1, hi, lo);
                        *(uint32_t*)(sm8 + row * 272 + colb * 2) = hi;
                        *(uint32_t*)(sm8 + 17408 + row * 272 + colb * 2) = lo;
                    }
                }
            }
    }
}

// ---------------- GRU: 64 rows/CTA, 64k-wide streamed chunks ---------------
// smem: AH 0(33792) AL 33792 | EV 67584(33792) | B 101376(2x36864=73728)
//       brz 175104(1024) bin 176128(512) bhn 176640(512) mask 177152(256)
#define GRU_SM 177408

// NP = n-tile pairs per warp (2 -> N=128 total, 4 -> N=256 total)
template<int NP>
__device__ __forceinline__ void rungate(
    float (*acc)[4],          // [2*2*NP][4], index mt*(2*NP)+tile
    int kab, const uint8_t* img, int nch, int rb,
    const uint8_t* nimg, int nNn, int nrb,
    uint32_t sb, uint8_t* sm8, int& cur, int tid, int lane, int wm, int wn)
{
    const int TPW = 2 * NP;
    #pragma unroll
    for (int i = 0; i < 2 * TPW; ++i)
        #pragma unroll
        for (int e = 0; e < 4; ++e) acc[i][e] = 0.f;
    #pragma unroll 1
    for (int kc = 0; kc < nch; ++kc) {
        WAIT0;
        __syncthreads();
        if (kc + 1 < nch) issueB64(sb + 101376 + (cur ^ 1) * 36864, img, NP * 64, rb, kc + 1, tid);
        else if (nimg)    issueB64(sb + 101376 + (cur ^ 1) * 36864, nimg, nNn, nrb, 0, tid);
        uint32_t bb = sb + 101376 + cur * 36864;
        #pragma unroll
        for (int ks = 0; ks < 4; ++ks) {
            int kb = kab + (kc * 64 + ks * 16) * 2;
            uint32_t ah0[4], ah1[4], al0[4], al1[4];
            ldm4(ah0, aaddr(sb,         wm * 32,      kb, 528, lane));
            ldm4(ah1, aaddr(sb,         wm * 32 + 16, kb, 528, lane));
            ldm4(al0, aaddr(sb + 33792, wm * 32,      kb, 528, lane));
            ldm4(al1, aaddr(sb + 33792, wm * 32 + 16, kb, 528, lane));
            #pragma unroll
            for (int np = 0; np < NP; ++np) {
                uint32_t bh[4];
                ldm4(bh, baddr2(bb, wn * (NP * 16) + np * 16, ks * 32, lane, 144));
                mmab(acc[0 * TPW + 2 * np], ah0, bh);     mmab(acc[1 * TPW + 2 * np], ah1, bh);
                mmab(acc[0 * TPW + 2 * np], al0, bh);     mmab(acc[1 * TPW + 2 * np], al1, bh);
                mmab(acc[0 * TPW + 2 * np + 1], ah0, bh + 2); mmab(acc[1 * TPW + 2 * np + 1], ah1, bh + 2);
                mmab(acc[0 * TPW + 2 * np + 1], al0, bh + 2); mmab(acc[1 * TPW + 2 * np + 1], al1, bh + 2);
            }
        }
        cur ^= 1;
    }
}

__global__ void __launch_bounds__(NT, 1) gru_kernel(
    const float* __restrict__ evolved, const float* __restrict__ obs,
    const int* __restrict__ mask,
    const float* __restrict__ bih, const float* __restrict__ bhh,
    float* __restrict__ updated)
{
    extern __shared__ uint8_t sm8[];
    const uint32_t sb = s2u(sm8);
    float* brz  = (float*)(sm8 + 175104);
    float* bin  = (float*)(sm8 + 176128);
    float* bhn  = (float*)(sm8 + 176640);
    int*   mskS = (int*)(sm8 + 177152);

    const int tid = threadIdx.x, lane = tid & 31, wrp = tid >> 5;
    const int gid = lane >> 2, tig = lane & 3;
    const int wm = wrp >> 2, wn = wrp & 3;
    const size_t rowbase = (size_t)blockIdx.x * 64;

    brz[tid] = bih[tid] + bhh[tid];
    if (tid < 128) { bin[tid] = bih[256 + tid]; bhn[tid] = bhh[256 + tid]; }
    if (tid < 64)  mskS[tid] = __ldg(mask + rowbase + tid);
    for (int idx = tid; idx < 8192; idx += NT) {
        int r = idx >> 7, c = idx & 127;
        float vo = __ldg(obs + (rowbase + r) * 128 + c);
        float ve = __ldg(evolved + (rowbase + r) * 128 + c);
        __half oh = __float2half_rn(vo);
        __half ol = __float2half_rn(vo - __half2float(oh));
        __half eh = __float2half_rn(ve);
        __half el = __float2half_rn(ve - __half2float(eh));
        *(uint16_t*)(sm8 + r * 528 + c * 2) = __half_as_ushort(oh);
        *(uint16_t*)(sm8 + r * 528 + 256 + c * 2) = __half_as_ushort(eh);
        *(uint16_t*)(sm8 + 33792 + r * 528 + c * 2) = __half_as_ushort(ol);
        *(uint16_t*)(sm8 + 33792 + r * 528 + 256 + c * 2) = __half_as_ushort(el);
        *(float*)(sm8 + 67584 + r * 528 + c * 4) = ve;
    }
    int cur = 0;
    issueB64(sb + 101376, pIN, 128, 256, 0, tid);

    float aN[8][4], aH[8][4], aRZ[16][4];
    rungate<2>(aN, 0,   pIN, 2, 256, pHN, 128, 256, sb, sm8, cur, tid, lane, wm, wn);
    rungate<2>(aH, 256, pHN, 2, 256, pRZ, 256, 512, sb, sm8, cur, tid, lane, wm, wn);
    rungate<4>(aRZ, 0,  pRZ, 4, 512, (const uint8_t*)0, 0, 0, sb, sm8, cur, tid, lane, wm, wn);

    // n = tanh(in + bin + r*(hn + bhn));  r from aRZ tiles 0-3, z from 4-7
    #pragma unroll
    for (int mt = 0; mt < 2; ++mt)
        #pragma unroll
        for (int nt = 0; nt < 4; ++nt)
            #pragma unroll
            for (int e = 0; e < 4; ++e) {
                int col = wn * 32 + nt * 8 + tig * 2 + (e & 1);
                float r = 1.0f / (1.0f + __expf(-(aRZ[mt * 8 + nt][e] + brz[col])));
                aN[mt * 4 + nt][e] = tanhf(aN[mt * 4 + nt][e] + bin[col]
                                           + r * (aH[mt * 4 + nt][e] + bhn[col]));
            }

    #pragma unroll
    for (int mt = 0; mt < 2; ++mt)
        #pragma unroll
        for (int half = 0; half < 2; ++half) {
            int row = wm * 32 + mt * 16 + gid + half * 8;
            int msk = mskS[row];
            #pragma unroll
            for (int nt = 0; nt < 4; ++nt) {
                int colb = wn * 32 + nt * 8 + tig * 2;
                float2 ev = *(const float2*)(sm8 + 67584 + row * 528 + colb * 4);
                float2 o;
                {
                    float z = 1.0f / (1.0f + __expf(-(aRZ[mt * 8 + nt + 4][half * 2] + brz[128 + colb])));
                    float g = (1.0f - z) * aN[mt * 4 + nt][half * 2] + z * ev.x;
                    o.x = (msk > 0) ? g : ev.x;
                }
                {
                    float z = 1.0f / (1.0f + __expf(-(aRZ[mt * 8 + nt + 4][half * 2 + 1] + brz[128 + colb + 1])));
                    float g = (1.0f - z) * aN[mt * 4 + nt][half * 2 + 1] + z * ev.y;
                    o.y = (msk > 0) ? g : ev.y;
                }
                *(float2*)(updated + (rowbase + row) * 128 + colb) = o;
            }
        }
}

// ---------------------------------------------------------------------------
extern "C" void kernel_launch(void* const* d_in, const int* in_sizes, int n_in,
                              void* d_out, int out_size)
{
    const float* hidden = (const float*)d_in[0];
    const float* dts    = (const float*)d_in[1];
    const float* obs    = (const float*)d_in[2];
    const int*   mask   = (const int*)d_in[3];
    const float* w1     = (const float*)d_in[4];
    const float* b1     = (const float*)d_in[5];
    const float* lnw    = (const float*)d_in[6];
    const float* lnb    = (const float*)d_in[7];
    const float* w2     = (const float*)d_in[8];
    const float* b2     = (const float*)d_in[9];
    const float* wih    = (const float*)d_in[10];
    const float* whh    = (const float*)d_in[11];
    const float* bih    = (const float*)d_in[12];
    const float* bhh    = (const float*)d_in[13];

    float* evolved = (float*)d_out;
    float* updated = evolved + (size_t)131072 * 128;

    cudaFuncSetAttribute(evolve_kernel, cudaFuncAttributeMaxDynamicSharedMemorySize, EV_SM);
    cudaFuncSetAttribute(gru_kernel, cudaFuncAttributeMaxDynamicSharedMemorySize, GRU_SM);

    prep_kernel<<<640, 256>>>(w1, w2, wih, whh);
    evolve_kernel<<<2048, NT, EV_SM>>>(hidden, dts, b1, lnw, lnb, b2, evolved);
    gru_kernel<<<2048, NT, GRU_SM>>>(evolved, obs, mask, bih, bhh, updated);
}

// round 17
// speedup vs baseline: 4.6675x; 1.1757x over previous
#include <cuda_runtime.h>
#include <cuda_fp16.h>
#include <math.h>
#include <stdint.h>

#define NT 256

// ---------------- weight images: [n][k] fp16 ----------------
__device__ __align__(16) uint8_t pB1[65536];    // w1^T  [256][128]
__device__ __align__(16) uint8_t pB2[65536];    // w2^T  [128][256]
__device__ __align__(16) uint8_t pRZ[131072];   // rz interleaved [256][256]
__device__ __align__(16) uint8_t pIN[32768];    // wih_n [128][128]
__device__ __align__(16) uint8_t pHN[32768];    // whh_n [128][128]

__device__ __forceinline__ void wsp(float x, uint8_t* img, uint32_t o) {
    *(uint16_t*)(img + o) = __half_as_ushort(__float2half_rn(x));
}

__global__ void prep_kernel(const float* __restrict__ w1, const float* __restrict__ w2,
                            const float* __restrict__ wih, const float* __restrict__ whh) {
    int i = blockIdx.x * blockDim.x + threadIdx.x;
    if (i < 32768) {
        int n = i >> 7, k = i & 127;
        wsp(w1[k * 256 + n], pB1, (uint32_t)(n * 128 + k) * 2);
    } else if (i < 65536) {
        int t = i - 32768, n = t >> 8, k = t & 255;
        wsp(w2[k * 128 + n], pB2, (uint32_t)(n * 256 + k) * 2);
    } else if (i < 131072) {
        // rz merged, gate-interleaved: image row n -> h=(n>>6)*32+(n&31), gate=(n>>5)&1
        int t = i - 65536, n = t >> 8, k = t & 255;
        int h = (n >> 6) * 32 + (n & 31);
        int g = (n >> 5) & 1;
        int src = g * 128 + h;
        float v = (k < 128) ? wih[src * 128 + k] : whh[src * 128 + (k - 128)];
        wsp(v, pRZ, (uint32_t)(n * 256 + k) * 2);
    } else if (i < 147456) {
        int t = i - 131072, n = t >> 7, k = t & 127;
        wsp(wih[(256 + n) * 128 + k], pIN, (uint32_t)(n * 128 + k) * 2);
    } else if (i < 163840) {
        int t = i - 147456, n = t >> 7, k = t & 127;
        wsp(whh[(256 + n) * 128 + k], pHN, (uint32_t)(n * 128 + k) * 2);
    }
}

// ---------------- helpers ----------------
__device__ __forceinline__ uint32_t s2u(const void* p) {
    uint32_t a;
    asm("{.reg .u64 t; cvta.to.shared.u64 t,%1; cvt.u32.u64 %0,t;}" : "=r"(a) : "l"(p));
    return a;
}
__device__ __forceinline__ void cpa(uint32_t d, const void* s) {
    asm volatile("cp.async.cg.shared.global [%0],[%1],16;" :: "r"(d), "l"(s) : "memory");
}
#define CPC()  asm volatile("cp.async.commit_group;" ::: "memory")
#define WAIT0 asm volatile("cp.async.wait_group 0;" ::: "memory")

__device__ __forceinline__ void mmab(float c[4], const uint32_t a[4], const uint32_t b[2]) {
    asm volatile("mma.sync.aligned.m16n8k16.row.col.f32.f16.f16.f32 "
        "{%0,%1,%2,%3},{%4,%5,%6,%7},{%8,%9},{%0,%1,%2,%3};"
        : "+f"(c[0]), "+f"(c[1]), "+f"(c[2]), "+f"(c[3])
        : "r"(a[0]), "r"(a[1]), "r"(a[2]), "r"(a[3]), "r"(b[0]), "r"(b[1]));
}
__device__ __forceinline__ void ldm4(uint32_t f[4], uint32_t addr) {
    asm volatile("ldmatrix.sync.aligned.m8n8.x4.shared.b16 {%0,%1,%2,%3},[%4];"
        : "=r"(f[0]), "=r"(f[1]), "=r"(f[2]), "=r"(f[3]) : "r"(addr));
}
__device__ __forceinline__ uint32_t aaddr(uint32_t plane, int rowTile, int kb,
                                          int stride, int lane) {
    int r = rowTile + (lane & 7) + (lane & 8);
    int ko = kb + ((lane & 16) ? 16 : 0);
    return plane + (uint32_t)(r * stride + ko);
}
// B fragment address with arbitrary row stride (row-major [n][k] region)
__device__ __forceinline__ uint32_t baddr2(uint32_t plane, int n0, int kb,
                                           int lane, int stride) {
    int n = n0 + (lane & 7) + ((lane & 16) ? 8 : 0);
    int ko = kb + ((lane & 8) ? 16 : 0);
    return plane + (uint32_t)(n * stride + ko);
}
__device__ __forceinline__ uint32_t pk2(float v0, float v1) {
    __half h0 = __float2half_rn(v0), h1 = __float2half_rn(v1);
    return (uint32_t)__half_as_ushort(h0) | ((uint32_t)__half_as_ushort(h1) << 16);
}
// resident weight load: [rows][rowbytes] image -> smem rows with given stride
__device__ __forceinline__ void loadRes(uint32_t dst, const uint8_t* img,
                                        int rows, int rowbytes, int stride, int tid) {
    int per = rowbytes >> 4, tot = rows * per;
    for (int f = tid; f < tot; f += NT) {
        int r = f / per, q = f - r * per;
        cpa(dst + (uint32_t)(r * stride + q * 16),
            img + (size_t)r * rowbytes + q * 16);
    }
}
// stream a [Nn][64k] fp16 chunk into smem (row stride 144B, conflict-free)
__device__ __forceinline__ void issueB64(uint32_t dst, const uint8_t* img,
                                         int Nn, int rowbytes, int kc, int tid) {
    const int tot = Nn * 8;
    for (int f = tid; f < tot; f += NT) {
        int r = f >> 3, q = f & 7;
        cpa(dst + (uint32_t)(r * 144 + q * 16),
            img + (size_t)r * rowbytes + kc * 128 + q * 16);
    }
    CPC();
}
__device__ __forceinline__ float gelu_e(float v) {
    return 0.5f * v * (1.0f + erff(v * 0.70710678f));
}

// ---------------- evolve: RK4(3/8), 64 rows/CTA, ALL weights resident ------
// smem: AH 0(17408) | A2H 17408(33792) |
//       B1 51200(256x272=69632) | B2 120832(128x528=67584)
//       stats 188416(2048) b1 190464(1024) lnw 191488 lnb 192512 b2 193536(512)
#define EV_SM 194048
__global__ void __launch_bounds__(NT, 1) evolve_kernel(
    const float* __restrict__ hidden, const float* __restrict__ dts,
    const float* __restrict__ b1, const float* __restrict__ lnw,
    const float* __restrict__ lnb, const float* __restrict__ b2,
    float* __restrict__ evolved)
{
    extern __shared__ uint8_t sm8[];
    const uint32_t sb = s2u(sm8);
    const uint32_t a2h   = sb + 17408;
    const uint32_t b1res = sb + 51200;
    const uint32_t b2res = sb + 120832;
    float* stats = (float*)(sm8 + 188416);
    float* b1s   = (float*)(sm8 + 190464);
    float* lnws  = (float*)(sm8 + 191488);
    float* lnbs  = (float*)(sm8 + 192512);
    float* b2s   = (float*)(sm8 + 193536);

    const int tid = threadIdx.x, lane = tid & 31, wrp = tid >> 5;
    const int gid = lane >> 2, tig = lane & 3;
    const int wm = wrp >> 2, wn = wrp & 3;
    const size_t rowbase = (size_t)blockIdx.x * 64;

    // load ALL weights once (overlapped with A staging below)
    loadRes(b1res, pB1, 256, 256, 272, tid);
    loadRes(b2res, pB2, 128, 512, 528, tid);
    CPC();

    b1s[tid] = b1[tid]; lnws[tid] = lnw[tid]; lnbs[tid] = lnb[tid];
    if (tid < 128) b2s[tid] = b2[tid];
    // A0 = fp16(h), single plane
    for (int idx = tid; idx < 8192; idx += NT) {
        int r = idx >> 7, c = idx & 127;
        float v = __ldg(hidden + (rowbase + r) * 128 + c);
        *(uint16_t*)(sm8 + r * 272 + c * 2) = __half_as_ushort(__float2half_rn(v));
    }
    // h, dt, RK4 state in registers (fragment coords)
    float hreg[32], dtr[4];
    #pragma unroll
    for (int mt = 0; mt < 2; ++mt)
        #pragma unroll
        for (int half = 0; half < 2; ++half) {
            int row = wm * 32 + mt * 16 + gid + half * 8;
            dtr[mt * 2 + half] = fmaxf(__ldg(dts + rowbase + row), 0.0f);
            #pragma unroll
            for (int nt = 0; nt < 4; ++nt) {
                float2 hv = __ldg((const float2*)(hidden + (rowbase + row) * 128
                                                  + wn * 32 + nt * 8 + tig * 2));
                hreg[mt * 16 + nt * 4 + half * 2]     = hv.x;
                hreg[mt * 16 + nt * 4 + half * 2 + 1] = hv.y;
            }
        }
    float k1r[32], pr[32];

    WAIT0;   // weights arrived (per-thread); stage-top sync publishes

    #pragma unroll 1
    for (int s = 0; s < 4; ++s) {
        __syncthreads();   // publish A arg plane (and weights on s=0)

        // ================= mm1: N=256, K=128 (resident B1, 1-term) ========
        float c1[2][8][4];
        #pragma unroll
        for (int mt = 0; mt < 2; ++mt)
            #pragma unroll
            for (int nt = 0; nt < 8; ++nt)
                #pragma unroll
                for (int e = 0; e < 4; ++e) c1[mt][nt][e] = 0.f;

        #pragma unroll 2
        for (int ks = 0; ks < 8; ++ks) {
            int kb = ks * 32;
            uint32_t ah0[4], ah1[4];
            ldm4(ah0, aaddr(sb, wm * 32,      kb, 272, lane));
            ldm4(ah1, aaddr(sb, wm * 32 + 16, kb, 272, lane));
            #pragma unroll
            for (int np = 0; np < 4; ++np) {
                uint32_t bh[4];
                ldm4(bh, baddr2(b1res, wn * 64 + np * 16, kb, lane, 272));
                mmab(c1[0][2 * np], ah0, bh);         mmab(c1[1][2 * np], ah1, bh);
                mmab(c1[0][2 * np + 1], ah0, bh + 2); mmab(c1[1][2 * np + 1], ah1, bh + 2);
            }
        }

        // ================= epilogue1: +b1, LN, GELU(erf) -> A2 ============
        #pragma unroll
        for (int mt = 0; mt < 2; ++mt)
            #pragma unroll
            for (int half = 0; half < 2; ++half) {
                float s1 = 0.f, s2 = 0.f;
                #pragma unroll
                for (int nt = 0; nt < 8; ++nt)
                    #pragma unroll
                    for (int j = 0; j < 2; ++j) {
                        int col = wn * 64 + nt * 8 + tig * 2 + j;
                        float v = c1[mt][nt][half * 2 + j] + b1s[col];
                        c1[mt][nt][half * 2 + j] = v;
                        s1 += v; s2 += v * v;
                    }
                s1 += __shfl_xor_sync(0xffffffffu, s1, 1);
                s1 += __shfl_xor_sync(0xffffffffu, s1, 2);
                s2 += __shfl_xor_sync(0xffffffffu, s2, 1);
                s2 += __shfl_xor_sync(0xffffffffu, s2, 2);
                if (tig == 0) {
                    int row = wm * 32 + mt * 16 + gid + half * 8;
                    stats[row * 8 + wn * 2] = s1;
                    stats[row * 8 + wn * 2 + 1] = s2;
                }
            }
        __syncthreads();
        #pragma unroll
        for (int mt = 0; mt < 2; ++mt)
            #pragma unroll
            for (int half = 0; half < 2; ++half) {
                int row = wm * 32 + mt * 16 + gid + half * 8;
                float t1 = stats[row * 8] + stats[row * 8 + 2] + stats[row * 8 + 4] + stats[row * 8 + 6];
                float t2 = stats[row * 8 + 1] + stats[row * 8 + 3] + stats[row * 8 + 5] + stats[row * 8 + 7];
                float mu = t1 * (1.0f / 256.0f);
                float var = t2 * (1.0f / 256.0f) - mu * mu;
                float rstd = rsqrtf(var + 1e-5f);
                #pragma unroll
                for (int nt = 0; nt < 8; ++nt) {
                    int col0 = wn * 64 + nt * 8 + tig * 2;
                    float v0 = (c1[mt][nt][half * 2] - mu) * rstd * lnws[col0] + lnbs[col0];
                    float v1 = (c1[mt][nt][half * 2 + 1] - mu) * rstd * lnws[col0 + 1] + lnbs[col0 + 1];
                    *(uint32_t*)(sm8 + 17408 + row * 528 + col0 * 2) = pk2(gelu_e(v0), gelu_e(v1));
                }
            }
        __syncthreads();   // publish A2 before cross-warp mm2 reads

        // ================= mm2: N=128, K=256 (resident B2, 1-term) ========
        float c2[2][4][4];
        #pragma unroll
        for (int mt = 0; mt < 2; ++mt)
            #pragma unroll
            for (int nt = 0; nt < 4; ++nt)
                #pragma unroll
                for (int e = 0; e < 4; ++e) c2[mt][nt][e] = 0.f;

        #pragma unroll 2
        for (int ks = 0; ks < 16; ++ks) {
            int kb = ks * 32;
            uint32_t ah0[4], ah1[4];
            ldm4(ah0, aaddr(a2h, wm * 32,      kb, 528, lane));
            ldm4(ah1, aaddr(a2h, wm * 32 + 16, kb, 528, lane));
            #pragma unroll
            for (int np = 0; np < 2; ++np) {
                uint32_t bh[4];
                ldm4(bh, baddr2(b2res, wn * 32 + np * 16, kb, lane, 528));
                mmab(c2[0][2 * np], ah0, bh);         mmab(c2[1][2 * np], ah1, bh);
                mmab(c2[0][2 * np + 1], ah0, bh + 2); mmab(c2[1][2 * np + 1], ah1, bh + 2);
            }
        }

        // ================= epilogue2: RK4 combine (register state) =========
        #pragma unroll
        for (int mt = 0; mt < 2; ++mt)
            #pragma unroll
            for (int half = 0; half < 2; ++half) {
                int row = wm * 32 + mt * 16 + gid + half * 8;
                float dt = dtr[mt * 2 + half];
                #pragma unroll
                for (int nt = 0; nt < 4; ++nt) {
                    int colb = wn * 32 + nt * 8 + tig * 2;
                    float a0 = 0.f, a1 = 0.f;
                    #pragma unroll
                    for (int jj = 0; jj < 2; ++jj) {
                        int j = mt * 16 + nt * 4 + half * 2 + jj;
                        float kv = c2[mt][nt][half * 2 + jj] + b2s[colb + jj];
                        float h = hreg[j];
                        float arg;
                        if (s == 0) {
                            k1r[j] = kv;
                            arg = h + dt * (kv * (1.0f / 3.0f));
                        } else if (s == 1) {
                            pr[j] = k1r[j] - kv;
                            arg = h + dt * (kv - k1r[j] * (1.0f / 3.0f));
                        } else if (s == 2) {
                            arg = h + dt * (pr[j] + kv);
                            pr[j] = 4.0f * k1r[j] - 3.0f * pr[j] + 3.0f * kv;
                        } else {
                            arg = (dt > 0.0f) ? (h + dt * (pr[j] + kv) * 0.125f) : h;
                        }
                        if (jj) a1 = arg; else a0 = arg;
                    }
                    if (s == 3) {
                        float2 o; o.x = a0; o.y = a1;
                        *(float2*)(evolved + (rowbase + row) * 128 + colb) = o;
                    } else {
                        *(uint32_t*)(sm8 + row * 272 + colb * 2) = pk2(a0, a1);
                    }
                }
            }
    }
}

// ---------------- GRU: 64 rows/CTA, 64k-wide streamed chunks, 1-term -------
// smem: AH 0(33792) | EV 33792(33792) | B 67584(2x36864=73728)
//       brz 141312(1024) bin 142336(512) bhn 142848(512) mask 143360(256)
#define GRU_SM 143616

// NP = n-tile pairs per warp (2 -> N=128 total, 4 -> N=256 total)
template<int NP>
__device__ __forceinline__ void rungate(
    float (*acc)[4],          // [2*2*NP][4], index mt*(2*NP)+tile
    int kab, const uint8_t* img, int nch, int rb,
    const uint8_t* nimg, int nNn, int nrb,
    uint32_t sb, uint8_t* sm8, int& cur, int tid, int lane, int wm, int wn)
{
    const int TPW = 2 * NP;
    #pragma unroll
    for (int i = 0; i < 2 * TPW; ++i)
        #pragma unroll
        for (int e = 0; e < 4; ++e) acc[i][e] = 0.f;
    #pragma unroll 1
    for (int kc = 0; kc < nch; ++kc) {
        WAIT0;
        __syncthreads();
        if (kc + 1 < nch) issueB64(sb + 67584 + (cur ^ 1) * 36864, img, NP * 64, rb, kc + 1, tid);
        else if (nimg)    issueB64(sb + 67584 + (cur ^ 1) * 36864, nimg, nNn, nrb, 0, tid);
        uint32_t bb = sb + 67584 + cur * 36864;
        #pragma unroll
        for (int ks = 0; ks < 4; ++ks) {
            int kb = kab + (kc * 64 + ks * 16) * 2;
            uint32_t ah0[4], ah1[4];
            ldm4(ah0, aaddr(sb, wm * 32,      kb, 528, lane));
            ldm4(ah1, aaddr(sb, wm * 32 + 16, kb, 528, lane));
            #pragma unroll
            for (int np = 0; np < NP; ++np) {
                uint32_t bh[4];
                ldm4(bh, baddr2(bb, wn * (NP * 16) + np * 16, ks * 32, lane, 144));
                mmab(acc[0 * TPW + 2 * np], ah0, bh);         mmab(acc[1 * TPW + 2 * np], ah1, bh);
                mmab(acc[0 * TPW + 2 * np + 1], ah0, bh + 2); mmab(acc[1 * TPW + 2 * np + 1], ah1, bh + 2);
            }
        }
        cur ^= 1;
    }
}

__global__ void __launch_bounds__(NT, 1) gru_kernel(
    const float* __restrict__ evolved, const float* __restrict__ obs,
    const int* __restrict__ mask,
    const float* __restrict__ bih, const float* __restrict__ bhh,
    float* __restrict__ updated)
{
    extern __shared__ uint8_t sm8[];
    const uint32_t sb = s2u(sm8);
    float* brz  = (float*)(sm8 + 141312);
    float* bin  = (float*)(sm8 + 142336);
    float* bhn  = (float*)(sm8 + 142848);
    int*   mskS = (int*)(sm8 + 143360);

    const int tid = threadIdx.x, lane = tid & 31, wrp = tid >> 5;
    const int gid = lane >> 2, tig = lane & 3;
    const int wm = wrp >> 2, wn = wrp & 3;
    const size_t rowbase = (size_t)blockIdx.x * 64;

    brz[tid] = bih[tid] + bhh[tid];
    if (tid < 128) { bin[tid] = bih[256 + tid]; bhn[tid] = bhh[256 + tid]; }
    if (tid < 64)  mskS[tid] = __ldg(mask + rowbase + tid);
    for (int idx = tid; idx < 8192; idx += NT) {
        int r = idx >> 7, c = idx & 127;
        float vo = __ldg(obs + (rowbase + r) * 128 + c);
        float ve = __ldg(evolved + (rowbase + r) * 128 + c);
        *(uint16_t*)(sm8 + r * 528 + c * 2)       = __half_as_ushort(__float2half_rn(vo));
        *(uint16_t*)(sm8 + r * 528 + 256 + c * 2) = __half_as_ushort(__float2half_rn(ve));
        *(float*)(sm8 + 33792 + r * 528 + c * 4)  = ve;
    }
    int cur = 0;
    issueB64(sb + 67584, pIN, 128, 256, 0, tid);

    float aN[8][4], aH[8][4], aRZ[16][4];
    rungate<2>(aN, 0,   pIN, 2, 256, pHN, 128, 256, sb, sm8, cur, tid, lane, wm, wn);
    rungate<2>(aH, 256, pHN, 2, 256, pRZ, 256, 512, sb, sm8, cur, tid, lane, wm, wn);
    rungate<4>(aRZ, 0,  pRZ, 4, 512, (const uint8_t*)0, 0, 0, sb, sm8, cur, tid, lane, wm, wn);

    // n = tanh(in + bin + r*(hn + bhn));  r from aRZ tiles 0-3, z from 4-7
    #pragma unroll
    for (int mt = 0; mt < 2; ++mt)
        #pragma unroll
        for (int nt = 0; nt < 4; ++nt)
            #pragma unroll
            for (int e = 0; e < 4; ++e) {
                int col = wn * 32 + nt * 8 + tig * 2 + (e & 1);
                float r = 1.0f / (1.0f + __expf(-(aRZ[mt * 8 + nt][e] + brz[col])));
                aN[mt * 4 + nt][e] = tanhf(aN[mt * 4 + nt][e] + bin[col]
                                           + r * (aH[mt * 4 + nt][e] + bhn[col]));
            }

    #pragma unroll
    for (int mt = 0; mt < 2; ++mt)
        #pragma unroll
        for (int half = 0; half < 2; ++half) {
            int row = wm * 32 + mt * 16 + gid + half * 8;
            int msk = mskS[row];
            #pragma unroll
            for (int nt = 0; nt < 4; ++nt) {
                int colb = wn * 32 + nt * 8 + tig * 2;
                float2 ev = *(const float2*)(sm8 + 33792 + row * 528 + colb * 4);
                float2 o;
                {
                    float z = 1.0f / (1.0f + __expf(-(aRZ[mt * 8 + nt + 4][half * 2] + brz[128 + colb])));
                    float g = (1.0f - z) * aN[mt * 4 + nt][half * 2] + z * ev.x;
                    o.x = (msk > 0) ? g : ev.x;
                }
                {
                    float z = 1.0f / (1.0f + __expf(-(aRZ[mt * 8 + nt + 4][half * 2 + 1] + brz[128 + colb + 1])));
                    float g = (1.0f - z) * aN[mt * 4 + nt][half * 2 + 1] + z * ev.y;
                    o.y = (msk > 0) ? g : ev.y;
                }
                *(float2*)(updated + (rowbase + row) * 128 + colb) = o;
            }
        }
}

// ---------------------------------------------------------------------------
extern "C" void kernel_launch(void* const* d_in, const int* in_sizes, int n_in,
                              void* d_out, int out_size)
{
    const float* hidden = (const float*)d_in[0];
    const float* dts    = (const float*)d_in[1];
    const float* obs    = (const float*)d_in[2];
    const int*   mask   = (const int*)d_in[3];
    const float* w1     = (const float*)d_in[4];
    const float* b1     = (const float*)d_in[5];
    const float* lnw    = (const float*)d_in[6];
    const float* lnb    = (const float*)d_in[7];
    const float* w2     = (const float*)d_in[8];
    const float* b2     = (const float*)d_in[9];
    const float* wih    = (const float*)d_in[10];
    const float* whh    = (const float*)d_in[11];
    const float* bih    = (const float*)d_in[12];
    const float* bhh    = (const float*)d_in[13];

    float* evolved = (float*)d_out;
    float* updated = evolved + (size_t)131072 * 128;

    cudaFuncSetAttribute(evolve_kernel, cudaFuncAttributeMaxDynamicSharedMemorySize, EV_SM);
    cudaFuncSetAttribute(gru_kernel, cudaFuncAttributeMaxDynamicSharedMemorySize, GRU_SM);

    prep_kernel<<<640, 256>>>(w1, w2, wih, whh);
    evolve_kernel<<<2048, NT, EV_SM>>>(hidden, dts, b1, lnw, lnb, b2, evolved);
    gru_kernel<<<2048, NT, GRU_SM>>>(evolved, obs, mask, bih, bhh, updated);
}